// round 3
// baseline (speedup 1.0000x reference)
#include <cuda_runtime.h>
#include <cuda_bf16.h>
#include <math.h>

// Problem constants
#define Bq   2
#define Mq   2048
#define Nq   2048
#define Dm   2048
#define NH   16
#define DH   128
#define DR   64
#define FFN_ 8192
#define Tt   (Bq*Mq)          // 4096 tokens (same for q and kv)
#define DCAT (DH+DR)          // 192
#define SCALE_ (0.0721687836487032f) // 1/sqrt(192)

// ---------------- scratch (single __device__ global) ----------------
// offsets in floats
#define O_QN    0LL
#define O_KVN   (O_QN   + (long long)Tt*Dm)          // 8388608
#define O_QC    (O_KVN  + (long long)Tt*Dm)
#define O_KC    (O_QC   + (long long)Tt*NH*DH)
#define O_QR    (O_KC   + (long long)Tt*NH*DH)
#define O_KR    (O_QR   + (long long)Tt*NH*DR)
#define O_V     (O_KR   + (long long)Tt*NH*DR)
#define O_QCAT  (O_V    + (long long)Tt*NH*DH)
#define O_KCAT  (O_QCAT + (long long)Tt*NH*DCAT)
#define O_SC    (O_KCAT + (long long)Tt*NH*DCAT)
#define O_ATT   (O_SC   + (long long)Bq*NH*Mq*Nq)
#define O_X     (O_ATT  + (long long)Tt*NH*DH)
#define O_XN    (O_X    + (long long)Tt*Dm)
#define O_GATE  (O_XN   + (long long)Tt*Dm)
#define O_UP    (O_GATE + (long long)Tt*FFN_)
#define O_TOTAL (O_UP   + (long long)Tt*FFN_)

__device__ float g_scratch[O_TOTAL];

// ---------------- RMSNorm ----------------
__global__ void rmsnorm_k(const float* __restrict__ x, const float* __restrict__ g,
                          float* __restrict__ y) {
    const int D = Dm;
    long long row = blockIdx.x;
    const float* xr = x + row * D;
    float* yr = y + row * D;
    float s = 0.f;
    for (int i = threadIdx.x; i < D; i += blockDim.x) { float v = xr[i]; s += v * v; }
    #pragma unroll
    for (int o = 16; o; o >>= 1) s += __shfl_xor_sync(0xffffffffu, s, o);
    __shared__ float sh[8];
    if ((threadIdx.x & 31) == 0) sh[threadIdx.x >> 5] = s;
    __syncthreads();
    float tot = 0.f;
    #pragma unroll
    for (int i = 0; i < 8; i++) tot += sh[i];
    float n = rsqrtf(tot / (float)D + 1e-6f);
    for (int i = threadIdx.x; i < D; i += blockDim.x) yr[i] = xr[i] * n * g[i];
}

// ---------------- generic tiled SGEMM ----------------
// C[M,N] = alpha * A[M,K] @ B(K,N)  (+ residual R, same layout as C)
// TB=false: B element (k,n) at B[k*ldb + n]
// TB=true : B element (k,n) at B[n*ldb + k]  (i.e. C = A @ B^T, B stored row-major [N,K])
// batch: blockIdx.z = z, b = z/16, h = z%16, pointer += b*<X>B + h*<X>H
template<bool TB>
__global__ void __launch_bounds__(256) sgemm_k(
    const float* __restrict__ A, const float* __restrict__ B,
    const float* __restrict__ R, float* __restrict__ C,
    int M, int N, int K, int lda, int ldb, int ldc,
    long long aB, long long aH, long long bB, long long bH,
    long long cB, long long cH, float alpha)
{
    const int BM = 128, BN = 128, BK = 8, TM = 8, TN = 8;
    int z = blockIdx.z, bb = z >> 4, hh = z & 15;
    A += bb * aB + hh * aH;
    B += bb * bB + hh * bH;
    C += bb * cB + hh * cH;
    if (R) R += bb * cB + hh * cH;

    __shared__ float As[BK][BM + 4];
    __shared__ float Bs[BK][BN + 4];

    int row0 = blockIdx.y * BM, col0 = blockIdx.x * BN;
    int tid = threadIdx.x;
    float acc[TM][TN];
    #pragma unroll
    for (int i = 0; i < TM; i++)
        #pragma unroll
        for (int j = 0; j < TN; j++) acc[i][j] = 0.f;

    int aK = tid & 7;        // k in tile
    int aR = tid >> 3;       // 0..31
    int bK = tid >> 5;       // 0..7
    int bC = tid & 31;

    for (int kt = 0; kt < K; kt += BK) {
        #pragma unroll
        for (int i = 0; i < 4; i++) {
            int r = aR + i * 32;
            As[aK][r] = A[(long long)(row0 + r) * lda + (kt + aK)];
        }
        if (!TB) {
            #pragma unroll
            for (int j = 0; j < 4; j++)
                Bs[bK][bC + j * 32] = B[(long long)(kt + bK) * ldb + (col0 + bC + j * 32)];
        } else {
            #pragma unroll
            for (int i = 0; i < 4; i++) {
                int c = aR + i * 32;
                Bs[aK][c] = B[(long long)(col0 + c) * ldb + (kt + aK)];
            }
        }
        __syncthreads();

        int tr = tid >> 4, tc = tid & 15;
        #pragma unroll
        for (int kk = 0; kk < BK; kk++) {
            float a[TM], b[TN];
            #pragma unroll
            for (int i = 0; i < TM; i++) a[i] = As[kk][tr * TM + i];
            #pragma unroll
            for (int j = 0; j < TN; j++) b[j] = Bs[kk][tc * TN + j];
            #pragma unroll
            for (int i = 0; i < TM; i++)
                #pragma unroll
                for (int j = 0; j < TN; j++) acc[i][j] += a[i] * b[j];
        }
        __syncthreads();
    }

    int tr = tid >> 4, tc = tid & 15;
    #pragma unroll
    for (int i = 0; i < TM; i++) {
        long long r = row0 + tr * TM + i;
        #pragma unroll
        for (int j = 0; j < TN; j++) {
            long long c = col0 + tc * TN + j;
            float v = acc[i][j] * alpha;
            if (R) v += R[r * ldc + c];
            C[r * ldc + c] = v;
        }
    }
}

// ---------------- RoPE (in-place on (T, NH, DR) buffer) ----------------
__global__ void rope_k(float* __restrict__ x, int seqlen) {
    long long g = (long long)blockIdx.x * blockDim.x + threadIdx.x;
    const long long total = (long long)Tt * NH * (DR / 2);
    if (g >= total) return;
    int j = (int)(g % (DR / 2));
    long long th = g / (DR / 2);
    int h = (int)(th % NH);
    long long tok = th / NH;
    int s = (int)(tok % seqlen);
    float freq = (float)pow((double)1000000.0, -2.0 * j / (double)DR);
    float ang = (float)s * freq;
    float c = cosf(ang), si = sinf(ang);
    long long idx = tok * (NH * DR) + h * DR + 2 * j;
    float x1 = x[idx], x2 = x[idx + 1];
    x[idx]     = x1 * c - x2 * si;
    x[idx + 1] = x2 * c + x1 * si;
}

// ---------------- pack [C | R] -> (T, NH, 192) ----------------
__global__ void pack_k(const float* __restrict__ c, const float* __restrict__ rr,
                       float* __restrict__ cat) {
    long long i = (long long)blockIdx.x * blockDim.x + threadIdx.x;
    const long long total = (long long)Tt * NH * DCAT;
    if (i >= total) return;
    int d = (int)(i % DCAT);
    long long th = i / DCAT;
    int h = (int)(th % NH);
    long long tok = th / NH;
    cat[i] = (d < DH) ? c[tok * (NH * DH) + h * DH + d]
                      : rr[tok * (NH * DR) + h * DR + (d - DH)];
}

// ---------------- row softmax (rows of length Nq=2048), 256 threads ----------------
__global__ void softmax_k(float* __restrict__ sc) {
    const int N = Nq;
    float* r = sc + (long long)blockIdx.x * N;
    float v[8];
    float m = -3.4e38f;
    #pragma unroll
    for (int k = 0; k < 8; k++) { v[k] = r[threadIdx.x + k * 256]; m = fmaxf(m, v[k]); }
    #pragma unroll
    for (int o = 16; o; o >>= 1) m = fmaxf(m, __shfl_xor_sync(0xffffffffu, m, o));
    __shared__ float shm[8], shs[8];
    if ((threadIdx.x & 31) == 0) shm[threadIdx.x >> 5] = m;
    __syncthreads();
    #pragma unroll
    for (int i = 0; i < 8; i++) m = fmaxf(m, shm[i]);
    float s = 0.f;
    #pragma unroll
    for (int k = 0; k < 8; k++) { v[k] = expf(v[k] - m); s += v[k]; }
    #pragma unroll
    for (int o = 16; o; o >>= 1) s += __shfl_xor_sync(0xffffffffu, s, o);
    if ((threadIdx.x & 31) == 0) shs[threadIdx.x >> 5] = s;
    __syncthreads();
    float tot = 0.f;
    #pragma unroll
    for (int i = 0; i < 8; i++) tot += shs[i];
    float inv = 1.f / tot;
    #pragma unroll
    for (int k = 0; k < 8; k++) r[threadIdx.x + k * 256] = v[k] * inv;
}

// ---------------- silu(gate)*up, in-place on gate ----------------
__global__ void silumul_k(float* __restrict__ g, const float* __restrict__ u) {
    long long i = (long long)blockIdx.x * blockDim.x + threadIdx.x;
    const long long total = (long long)Tt * FFN_;
    if (i >= total) return;
    float x = g[i];
    g[i] = (x / (1.f + expf(-x))) * u[i];
}

// ---------------- launch ----------------
extern "C" void kernel_launch(void* const* d_in, const int* in_sizes, int n_in,
                              void* d_out, int out_size) {
    (void)in_sizes; (void)n_in; (void)out_size;
    const float* query  = (const float*)d_in[0];
    const float* keyval = (const float*)d_in[1];
    const float* g_q    = (const float*)d_in[2];
    const float* g_kv   = (const float*)d_in[3];
    const float* g_ffn  = (const float*)d_in[4];
    const float* w_qc   = (const float*)d_in[5];
    const float* w_kc   = (const float*)d_in[6];
    const float* w_qr   = (const float*)d_in[7];
    const float* w_kr   = (const float*)d_in[8];
    const float* w_v    = (const float*)d_in[9];
    const float* w_o    = (const float*)d_in[10];
    const float* w_gate = (const float*)d_in[11];
    const float* w_up   = (const float*)d_in[12];
    const float* w_down = (const float*)d_in[13];
    float* out = (float*)d_out;

    float* S = nullptr;
    cudaGetSymbolAddress((void**)&S, g_scratch);
    float* qn   = S + O_QN;
    float* kvn  = S + O_KVN;
    float* qc   = S + O_QC;
    float* kc   = S + O_KC;
    float* qr   = S + O_QR;
    float* kr   = S + O_KR;
    float* vv   = S + O_V;
    float* qcat = S + O_QCAT;
    float* kcat = S + O_KCAT;
    float* sc   = S + O_SC;
    float* att  = S + O_ATT;
    float* x    = S + O_X;
    float* xn   = S + O_XN;
    float* gate = S + O_GATE;
    float* up   = S + O_UP;

    // 1. RMSNorm inputs
    rmsnorm_k<<<Tt, 256>>>(query,  g_q,  qn);
    rmsnorm_k<<<Tt, 256>>>(keyval, g_kv, kvn);

    // 2. Projections (M=4096 tokens)
    {
        dim3 grid(Dm / 128, Tt / 128, 1);
        sgemm_k<false><<<grid, 256>>>(qn,  w_qc, nullptr, qc, Tt, Dm, Dm, Dm, Dm, Dm, 0,0,0,0,0,0, 1.f);
        sgemm_k<false><<<grid, 256>>>(kvn, w_kc, nullptr, kc, Tt, Dm, Dm, Dm, Dm, Dm, 0,0,0,0,0,0, 1.f);
        sgemm_k<false><<<grid, 256>>>(kvn, w_v,  nullptr, vv, Tt, Dm, Dm, Dm, Dm, Dm, 0,0,0,0,0,0, 1.f);
    }
    {
        dim3 grid((NH * DR) / 128, Tt / 128, 1);
        sgemm_k<false><<<grid, 256>>>(qn,  w_qr, nullptr, qr, Tt, NH * DR, Dm, Dm, NH * DR, NH * DR, 0,0,0,0,0,0, 1.f);
        sgemm_k<false><<<grid, 256>>>(kvn, w_kr, nullptr, kr, Tt, NH * DR, Dm, Dm, NH * DR, NH * DR, 0,0,0,0,0,0, 1.f);
    }

    // 3. RoPE (seq length per batch = 2048 for both q and kv)
    {
        long long pairs = (long long)Tt * NH * (DR / 2);
        int blocks = (int)((pairs + 255) / 256);
        rope_k<<<blocks, 256>>>(qr, Mq);
        rope_k<<<blocks, 256>>>(kr, Nq);
    }

    // 4. Pack [C|R] per head
    {
        long long tot = (long long)Tt * NH * DCAT;
        int blocks = (int)((tot + 255) / 256);
        pack_k<<<blocks, 256>>>(qc, qr, qcat);
        pack_k<<<blocks, 256>>>(kc, kr, kcat);
    }

    // 5. Scores = scale * Qcat @ Kcat^T, batched over (b,h): z = b*16+h
    {
        dim3 grid(Nq / 128, Mq / 128, Bq * NH);
        sgemm_k<true><<<grid, 256>>>(qcat, kcat, nullptr, sc,
            Mq, Nq, DCAT, NH * DCAT, NH * DCAT, Nq,
            (long long)Mq * NH * DCAT, (long long)DCAT,
            (long long)Nq * NH * DCAT, (long long)DCAT,
            (long long)NH * Mq * Nq, (long long)Mq * Nq,
            SCALE_);
    }

    // 6. Softmax rows
    softmax_k<<<Bq * NH * Mq, 256>>>(sc);

    // 7. attn @ V  -> att (T, NH*DH)
    {
        dim3 grid(DH / 128, Mq / 128, Bq * NH);
        sgemm_k<false><<<grid, 256>>>(sc, vv, nullptr, att,
            Mq, DH, Nq, Nq, NH * DH, NH * DH,
            (long long)NH * Mq * Nq, (long long)Mq * Nq,
            (long long)Nq * NH * DH, (long long)DH,
            (long long)Mq * NH * DH, (long long)DH,
            1.f);
    }

    // 8. x = att @ w_o + query
    {
        dim3 grid(Dm / 128, Tt / 128, 1);
        sgemm_k<false><<<grid, 256>>>(att, w_o, query, x, Tt, Dm, NH * DH,
                                      NH * DH, Dm, Dm, 0,0,0,0,0,0, 1.f);
    }

    // 9. RMSNorm -> xn
    rmsnorm_k<<<Tt, 256>>>(x, g_ffn, xn);

    // 10. gate / up
    {
        dim3 grid(FFN_ / 128, Tt / 128, 1);
        sgemm_k<false><<<grid, 256>>>(xn, w_gate, nullptr, gate, Tt, FFN_, Dm, Dm, FFN_, FFN_, 0,0,0,0,0,0, 1.f);
        sgemm_k<false><<<grid, 256>>>(xn, w_up,   nullptr, up,   Tt, FFN_, Dm, Dm, FFN_, FFN_, 0,0,0,0,0,0, 1.f);
    }

    // 11. h = silu(gate)*up (in-place on gate)
    {
        long long tot = (long long)Tt * FFN_;
        int blocks = (int)((tot + 255) / 256);
        silumul_k<<<blocks, 256>>>(gate, up);
    }

    // 12. out = h @ w_down + x
    {
        dim3 grid(Dm / 128, Tt / 128, 1);
        sgemm_k<false><<<grid, 256>>>(gate, w_down, x, out, Tt, Dm, FFN_,
                                      FFN_, Dm, Dm, 0,0,0,0,0,0, 1.f);
    }
}

// round 4
// speedup vs baseline: 2.8056x; 2.8056x over previous
#include <cuda_runtime.h>
#include <cuda_bf16.h>
#include <math.h>

// Problem constants
#define Bq   2
#define Mq   2048
#define Nq   2048
#define Dm   2048
#define NH   16
#define DH   128
#define DR   64
#define FFN_ 8192
#define Tt   (Bq*Mq)
#define DCAT (DH+DR)          // 192
#define SCALE_ (0.0721687836487032f) // 1/sqrt(192)

// ---------------- scratch ----------------
#define O_QN    0LL
#define O_KVN   (O_QN   + (long long)Tt*Dm)
#define O_QC    (O_KVN  + (long long)Tt*Dm)
#define O_KC    (O_QC   + (long long)Tt*NH*DH)
#define O_QR    (O_KC   + (long long)Tt*NH*DH)
#define O_KR    (O_QR   + (long long)Tt*NH*DR)
#define O_V     (O_KR   + (long long)Tt*NH*DR)
#define O_QCAT  (O_V    + (long long)Tt*NH*DH)
#define O_KCAT  (O_QCAT + (long long)Tt*NH*DCAT)
#define O_SC    (O_KCAT + (long long)Tt*NH*DCAT)
#define O_ATT   (O_SC   + (long long)Bq*NH*Mq*Nq)
#define O_X     (O_ATT  + (long long)Tt*NH*DH)
#define O_XN    (O_X    + (long long)Tt*Dm)
#define O_GATE  (O_XN   + (long long)Tt*Dm)
#define O_UP    (O_GATE + (long long)Tt*FFN_)
#define O_TOTAL (O_UP   + (long long)Tt*FFN_)

__device__ float g_scratch[O_TOTAL];

// ---------------- RMSNorm ----------------
__global__ void rmsnorm_k(const float* __restrict__ x, const float* __restrict__ g,
                          float* __restrict__ y) {
    const int D = Dm;
    long long row = blockIdx.x;
    const float* xr = x + row * D;
    float* yr = y + row * D;
    float s = 0.f;
    for (int i = threadIdx.x; i < D; i += blockDim.x) { float v = xr[i]; s += v * v; }
    #pragma unroll
    for (int o = 16; o; o >>= 1) s += __shfl_xor_sync(0xffffffffu, s, o);
    __shared__ float sh[8];
    if ((threadIdx.x & 31) == 0) sh[threadIdx.x >> 5] = s;
    __syncthreads();
    float tot = 0.f;
    #pragma unroll
    for (int i = 0; i < 8; i++) tot += sh[i];
    float n = rsqrtf(tot / (float)D + 1e-6f);
    for (int i = threadIdx.x; i < D; i += blockDim.x) yr[i] = xr[i] * n * g[i];
}

// ---------------- tf32 tensor-core GEMM ----------------
// C[M,N] = alpha * A[M,K] @ B + residual R
// TB=false: B row-major [K,N]   (B[k*ldb+n])
// TB=true : B row-major [N,K]   (C = A @ B^T)
// Batched over blockIdx.z = b*16+h with per-operand strides.
#define BM 128
#define BN 128
#define BK 16
#define LDA_S 20      // As/Bs(TB) row stride in floats: 20*r mod 32 spans all banks
#define LDB_S 136     // Bs(non-TB) row stride: 8*k+n distinct mod 32

__device__ __forceinline__ unsigned f2tf(float f) {
    unsigned r; asm("cvt.rna.tf32.f32 %0, %1;" : "=r"(r) : "f"(f)); return r;
}

template<bool TB>
__global__ void __launch_bounds__(256) mm_k(
    const float* __restrict__ A, const float* __restrict__ B,
    const float* __restrict__ R, float* __restrict__ C,
    int M, int N, int K, int lda, int ldb, int ldc,
    long long aB, long long aH, long long bB, long long bH,
    long long cB, long long cH, float alpha)
{
    int z = blockIdx.z, bb = z >> 4, hh = z & 15;
    A += bb * aB + hh * aH;
    B += bb * bB + hh * bH;
    C += bb * cB + hh * cH;
    if (R) R += bb * cB + hh * cH;

    constexpr int BSZ = TB ? (BN * LDA_S) : (BK * LDB_S);
    __shared__ float As[2][BM * LDA_S];
    __shared__ float Bs[2][BSZ];

    const int tid = threadIdx.x;
    const int row0 = blockIdx.y * BM, col0 = blockIdx.x * BN;

    const int lane = tid & 31, warp = tid >> 5;
    const int g  = lane >> 2, tg = lane & 3;
    const int mb = (warp >> 1) * 32;     // 4 warp-rows
    const int nb = (warp & 1) * 64;      // 2 warp-cols

    float acc[2][8][4];
    #pragma unroll
    for (int mi = 0; mi < 2; mi++)
        #pragma unroll
        for (int ni = 0; ni < 8; ni++)
            #pragma unroll
            for (int q = 0; q < 4; q++) acc[mi][ni][q] = 0.f;

    // --- async tile copy ---
    auto copyA = [&](int buf, int kt) {
        #pragma unroll
        for (int q = tid; q < 512; q += 256) {
            int r = q >> 2, cs = (q & 3) * 4;
            const float* gp = A + (long long)(row0 + r) * lda + kt + cs;
            unsigned s = (unsigned)__cvta_generic_to_shared(&As[buf][r * LDA_S + cs]);
            asm volatile("cp.async.ca.shared.global [%0], [%1], 16;\n" :: "r"(s), "l"(gp));
        }
    };
    auto copyB = [&](int buf, int kt) {
        if (TB) {
            #pragma unroll
            for (int q = tid; q < 512; q += 256) {
                int r = q >> 2, cs = (q & 3) * 4;
                const float* gp = B + (long long)(col0 + r) * ldb + kt + cs;
                unsigned s = (unsigned)__cvta_generic_to_shared(&Bs[buf][r * LDA_S + cs]);
                asm volatile("cp.async.ca.shared.global [%0], [%1], 16;\n" :: "r"(s), "l"(gp));
            }
        } else {
            #pragma unroll
            for (int q = tid; q < 512; q += 256) {
                int kr = q >> 5, ns = (q & 31) * 4;
                const float* gp = B + (long long)(kt + kr) * ldb + col0 + ns;
                unsigned s = (unsigned)__cvta_generic_to_shared(&Bs[buf][kr * LDB_S + ns]);
                asm volatile("cp.async.ca.shared.global [%0], [%1], 16;\n" :: "r"(s), "l"(gp));
            }
        }
    };

    copyA(0, 0); copyB(0, 0);
    asm volatile("cp.async.commit_group;\n" ::: "memory");

    const int nt = K / BK;
    for (int t = 0; t < nt; ++t) {
        int cur = t & 1;
        if (t + 1 < nt) {
            copyA(cur ^ 1, (t + 1) * BK);
            copyB(cur ^ 1, (t + 1) * BK);
            asm volatile("cp.async.commit_group;\n" ::: "memory");
            asm volatile("cp.async.wait_group 1;\n" ::: "memory");
        } else {
            asm volatile("cp.async.wait_group 0;\n" ::: "memory");
        }
        __syncthreads();

        const float* as = As[cur];
        const float* bs = Bs[cur];

        #pragma unroll
        for (int kk = 0; kk < BK; kk += 8) {
            unsigned a[2][4], b[8][2];
            #pragma unroll
            for (int mi = 0; mi < 2; ++mi) {
                int r = mb + mi * 16 + g;
                a[mi][0] = f2tf(as[r * LDA_S + kk + tg]);
                a[mi][1] = f2tf(as[(r + 8) * LDA_S + kk + tg]);
                a[mi][2] = f2tf(as[r * LDA_S + kk + tg + 4]);
                a[mi][3] = f2tf(as[(r + 8) * LDA_S + kk + tg + 4]);
            }
            #pragma unroll
            for (int ni = 0; ni < 8; ++ni) {
                int n = nb + ni * 8 + g;
                if (TB) {
                    b[ni][0] = f2tf(bs[n * LDA_S + kk + tg]);
                    b[ni][1] = f2tf(bs[n * LDA_S + kk + tg + 4]);
                } else {
                    b[ni][0] = f2tf(bs[(kk + tg) * LDB_S + n]);
                    b[ni][1] = f2tf(bs[(kk + tg + 4) * LDB_S + n]);
                }
            }
            #pragma unroll
            for (int mi = 0; mi < 2; ++mi)
                #pragma unroll
                for (int ni = 0; ni < 8; ++ni)
                    asm volatile(
                        "mma.sync.aligned.m16n8k8.row.col.f32.tf32.tf32.f32 "
                        "{%0,%1,%2,%3}, {%4,%5,%6,%7}, {%8,%9}, {%0,%1,%2,%3};\n"
                        : "+f"(acc[mi][ni][0]), "+f"(acc[mi][ni][1]),
                          "+f"(acc[mi][ni][2]), "+f"(acc[mi][ni][3])
                        : "r"(a[mi][0]), "r"(a[mi][1]), "r"(a[mi][2]), "r"(a[mi][3]),
                          "r"(b[ni][0]), "r"(b[ni][1]));
        }
        __syncthreads();
    }

    // epilogue
    #pragma unroll
    for (int mi = 0; mi < 2; ++mi) {
        #pragma unroll
        for (int ni = 0; ni < 8; ++ni) {
            long long rr = row0 + mb + mi * 16 + g;
            long long cc = col0 + nb + ni * 8 + tg * 2;
            float2 v0 = make_float2(acc[mi][ni][0] * alpha, acc[mi][ni][1] * alpha);
            float2 v1 = make_float2(acc[mi][ni][2] * alpha, acc[mi][ni][3] * alpha);
            if (R) {
                float2 r0 = *(const float2*)&R[rr * ldc + cc];
                float2 r1 = *(const float2*)&R[(rr + 8) * ldc + cc];
                v0.x += r0.x; v0.y += r0.y; v1.x += r1.x; v1.y += r1.y;
            }
            *(float2*)&C[rr * ldc + cc] = v0;
            *(float2*)&C[(rr + 8) * ldc + cc] = v1;
        }
    }
}

// ---------------- RoPE ----------------
__global__ void rope_k(float* __restrict__ x, int seqlen) {
    long long g = (long long)blockIdx.x * blockDim.x + threadIdx.x;
    const long long total = (long long)Tt * NH * (DR / 2);
    if (g >= total) return;
    int j = (int)(g % (DR / 2));
    long long th = g / (DR / 2);
    int h = (int)(th % NH);
    long long tok = th / NH;
    int s = (int)(tok % seqlen);
    float freq = (float)pow((double)1000000.0, -2.0 * j / (double)DR);
    float ang = (float)s * freq;
    float c = cosf(ang), si = sinf(ang);
    long long idx = tok * (NH * DR) + h * DR + 2 * j;
    float x1 = x[idx], x2 = x[idx + 1];
    x[idx]     = x1 * c - x2 * si;
    x[idx + 1] = x2 * c + x1 * si;
}

// ---------------- pack [C | R] ----------------
__global__ void pack_k(const float* __restrict__ c, const float* __restrict__ rr,
                       float* __restrict__ cat) {
    long long i = (long long)blockIdx.x * blockDim.x + threadIdx.x;
    const long long total = (long long)Tt * NH * DCAT;
    if (i >= total) return;
    int d = (int)(i % DCAT);
    long long th = i / DCAT;
    int h = (int)(th % NH);
    long long tok = th / NH;
    cat[i] = (d < DH) ? c[tok * (NH * DH) + h * DH + d]
                      : rr[tok * (NH * DR) + h * DR + (d - DH)];
}

// ---------------- row softmax ----------------
__global__ void softmax_k(float* __restrict__ sc) {
    const int N = Nq;
    float* r = sc + (long long)blockIdx.x * N;
    float v[8];
    float m = -3.4e38f;
    #pragma unroll
    for (int k = 0; k < 8; k++) { v[k] = r[threadIdx.x + k * 256]; m = fmaxf(m, v[k]); }
    #pragma unroll
    for (int o = 16; o; o >>= 1) m = fmaxf(m, __shfl_xor_sync(0xffffffffu, m, o));
    __shared__ float shm[8], shs[8];
    if ((threadIdx.x & 31) == 0) shm[threadIdx.x >> 5] = m;
    __syncthreads();
    #pragma unroll
    for (int i = 0; i < 8; i++) m = fmaxf(m, shm[i]);
    float s = 0.f;
    #pragma unroll
    for (int k = 0; k < 8; k++) { v[k] = expf(v[k] - m); s += v[k]; }
    #pragma unroll
    for (int o = 16; o; o >>= 1) s += __shfl_xor_sync(0xffffffffu, s, o);
    if ((threadIdx.x & 31) == 0) shs[threadIdx.x >> 5] = s;
    __syncthreads();
    float tot = 0.f;
    #pragma unroll
    for (int i = 0; i < 8; i++) tot += shs[i];
    float inv = 1.f / tot;
    #pragma unroll
    for (int k = 0; k < 8; k++) r[threadIdx.x + k * 256] = v[k] * inv;
}

// ---------------- silu(gate)*up ----------------
__global__ void silumul_k(float* __restrict__ g, const float* __restrict__ u) {
    long long i = (long long)blockIdx.x * blockDim.x + threadIdx.x;
    const long long total = (long long)Tt * FFN_;
    if (i >= total) return;
    float x = g[i];
    g[i] = (x / (1.f + expf(-x))) * u[i];
}

// ---------------- launch ----------------
extern "C" void kernel_launch(void* const* d_in, const int* in_sizes, int n_in,
                              void* d_out, int out_size) {
    (void)in_sizes; (void)n_in; (void)out_size;
    const float* query  = (const float*)d_in[0];
    const float* keyval = (const float*)d_in[1];
    const float* g_q    = (const float*)d_in[2];
    const float* g_kv   = (const float*)d_in[3];
    const float* g_ffn  = (const float*)d_in[4];
    const float* w_qc   = (const float*)d_in[5];
    const float* w_kc   = (const float*)d_in[6];
    const float* w_qr   = (const float*)d_in[7];
    const float* w_kr   = (const float*)d_in[8];
    const float* w_v    = (const float*)d_in[9];
    const float* w_o    = (const float*)d_in[10];
    const float* w_gate = (const float*)d_in[11];
    const float* w_up   = (const float*)d_in[12];
    const float* w_down = (const float*)d_in[13];
    float* out = (float*)d_out;

    float* S = nullptr;
    cudaGetSymbolAddress((void**)&S, g_scratch);
    float* qn   = S + O_QN;
    float* kvn  = S + O_KVN;
    float* qc   = S + O_QC;
    float* kc   = S + O_KC;
    float* qr   = S + O_QR;
    float* kr   = S + O_KR;
    float* vv   = S + O_V;
    float* qcat = S + O_QCAT;
    float* kcat = S + O_KCAT;
    float* sc   = S + O_SC;
    float* att  = S + O_ATT;
    float* x    = S + O_X;
    float* xn   = S + O_XN;
    float* gate = S + O_GATE;
    float* up   = S + O_UP;

    // 1. RMSNorm inputs
    rmsnorm_k<<<Tt, 256>>>(query,  g_q,  qn);
    rmsnorm_k<<<Tt, 256>>>(keyval, g_kv, kvn);

    // 2. Projections
    {
        dim3 grid(Dm / BN, Tt / BM, 1);
        mm_k<false><<<grid, 256>>>(qn,  w_qc, nullptr, qc, Tt, Dm, Dm, Dm, Dm, Dm, 0,0,0,0,0,0, 1.f);
        mm_k<false><<<grid, 256>>>(kvn, w_kc, nullptr, kc, Tt, Dm, Dm, Dm, Dm, Dm, 0,0,0,0,0,0, 1.f);
        mm_k<false><<<grid, 256>>>(kvn, w_v,  nullptr, vv, Tt, Dm, Dm, Dm, Dm, Dm, 0,0,0,0,0,0, 1.f);
    }
    {
        dim3 grid((NH * DR) / BN, Tt / BM, 1);
        mm_k<false><<<grid, 256>>>(qn,  w_qr, nullptr, qr, Tt, NH * DR, Dm, Dm, NH * DR, NH * DR, 0,0,0,0,0,0, 1.f);
        mm_k<false><<<grid, 256>>>(kvn, w_kr, nullptr, kr, Tt, NH * DR, Dm, Dm, NH * DR, NH * DR, 0,0,0,0,0,0, 1.f);
    }

    // 3. RoPE
    {
        long long pairs = (long long)Tt * NH * (DR / 2);
        int blocks = (int)((pairs + 255) / 256);
        rope_k<<<blocks, 256>>>(qr, Mq);
        rope_k<<<blocks, 256>>>(kr, Nq);
    }

    // 4. Pack [C|R]
    {
        long long tot = (long long)Tt * NH * DCAT;
        int blocks = (int)((tot + 255) / 256);
        pack_k<<<blocks, 256>>>(qc, qr, qcat);
        pack_k<<<blocks, 256>>>(kc, kr, kcat);
    }

    // 5. Scores = scale * Qcat @ Kcat^T (batched over b,h)
    {
        dim3 grid(Nq / BN, Mq / BM, Bq * NH);
        mm_k<true><<<grid, 256>>>(qcat, kcat, nullptr, sc,
            Mq, Nq, DCAT, NH * DCAT, NH * DCAT, Nq,
            (long long)Mq * NH * DCAT, (long long)DCAT,
            (long long)Nq * NH * DCAT, (long long)DCAT,
            (long long)NH * Mq * Nq, (long long)Mq * Nq,
            SCALE_);
    }

    // 6. Softmax
    softmax_k<<<Bq * NH * Mq, 256>>>(sc);

    // 7. attn @ V
    {
        dim3 grid(DH / BN, Mq / BM, Bq * NH);
        mm_k<false><<<grid, 256>>>(sc, vv, nullptr, att,
            Mq, DH, Nq, Nq, NH * DH, NH * DH,
            (long long)NH * Mq * Nq, (long long)Mq * Nq,
            (long long)Nq * NH * DH, (long long)DH,
            (long long)Mq * NH * DH, (long long)DH,
            1.f);
    }

    // 8. x = att @ w_o + query
    {
        dim3 grid(Dm / BN, Tt / BM, 1);
        mm_k<false><<<grid, 256>>>(att, w_o, query, x, Tt, Dm, NH * DH,
                                   NH * DH, Dm, Dm, 0,0,0,0,0,0, 1.f);
    }

    // 9. RMSNorm -> xn
    rmsnorm_k<<<Tt, 256>>>(x, g_ffn, xn);

    // 10. gate / up
    {
        dim3 grid(FFN_ / BN, Tt / BM, 1);
        mm_k<false><<<grid, 256>>>(xn, w_gate, nullptr, gate, Tt, FFN_, Dm, Dm, FFN_, FFN_, 0,0,0,0,0,0, 1.f);
        mm_k<false><<<grid, 256>>>(xn, w_up,   nullptr, up,   Tt, FFN_, Dm, Dm, FFN_, FFN_, 0,0,0,0,0,0, 1.f);
    }

    // 11. silu(gate)*up
    {
        long long tot = (long long)Tt * FFN_;
        int blocks = (int)((tot + 255) / 256);
        silumul_k<<<blocks, 256>>>(gate, up);
    }

    // 12. out = h @ w_down + x
    {
        dim3 grid(Dm / BN, Tt / BM, 1);
        mm_k<false><<<grid, 256>>>(gate, w_down, x, out, Tt, Dm, FFN_,
                                   FFN_, Dm, Dm, 0,0,0,0,0,0, 1.f);
    }
}

// round 8
// speedup vs baseline: 2.9534x; 1.0527x over previous
#include <cuda_runtime.h>
#include <cuda_bf16.h>
#include <math.h>

// Problem constants
#define Bq   2
#define Mq   2048
#define Nq   2048
#define Dm   2048
#define NH   16
#define DH   128
#define DR   64
#define FFN_ 8192
#define Tt   (Bq*Mq)
#define DCAT (DH+DR)          // 192
#define SCALE_ (0.0721687836487032f) // 1/sqrt(192)

// ---------------- scratch ----------------
#define O_QN    0LL
#define O_KVN   (O_QN   + (long long)Tt*Dm)
#define O_QC    (O_KVN  + (long long)Tt*Dm)
#define O_KC    (O_QC   + (long long)Tt*NH*DH)
#define O_QR    (O_KC   + (long long)Tt*NH*DH)
#define O_KR    (O_QR   + (long long)Tt*NH*DR)
#define O_V     (O_KR   + (long long)Tt*NH*DR)
#define O_QCAT  (O_V    + (long long)Tt*NH*DH)
#define O_KCAT  (O_QCAT + (long long)Tt*NH*DCAT)
#define O_SC    (O_KCAT + (long long)Tt*NH*DCAT)
#define O_ATT   (O_SC   + (long long)Bq*NH*Mq*Nq)
#define O_X     (O_ATT  + (long long)Tt*NH*DH)
#define O_XN    (O_X    + (long long)Tt*Dm)
#define O_GATE  (O_XN   + (long long)Tt*Dm)
#define O_UP    (O_GATE + (long long)Tt*FFN_)
// converted (tf32-rounded) weights
#define SZ_DD   ((long long)Dm*Dm)        // 4194304
#define SZ_DR2  ((long long)Dm*NH*DR)     // 2097152
#define SZ_DF   ((long long)Dm*FFN_)      // 16777216
#define O_WQC   (O_UP   + (long long)Tt*FFN_)
#define O_WKC   (O_WQC  + SZ_DD)
#define O_WQR   (O_WKC  + SZ_DD)
#define O_WKR   (O_WQR  + SZ_DR2)
#define O_WV    (O_WKR  + SZ_DR2)
#define O_WO    (O_WV   + SZ_DD)
#define O_WGATE (O_WO   + SZ_DD)
#define O_WUP   (O_WGATE+ SZ_DF)
#define O_WDOWN (O_WUP  + SZ_DF)
#define O_TOTAL (O_WDOWN+ SZ_DF)

__device__ float g_scratch[O_TOTAL];

__device__ __forceinline__ float tf32r(float f) {
    unsigned r; asm("cvt.rna.tf32.f32 %0, %1;" : "=r"(r) : "f"(f));
    return __uint_as_float(r);
}

// ---------------- weight tf32 pre-round ----------------
__global__ void cvtw_k(const float* __restrict__ src, float* __restrict__ dst, long long n) {
    long long i = (long long)blockIdx.x * blockDim.x + threadIdx.x;
    long long stride = (long long)gridDim.x * blockDim.x;
    for (; i < n; i += stride) dst[i] = tf32r(src[i]);
}

// ---------------- RMSNorm (output tf32-rounded: always feeds GEMM A) ----------------
__global__ void rmsnorm_k(const float* __restrict__ x, const float* __restrict__ g,
                          float* __restrict__ y) {
    const int D = Dm;
    long long row = blockIdx.x;
    const float* xr = x + row * D;
    float* yr = y + row * D;
    float s = 0.f;
    for (int i = threadIdx.x; i < D; i += blockDim.x) { float v = xr[i]; s += v * v; }
    #pragma unroll
    for (int o = 16; o; o >>= 1) s += __shfl_xor_sync(0xffffffffu, s, o);
    __shared__ float sh[8];
    if ((threadIdx.x & 31) == 0) sh[threadIdx.x >> 5] = s;
    __syncthreads();
    float tot = 0.f;
    #pragma unroll
    for (int i = 0; i < 8; i++) tot += sh[i];
    float n = rsqrtf(tot / (float)D + 1e-6f);
    for (int i = threadIdx.x; i < D; i += blockDim.x) yr[i] = tf32r(xr[i] * n * g[i]);
}

// ---------------- tf32 tensor-core GEMM (operands pre-rounded; no inner-loop cvt) ----------------
// C[M,N] = alpha * A[M,K] @ B + residual R
// TB=false: B row-major [K,N]; TB=true: B row-major [N,K] (C = A @ B^T)
// RND: round output to tf32 (when C feeds a later GEMM as raw operand)
#define BM 128
#define BN 128
#define BK 16
#define LDA_S 20
#define LDB_S 136

template<bool TB, bool RND>
__global__ void __launch_bounds__(256) mm_k(
    const float* __restrict__ A, const float* __restrict__ B,
    const float* __restrict__ R, float* __restrict__ C,
    int M, int N, int K, int lda, int ldb, int ldc,
    long long aB, long long aH, long long bB, long long bH,
    long long cB, long long cH, float alpha)
{
    int z = blockIdx.z, bb = z >> 4, hh = z & 15;
    A += bb * aB + hh * aH;
    B += bb * bB + hh * bH;
    C += bb * cB + hh * cH;
    if (R) R += bb * cB + hh * cH;

    constexpr int BSZ = TB ? (BN * LDA_S) : (BK * LDB_S);
    __shared__ float As[2][BM * LDA_S];
    __shared__ float Bs[2][BSZ];

    const int tid = threadIdx.x;
    const int row0 = blockIdx.y * BM, col0 = blockIdx.x * BN;

    const int lane = tid & 31, warp = tid >> 5;
    const int g  = lane >> 2, tg = lane & 3;
    const int mb = (warp >> 1) * 32;
    const int nb = (warp & 1) * 64;

    float acc[2][8][4];
    #pragma unroll
    for (int mi = 0; mi < 2; mi++)
        #pragma unroll
        for (int ni = 0; ni < 8; ni++)
            #pragma unroll
            for (int q = 0; q < 4; q++) acc[mi][ni][q] = 0.f;

    auto copyA = [&](int buf, int kt) {
        #pragma unroll
        for (int q = tid; q < 512; q += 256) {
            int r = q >> 2, cs = (q & 3) * 4;
            const float* gp = A + (long long)(row0 + r) * lda + kt + cs;
            unsigned s = (unsigned)__cvta_generic_to_shared(&As[buf][r * LDA_S + cs]);
            asm volatile("cp.async.ca.shared.global [%0], [%1], 16;\n" :: "r"(s), "l"(gp));
        }
    };
    auto copyB = [&](int buf, int kt) {
        if (TB) {
            #pragma unroll
            for (int q = tid; q < 512; q += 256) {
                int r = q >> 2, cs = (q & 3) * 4;
                const float* gp = B + (long long)(col0 + r) * ldb + kt + cs;
                unsigned s = (unsigned)__cvta_generic_to_shared(&Bs[buf][r * LDA_S + cs]);
                asm volatile("cp.async.ca.shared.global [%0], [%1], 16;\n" :: "r"(s), "l"(gp));
            }
        } else {
            #pragma unroll
            for (int q = tid; q < 512; q += 256) {
                int kr = q >> 5, ns = (q & 31) * 4;
                const float* gp = B + (long long)(kt + kr) * ldb + col0 + ns;
                unsigned s = (unsigned)__cvta_generic_to_shared(&Bs[buf][kr * LDB_S + ns]);
                asm volatile("cp.async.ca.shared.global [%0], [%1], 16;\n" :: "r"(s), "l"(gp));
            }
        }
    };

    copyA(0, 0); copyB(0, 0);
    asm volatile("cp.async.commit_group;\n" ::: "memory");

    const int nt = K / BK;
    for (int t = 0; t < nt; ++t) {
        int cur = t & 1;
        if (t + 1 < nt) {
            copyA(cur ^ 1, (t + 1) * BK);
            copyB(cur ^ 1, (t + 1) * BK);
            asm volatile("cp.async.commit_group;\n" ::: "memory");
            asm volatile("cp.async.wait_group 1;\n" ::: "memory");
        } else {
            asm volatile("cp.async.wait_group 0;\n" ::: "memory");
        }
        __syncthreads();

        const float* as = As[cur];
        const float* bs = Bs[cur];

        #pragma unroll
        for (int kk = 0; kk < BK; kk += 8) {
            unsigned a[2][4], b[8][2];
            #pragma unroll
            for (int mi = 0; mi < 2; ++mi) {
                int r = mb + mi * 16 + g;
                a[mi][0] = __float_as_uint(as[r * LDA_S + kk + tg]);
                a[mi][1] = __float_as_uint(as[(r + 8) * LDA_S + kk + tg]);
                a[mi][2] = __float_as_uint(as[r * LDA_S + kk + tg + 4]);
                a[mi][3] = __float_as_uint(as[(r + 8) * LDA_S + kk + tg + 4]);
            }
            #pragma unroll
            for (int ni = 0; ni < 8; ++ni) {
                int n = nb + ni * 8 + g;
                if (TB) {
                    b[ni][0] = __float_as_uint(bs[n * LDA_S + kk + tg]);
                    b[ni][1] = __float_as_uint(bs[n * LDA_S + kk + tg + 4]);
                } else {
                    b[ni][0] = __float_as_uint(bs[(kk + tg) * LDB_S + n]);
                    b[ni][1] = __float_as_uint(bs[(kk + tg + 4) * LDB_S + n]);
                }
            }
            #pragma unroll
            for (int mi = 0; mi < 2; ++mi)
                #pragma unroll
                for (int ni = 0; ni < 8; ++ni)
                    asm volatile(
                        "mma.sync.aligned.m16n8k8.row.col.f32.tf32.tf32.f32 "
                        "{%0,%1,%2,%3}, {%4,%5,%6,%7}, {%8,%9}, {%0,%1,%2,%3};\n"
                        : "+f"(acc[mi][ni][0]), "+f"(acc[mi][ni][1]),
                          "+f"(acc[mi][ni][2]), "+f"(acc[mi][ni][3])
                        : "r"(a[mi][0]), "r"(a[mi][1]), "r"(a[mi][2]), "r"(a[mi][3]),
                          "r"(b[ni][0]), "r"(b[ni][1]));
        }
        __syncthreads();
    }

    #pragma unroll
    for (int mi = 0; mi < 2; ++mi) {
        #pragma unroll
        for (int ni = 0; ni < 8; ++ni) {
            long long rr = row0 + mb + mi * 16 + g;
            long long cc = col0 + nb + ni * 8 + tg * 2;
            float2 v0 = make_float2(acc[mi][ni][0] * alpha, acc[mi][ni][1] * alpha);
            float2 v1 = make_float2(acc[mi][ni][2] * alpha, acc[mi][ni][3] * alpha);
            if (R) {
                float2 r0 = *(const float2*)&R[rr * ldc + cc];
                float2 r1 = *(const float2*)&R[(rr + 8) * ldc + cc];
                v0.x += r0.x; v0.y += r0.y; v1.x += r1.x; v1.y += r1.y;
            }
            if (RND) {
                v0.x = tf32r(v0.x); v0.y = tf32r(v0.y);
                v1.x = tf32r(v1.x); v1.y = tf32r(v1.y);
            }
            *(float2*)&C[rr * ldc + cc] = v0;
            *(float2*)&C[(rr + 8) * ldc + cc] = v1;
        }
    }
}

// ---------------- RoPE (fp32 in-place; pack rounds afterwards) ----------------
__global__ void rope_k(float* __restrict__ x, int seqlen) {
    long long g = (long long)blockIdx.x * blockDim.x + threadIdx.x;
    const long long total = (long long)Tt * NH * (DR / 2);
    if (g >= total) return;
    int j = (int)(g % (DR / 2));
    long long th = g / (DR / 2);
    int h = (int)(th % NH);
    long long tok = th / NH;
    int s = (int)(tok % seqlen);
    float freq = (float)pow((double)1000000.0, -2.0 * j / (double)DR);
    float ang = (float)s * freq;
    float c = cosf(ang), si = sinf(ang);
    long long idx = tok * (NH * DR) + h * DR + 2 * j;
    float x1 = x[idx], x2 = x[idx + 1];
    x[idx]     = x1 * c - x2 * si;
    x[idx + 1] = x2 * c + x1 * si;
}

// ---------------- pack [C | R] -> (T, NH, 192), tf32-rounded ----------------
__global__ void pack_k(const float* __restrict__ c, const float* __restrict__ rr,
                       float* __restrict__ cat) {
    long long i = (long long)blockIdx.x * blockDim.x + threadIdx.x;
    const long long total = (long long)Tt * NH * DCAT;
    if (i >= total) return;
    int d = (int)(i % DCAT);
    long long th = i / DCAT;
    int h = (int)(th % NH);
    long long tok = th / NH;
    float v = (d < DH) ? c[tok * (NH * DH) + h * DH + d]
                       : rr[tok * (NH * DR) + h * DR + (d - DH)];
    cat[i] = tf32r(v);
}

// ---------------- row softmax (output tf32-rounded: feeds attn@V as A) ----------------
__global__ void softmax_k(float* __restrict__ sc) {
    const int N = Nq;
    float* r = sc + (long long)blockIdx.x * N;
    float v[8];
    float m = -3.4e38f;
    #pragma unroll
    for (int k = 0; k < 8; k++) { v[k] = r[threadIdx.x + k * 256]; m = fmaxf(m, v[k]); }
    #pragma unroll
    for (int o = 16; o; o >>= 1) m = fmaxf(m, __shfl_xor_sync(0xffffffffu, m, o));
    __shared__ float shm[8], shs[8];
    if ((threadIdx.x & 31) == 0) shm[threadIdx.x >> 5] = m;
    __syncthreads();
    #pragma unroll
    for (int i = 0; i < 8; i++) m = fmaxf(m, shm[i]);
    float s = 0.f;
    #pragma unroll
    for (int k = 0; k < 8; k++) { v[k] = expf(v[k] - m); s += v[k]; }
    #pragma unroll
    for (int o = 16; o; o >>= 1) s += __shfl_xor_sync(0xffffffffu, s, o);
    if ((threadIdx.x & 31) == 0) shs[threadIdx.x >> 5] = s;
    __syncthreads();
    float tot = 0.f;
    #pragma unroll
    for (int i = 0; i < 8; i++) tot += shs[i];
    float inv = 1.f / tot;
    #pragma unroll
    for (int k = 0; k < 8; k++) r[threadIdx.x + k * 256] = tf32r(v[k] * inv);
}

// ---------------- silu(gate)*up, tf32-rounded (feeds w_down GEMM as A) ----------------
__global__ void silumul_k(float* __restrict__ g, const float* __restrict__ u) {
    long long i = (long long)blockIdx.x * blockDim.x + threadIdx.x;
    const long long total = (long long)Tt * FFN_;
    if (i >= total) return;
    float x = g[i];
    g[i] = tf32r((x / (1.f + expf(-x))) * u[i]);
}

// ---------------- launch ----------------
extern "C" void kernel_launch(void* const* d_in, const int* in_sizes, int n_in,
                              void* d_out, int out_size) {
    (void)in_sizes; (void)n_in; (void)out_size;
    const float* query  = (const float*)d_in[0];
    const float* keyval = (const float*)d_in[1];
    const float* g_q    = (const float*)d_in[2];
    const float* g_kv   = (const float*)d_in[3];
    const float* g_ffn  = (const float*)d_in[4];
    const float* w_qc   = (const float*)d_in[5];
    const float* w_kc   = (const float*)d_in[6];
    const float* w_qr   = (const float*)d_in[7];
    const float* w_kr   = (const float*)d_in[8];
    const float* w_v    = (const float*)d_in[9];
    const float* w_o    = (const float*)d_in[10];
    const float* w_gate = (const float*)d_in[11];
    const float* w_up   = (const float*)d_in[12];
    const float* w_down = (const float*)d_in[13];
    float* out = (float*)d_out;

    float* S = nullptr;
    cudaGetSymbolAddress((void**)&S, g_scratch);
    float* qn    = S + O_QN;
    float* kvn   = S + O_KVN;
    float* qc    = S + O_QC;
    float* kc    = S + O_KC;
    float* qr    = S + O_QR;
    float* kr    = S + O_KR;
    float* vv    = S + O_V;
    float* qcat  = S + O_QCAT;
    float* kcat  = S + O_KCAT;
    float* sc    = S + O_SC;
    float* att   = S + O_ATT;
    float* x     = S + O_X;
    float* xn    = S + O_XN;
    float* gate  = S + O_GATE;
    float* up    = S + O_UP;
    float* cwqc  = S + O_WQC;
    float* cwkc  = S + O_WKC;
    float* cwqr  = S + O_WQR;
    float* cwkr  = S + O_WKR;
    float* cwv   = S + O_WV;
    float* cwo   = S + O_WO;
    float* cwg   = S + O_WGATE;
    float* cwu   = S + O_WUP;
    float* cwd   = S + O_WDOWN;

    // 0. Pre-round weights to tf32 (once per launch; bandwidth-bound)
    cvtw_k<<<2048, 256>>>(w_qc,   cwqc, SZ_DD);
    cvtw_k<<<2048, 256>>>(w_kc,   cwkc, SZ_DD);
    cvtw_k<<<2048, 256>>>(w_qr,   cwqr, SZ_DR2);
    cvtw_k<<<2048, 256>>>(w_kr,   cwkr, SZ_DR2);
    cvtw_k<<<2048, 256>>>(w_v,    cwv,  SZ_DD);
    cvtw_k<<<2048, 256>>>(w_o,    cwo,  SZ_DD);
    cvtw_k<<<4096, 256>>>(w_gate, cwg,  SZ_DF);
    cvtw_k<<<4096, 256>>>(w_up,   cwu,  SZ_DF);
    cvtw_k<<<4096, 256>>>(w_down, cwd,  SZ_DF);

    // 1. RMSNorm inputs (tf32-rounded outputs)
    rmsnorm_k<<<Tt, 256>>>(query,  g_q,  qn);
    rmsnorm_k<<<Tt, 256>>>(keyval, g_kv, kvn);

    // 2. Projections
    {
        dim3 grid(Dm / BN, Tt / BM, 1);
        mm_k<false,false><<<grid, 256>>>(qn,  cwqc, nullptr, qc, Tt, Dm, Dm, Dm, Dm, Dm, 0,0,0,0,0,0, 1.f);
        mm_k<false,false><<<grid, 256>>>(kvn, cwkc, nullptr, kc, Tt, Dm, Dm, Dm, Dm, Dm, 0,0,0,0,0,0, 1.f);
        mm_k<false,true ><<<grid, 256>>>(kvn, cwv,  nullptr, vv, Tt, Dm, Dm, Dm, Dm, Dm, 0,0,0,0,0,0, 1.f);
    }
    {
        dim3 grid((NH * DR) / BN, Tt / BM, 1);
        mm_k<false,false><<<grid, 256>>>(qn,  cwqr, nullptr, qr, Tt, NH * DR, Dm, Dm, NH * DR, NH * DR, 0,0,0,0,0,0, 1.f);
        mm_k<false,false><<<grid, 256>>>(kvn, cwkr, nullptr, kr, Tt, NH * DR, Dm, Dm, NH * DR, NH * DR, 0,0,0,0,0,0, 1.f);
    }

    // 3. RoPE
    {
        long long pairs = (long long)Tt * NH * (DR / 2);
        int blocks = (int)((pairs + 255) / 256);
        rope_k<<<blocks, 256>>>(qr, Mq);
        rope_k<<<blocks, 256>>>(kr, Nq);
    }

    // 4. Pack [C|R] (tf32-rounded)
    {
        long long tot = (long long)Tt * NH * DCAT;
        int blocks = (int)((tot + 255) / 256);
        pack_k<<<blocks, 256>>>(qc, qr, qcat);
        pack_k<<<blocks, 256>>>(kc, kr, kcat);
    }

    // 5. Scores = scale * Qcat @ Kcat^T
    {
        dim3 grid(Nq / BN, Mq / BM, Bq * NH);
        mm_k<true,false><<<grid, 256>>>(qcat, kcat, nullptr, sc,
            Mq, Nq, DCAT, NH * DCAT, NH * DCAT, Nq,
            (long long)Mq * NH * DCAT, (long long)DCAT,
            (long long)Nq * NH * DCAT, (long long)DCAT,
            (long long)NH * Mq * Nq, (long long)Mq * Nq,
            SCALE_);
    }

    // 6. Softmax (tf32-rounded output)
    softmax_k<<<Bq * NH * Mq, 256>>>(sc);

    // 7. attn @ V (output rounded: feeds w_o GEMM)
    {
        dim3 grid(DH / BN, Mq / BM, Bq * NH);
        mm_k<false,true><<<grid, 256>>>(sc, vv, nullptr, att,
            Mq, DH, Nq, Nq, NH * DH, NH * DH,
            (long long)NH * Mq * Nq, (long long)Mq * Nq,
            (long long)Nq * NH * DH, (long long)DH,
            (long long)Mq * NH * DH, (long long)DH,
            1.f);
    }

    // 8. x = att @ w_o + query (fp32, residual)
    {
        dim3 grid(Dm / BN, Tt / BM, 1);
        mm_k<false,false><<<grid, 256>>>(att, cwo, query, x, Tt, Dm, NH * DH,
                                         NH * DH, Dm, Dm, 0,0,0,0,0,0, 1.f);
    }

    // 9. RMSNorm -> xn (rounded)
    rmsnorm_k<<<Tt, 256>>>(x, g_ffn, xn);

    // 10. gate / up
    {
        dim3 grid(FFN_ / BN, Tt / BM, 1);
        mm_k<false,false><<<grid, 256>>>(xn, cwg, nullptr, gate, Tt, FFN_, Dm, Dm, FFN_, FFN_, 0,0,0,0,0,0, 1.f);
        mm_k<false,false><<<grid, 256>>>(xn, cwu, nullptr, up,   Tt, FFN_, Dm, Dm, FFN_, FFN_, 0,0,0,0,0,0, 1.f);
    }

    // 11. silu(gate)*up (rounded)
    {
        long long tot = (long long)Tt * FFN_;
        int blocks = (int)((tot + 255) / 256);
        silumul_k<<<blocks, 256>>>(gate, up);
    }

    // 12. out = h @ w_down + x
    {
        dim3 grid(Dm / BN, Tt / BM, 1);
        mm_k<false,false><<<grid, 256>>>(gate, cwd, x, out, Tt, Dm, FFN_,
                                         FFN_, Dm, Dm, 0,0,0,0,0,0, 1.f);
    }
}

// round 9
// speedup vs baseline: 3.0111x; 1.0195x over previous
#include <cuda_runtime.h>
#include <cuda_bf16.h>
#include <math.h>

// Problem constants
#define Bq   2
#define Mq   2048
#define Nq   2048
#define Dm   2048
#define NH   16
#define DH   128
#define DR   64
#define FFN_ 8192
#define Tt   (Bq*Mq)
#define DCAT (DH+DR)          // 192
#define SCALE_ (0.0721687836487032f) // 1/sqrt(192)

// ---------------- scratch ----------------
#define O_QN    0LL
#define O_KVN   (O_QN   + (long long)Tt*Dm)
#define O_QC    (O_KVN  + (long long)Tt*Dm)
#define O_KC    (O_QC   + (long long)Tt*NH*DH)
#define O_QR    (O_KC   + (long long)Tt*NH*DH)
#define O_KR    (O_QR   + (long long)Tt*NH*DR)
#define O_V     (O_KR   + (long long)Tt*NH*DR)
#define O_QCAT  (O_V    + (long long)Tt*NH*DH)
#define O_KCAT  (O_QCAT + (long long)Tt*NH*DCAT)
#define O_SC    (O_KCAT + (long long)Tt*NH*DCAT)
#define O_ATT   (O_SC   + (long long)Bq*NH*Mq*Nq)
#define O_X     (O_ATT  + (long long)Tt*NH*DH)
#define O_XN    (O_X    + (long long)Tt*Dm)
#define O_GATE  (O_XN   + (long long)Tt*Dm)
#define O_UP    (O_GATE + (long long)Tt*FFN_)
// converted (tf32-rounded, TRANSPOSED [n][k]) weights
#define SZ_DD   ((long long)Dm*Dm)
#define SZ_DR2  ((long long)Dm*NH*DR)
#define SZ_DF   ((long long)Dm*FFN_)
#define O_WQC   (O_UP   + (long long)Tt*FFN_)
#define O_WKC   (O_WQC  + SZ_DD)
#define O_WQR   (O_WKC  + SZ_DD)
#define O_WKR   (O_WQR  + SZ_DR2)
#define O_WV    (O_WKR  + SZ_DR2)
#define O_WO    (O_WV   + SZ_DD)
#define O_WGATE (O_WO   + SZ_DD)
#define O_WUP   (O_WGATE+ SZ_DF)
#define O_WDOWN (O_WUP  + SZ_DF)
#define O_TOTAL (O_WDOWN+ SZ_DF)

__device__ float g_scratch[O_TOTAL];

__device__ __forceinline__ float tf32r(float f) {
    unsigned r; asm("cvt.rna.tf32.f32 %0, %1;" : "=r"(r) : "f"(f));
    return __uint_as_float(r);
}

// ---------------- weight tf32 round + transpose: src[K][N] -> dst[N][K] ----------------
__global__ void cvtwT_k(const float* __restrict__ src, float* __restrict__ dst,
                        int K, int N) {
    __shared__ float t[32][33];
    int n0 = blockIdx.x * 32, k0 = blockIdx.y * 32;
    int tx = threadIdx.x, ty0 = threadIdx.y;
    #pragma unroll
    for (int ty = ty0; ty < 32; ty += 8)
        t[ty][tx] = src[(long long)(k0 + ty) * N + n0 + tx];
    __syncthreads();
    #pragma unroll
    for (int ty = ty0; ty < 32; ty += 8)
        dst[(long long)(n0 + ty) * K + k0 + tx] = tf32r(t[tx][ty]);
}

// ---------------- RMSNorm (output tf32-rounded) ----------------
__global__ void rmsnorm_k(const float* __restrict__ x, const float* __restrict__ g,
                          float* __restrict__ y) {
    const int D = Dm;
    long long row = blockIdx.x;
    const float* xr = x + row * D;
    float* yr = y + row * D;
    float s = 0.f;
    for (int i = threadIdx.x; i < D; i += blockDim.x) { float v = xr[i]; s += v * v; }
    #pragma unroll
    for (int o = 16; o; o >>= 1) s += __shfl_xor_sync(0xffffffffu, s, o);
    __shared__ float sh[8];
    if ((threadIdx.x & 31) == 0) sh[threadIdx.x >> 5] = s;
    __syncthreads();
    float tot = 0.f;
    #pragma unroll
    for (int i = 0; i < 8; i++) tot += sh[i];
    float n = rsqrtf(tot / (float)D + 1e-6f);
    for (int i = threadIdx.x; i < D; i += blockDim.x) yr[i] = tf32r(xr[i] * n * g[i]);
}

// ---------------- ldmatrix helper ----------------
__device__ __forceinline__ void ldsm_x4(unsigned& r0, unsigned& r1, unsigned& r2, unsigned& r3,
                                        const float* p) {
    unsigned a = (unsigned)__cvta_generic_to_shared(p);
    asm volatile("ldmatrix.sync.aligned.m8n8.x4.shared.b16 {%0,%1,%2,%3}, [%4];"
                 : "=r"(r0), "=r"(r1), "=r"(r2), "=r"(r3) : "r"(a));
}

// ---------------- tf32 tensor-core GEMM ----------------
// C[M,N] = alpha * A[M,K] @ B + residual R
// TB=true : B row-major [N,K] (C = A @ B^T). Fragments for A AND B via ldmatrix.x4.
// TB=false: B row-major [K,N] (only attn@V uses this). A via ldmatrix; B via LDS.
// RND: round output to tf32.
#define BM 128
#define BN 128
#define BK 16
#define LDA_S 20
#define LDB_S 136

template<bool TB, bool RND>
__global__ void __launch_bounds__(256) mm_k(
    const float* __restrict__ A, const float* __restrict__ B,
    const float* __restrict__ R, float* __restrict__ C,
    int M, int N, int K, int lda, int ldb, int ldc,
    long long aB, long long aH, long long bB, long long bH,
    long long cB, long long cH, float alpha)
{
    int z = blockIdx.z, bb = z >> 4, hh = z & 15;
    A += bb * aB + hh * aH;
    B += bb * bB + hh * bH;
    C += bb * cB + hh * cH;
    if (R) R += bb * cB + hh * cH;

    constexpr int BSZ = TB ? (BN * LDA_S) : (BK * LDB_S);
    __shared__ float As[2][BM * LDA_S];
    __shared__ float Bs[2][BSZ];

    const int tid = threadIdx.x;
    const int row0 = blockIdx.y * BM, col0 = blockIdx.x * BN;

    const int lane = tid & 31, warp = tid >> 5;
    const int g  = lane >> 2, tg = lane & 3;
    const int mb = (warp >> 1) * 32;
    const int nb = (warp & 1) * 64;

    // ldmatrix per-lane address components: lane -> matrix lm (0..3), row lr (0..7)
    const int lm = lane >> 3, lr = lane & 7;
    // A: matrix lm: row += (lm&1)*8, col += (lm>>1)*4  (regs -> a0,a1,a2,a3)
    const int aoff0 = (mb + (lm & 1) * 8 + lr) * LDA_S + (lm >> 1) * 4;
    // B (TB): matrix lm: row += (lm>>1)*8, col += (lm&1)*4 (regs -> b[2j][0],b[2j][1],b[2j+1][0],b[2j+1][1])
    const int boff0 = (nb + (lm >> 1) * 8 + lr) * LDA_S + (lm & 1) * 4;

    float acc[2][8][4];
    #pragma unroll
    for (int mi = 0; mi < 2; mi++)
        #pragma unroll
        for (int ni = 0; ni < 8; ni++)
            #pragma unroll
            for (int q = 0; q < 4; q++) acc[mi][ni][q] = 0.f;

    auto copyA = [&](int buf, int kt) {
        #pragma unroll
        for (int q = tid; q < 512; q += 256) {
            int r = q >> 2, cs = (q & 3) * 4;
            const float* gp = A + (long long)(row0 + r) * lda + kt + cs;
            unsigned s = (unsigned)__cvta_generic_to_shared(&As[buf][r * LDA_S + cs]);
            asm volatile("cp.async.ca.shared.global [%0], [%1], 16;\n" :: "r"(s), "l"(gp));
        }
    };
    auto copyB = [&](int buf, int kt) {
        if (TB) {
            #pragma unroll
            for (int q = tid; q < 512; q += 256) {
                int r = q >> 2, cs = (q & 3) * 4;
                const float* gp = B + (long long)(col0 + r) * ldb + kt + cs;
                unsigned s = (unsigned)__cvta_generic_to_shared(&Bs[buf][r * LDA_S + cs]);
                asm volatile("cp.async.ca.shared.global [%0], [%1], 16;\n" :: "r"(s), "l"(gp));
            }
        } else {
            #pragma unroll
            for (int q = tid; q < 512; q += 256) {
                int kr = q >> 5, ns = (q & 31) * 4;
                const float* gp = B + (long long)(kt + kr) * ldb + col0 + ns;
                unsigned s = (unsigned)__cvta_generic_to_shared(&Bs[buf][kr * LDB_S + ns]);
                asm volatile("cp.async.ca.shared.global [%0], [%1], 16;\n" :: "r"(s), "l"(gp));
            }
        }
    };

    copyA(0, 0); copyB(0, 0);
    asm volatile("cp.async.commit_group;\n" ::: "memory");

    const int nt = K / BK;
    for (int t = 0; t < nt; ++t) {
        int cur = t & 1;
        if (t + 1 < nt) {
            copyA(cur ^ 1, (t + 1) * BK);
            copyB(cur ^ 1, (t + 1) * BK);
            asm volatile("cp.async.commit_group;\n" ::: "memory");
            asm volatile("cp.async.wait_group 1;\n" ::: "memory");
        } else {
            asm volatile("cp.async.wait_group 0;\n" ::: "memory");
        }
        __syncthreads();

        const float* as = As[cur];
        const float* bs = Bs[cur];

        #pragma unroll
        for (int kk = 0; kk < BK; kk += 8) {
            unsigned a[2][4], b[8][2];
            #pragma unroll
            for (int mi = 0; mi < 2; ++mi)
                ldsm_x4(a[mi][0], a[mi][1], a[mi][2], a[mi][3],
                        as + aoff0 + mi * 16 * LDA_S + kk);
            if (TB) {
                #pragma unroll
                for (int j = 0; j < 4; ++j)
                    ldsm_x4(b[2 * j][0], b[2 * j][1], b[2 * j + 1][0], b[2 * j + 1][1],
                            bs + boff0 + j * 16 * LDA_S + kk);
            } else {
                #pragma unroll
                for (int ni = 0; ni < 8; ++ni) {
                    int n = nb + ni * 8 + g;
                    b[ni][0] = __float_as_uint(bs[(kk + tg) * LDB_S + n]);
                    b[ni][1] = __float_as_uint(bs[(kk + tg + 4) * LDB_S + n]);
                }
            }
            #pragma unroll
            for (int mi = 0; mi < 2; ++mi)
                #pragma unroll
                for (int ni = 0; ni < 8; ++ni)
                    asm volatile(
                        "mma.sync.aligned.m16n8k8.row.col.f32.tf32.tf32.f32 "
                        "{%0,%1,%2,%3}, {%4,%5,%6,%7}, {%8,%9}, {%0,%1,%2,%3};\n"
                        : "+f"(acc[mi][ni][0]), "+f"(acc[mi][ni][1]),
                          "+f"(acc[mi][ni][2]), "+f"(acc[mi][ni][3])
                        : "r"(a[mi][0]), "r"(a[mi][1]), "r"(a[mi][2]), "r"(a[mi][3]),
                          "r"(b[ni][0]), "r"(b[ni][1]));
        }
        __syncthreads();
    }

    #pragma unroll
    for (int mi = 0; mi < 2; ++mi) {
        #pragma unroll
        for (int ni = 0; ni < 8; ++ni) {
            long long rr = row0 + mb + mi * 16 + g;
            long long cc = col0 + nb + ni * 8 + tg * 2;
            float2 v0 = make_float2(acc[mi][ni][0] * alpha, acc[mi][ni][1] * alpha);
            float2 v1 = make_float2(acc[mi][ni][2] * alpha, acc[mi][ni][3] * alpha);
            if (R) {
                float2 r0 = *(const float2*)&R[rr * ldc + cc];
                float2 r1 = *(const float2*)&R[(rr + 8) * ldc + cc];
                v0.x += r0.x; v0.y += r0.y; v1.x += r1.x; v1.y += r1.y;
            }
            if (RND) {
                v0.x = tf32r(v0.x); v0.y = tf32r(v0.y);
                v1.x = tf32r(v1.x); v1.y = tf32r(v1.y);
            }
            *(float2*)&C[rr * ldc + cc] = v0;
            *(float2*)&C[(rr + 8) * ldc + cc] = v1;
        }
    }
}

// ---------------- RoPE ----------------
__global__ void rope_k(float* __restrict__ x, int seqlen) {
    long long g = (long long)blockIdx.x * blockDim.x + threadIdx.x;
    const long long total = (long long)Tt * NH * (DR / 2);
    if (g >= total) return;
    int j = (int)(g % (DR / 2));
    long long th = g / (DR / 2);
    int h = (int)(th % NH);
    long long tok = th / NH;
    int s = (int)(tok % seqlen);
    float freq = (float)pow((double)1000000.0, -2.0 * j / (double)DR);
    float ang = (float)s * freq;
    float c = cosf(ang), si = sinf(ang);
    long long idx = tok * (NH * DR) + h * DR + 2 * j;
    float x1 = x[idx], x2 = x[idx + 1];
    x[idx]     = x1 * c - x2 * si;
    x[idx + 1] = x2 * c + x1 * si;
}

// ---------------- pack [C | R] -> (T, NH, 192), tf32-rounded ----------------
__global__ void pack_k(const float* __restrict__ c, const float* __restrict__ rr,
                       float* __restrict__ cat) {
    long long i = (long long)blockIdx.x * blockDim.x + threadIdx.x;
    const long long total = (long long)Tt * NH * DCAT;
    if (i >= total) return;
    int d = (int)(i % DCAT);
    long long th = i / DCAT;
    int h = (int)(th % NH);
    long long tok = th / NH;
    float v = (d < DH) ? c[tok * (NH * DH) + h * DH + d]
                       : rr[tok * (NH * DR) + h * DR + (d - DH)];
    cat[i] = tf32r(v);
}

// ---------------- row softmax (tf32-rounded output) ----------------
__global__ void softmax_k(float* __restrict__ sc) {
    const int N = Nq;
    float* r = sc + (long long)blockIdx.x * N;
    float v[8];
    float m = -3.4e38f;
    #pragma unroll
    for (int k = 0; k < 8; k++) { v[k] = r[threadIdx.x + k * 256]; m = fmaxf(m, v[k]); }
    #pragma unroll
    for (int o = 16; o; o >>= 1) m = fmaxf(m, __shfl_xor_sync(0xffffffffu, m, o));
    __shared__ float shm[8], shs[8];
    if ((threadIdx.x & 31) == 0) shm[threadIdx.x >> 5] = m;
    __syncthreads();
    #pragma unroll
    for (int i = 0; i < 8; i++) m = fmaxf(m, shm[i]);
    float s = 0.f;
    #pragma unroll
    for (int k = 0; k < 8; k++) { v[k] = expf(v[k] - m); s += v[k]; }
    #pragma unroll
    for (int o = 16; o; o >>= 1) s += __shfl_xor_sync(0xffffffffu, s, o);
    if ((threadIdx.x & 31) == 0) shs[threadIdx.x >> 5] = s;
    __syncthreads();
    float tot = 0.f;
    #pragma unroll
    for (int i = 0; i < 8; i++) tot += shs[i];
    float inv = 1.f / tot;
    #pragma unroll
    for (int k = 0; k < 8; k++) r[threadIdx.x + k * 256] = tf32r(v[k] * inv);
}

// ---------------- silu(gate)*up, tf32-rounded ----------------
__global__ void silumul_k(float* __restrict__ g, const float* __restrict__ u) {
    long long i = (long long)blockIdx.x * blockDim.x + threadIdx.x;
    const long long total = (long long)Tt * FFN_;
    if (i >= total) return;
    float x = g[i];
    g[i] = tf32r((x / (1.f + expf(-x))) * u[i]);
}

// ---------------- launch ----------------
extern "C" void kernel_launch(void* const* d_in, const int* in_sizes, int n_in,
                              void* d_out, int out_size) {
    (void)in_sizes; (void)n_in; (void)out_size;
    const float* query  = (const float*)d_in[0];
    const float* keyval = (const float*)d_in[1];
    const float* g_q    = (const float*)d_in[2];
    const float* g_kv   = (const float*)d_in[3];
    const float* g_ffn  = (const float*)d_in[4];
    const float* w_qc   = (const float*)d_in[5];
    const float* w_kc   = (const float*)d_in[6];
    const float* w_qr   = (const float*)d_in[7];
    const float* w_kr   = (const float*)d_in[8];
    const float* w_v    = (const float*)d_in[9];
    const float* w_o    = (const float*)d_in[10];
    const float* w_gate = (const float*)d_in[11];
    const float* w_up   = (const float*)d_in[12];
    const float* w_down = (const float*)d_in[13];
    float* out = (float*)d_out;

    float* S = nullptr;
    cudaGetSymbolAddress((void**)&S, g_scratch);
    float* qn    = S + O_QN;
    float* kvn   = S + O_KVN;
    float* qc    = S + O_QC;
    float* kc    = S + O_KC;
    float* qr    = S + O_QR;
    float* kr    = S + O_KR;
    float* vv    = S + O_V;
    float* qcat  = S + O_QCAT;
    float* kcat  = S + O_KCAT;
    float* sc    = S + O_SC;
    float* att   = S + O_ATT;
    float* x     = S + O_X;
    float* xn    = S + O_XN;
    float* gate  = S + O_GATE;
    float* up    = S + O_UP;
    float* cwqc  = S + O_WQC;   // [2048][2048] (n-major)
    float* cwkc  = S + O_WKC;
    float* cwqr  = S + O_WQR;   // [1024][2048]
    float* cwkr  = S + O_WKR;
    float* cwv   = S + O_WV;
    float* cwo   = S + O_WO;
    float* cwg   = S + O_WGATE; // [8192][2048]
    float* cwu   = S + O_WUP;
    float* cwd   = S + O_WDOWN; // [2048][8192]

    // 0. Pre-round + transpose weights to [n][k] tf32
    {
        dim3 blk(32, 8);
        dim3 gDD(Dm / 32, Dm / 32);
        dim3 gDR((NH * DR) / 32, Dm / 32);
        dim3 gDF(FFN_ / 32, Dm / 32);
        dim3 gFD(Dm / 32, FFN_ / 32);
        cvtwT_k<<<gDD, blk>>>(w_qc,   cwqc, Dm, Dm);
        cvtwT_k<<<gDD, blk>>>(w_kc,   cwkc, Dm, Dm);
        cvtwT_k<<<gDR, blk>>>(w_qr,   cwqr, Dm, NH * DR);
        cvtwT_k<<<gDR, blk>>>(w_kr,   cwkr, Dm, NH * DR);
        cvtwT_k<<<gDD, blk>>>(w_v,    cwv,  Dm, Dm);
        cvtwT_k<<<gDD, blk>>>(w_o,    cwo,  NH * DH, Dm);
        cvtwT_k<<<gDF, blk>>>(w_gate, cwg,  Dm, FFN_);
        cvtwT_k<<<gDF, blk>>>(w_up,   cwu,  Dm, FFN_);
        cvtwT_k<<<gFD, blk>>>(w_down, cwd,  FFN_, Dm);
    }

    // 1. RMSNorm inputs
    rmsnorm_k<<<Tt, 256>>>(query,  g_q,  qn);
    rmsnorm_k<<<Tt, 256>>>(keyval, g_kv, kvn);

    // 2. Projections (B = transposed weights, TB path, ldb = K)
    {
        dim3 grid(Dm / BN, Tt / BM, 1);
        mm_k<true,false><<<grid, 256>>>(qn,  cwqc, nullptr, qc, Tt, Dm, Dm, Dm, Dm, Dm, 0,0,0,0,0,0, 1.f);
        mm_k<true,false><<<grid, 256>>>(kvn, cwkc, nullptr, kc, Tt, Dm, Dm, Dm, Dm, Dm, 0,0,0,0,0,0, 1.f);
        mm_k<true,true ><<<grid, 256>>>(kvn, cwv,  nullptr, vv, Tt, Dm, Dm, Dm, Dm, Dm, 0,0,0,0,0,0, 1.f);
    }
    {
        dim3 grid((NH * DR) / BN, Tt / BM, 1);
        mm_k<true,false><<<grid, 256>>>(qn,  cwqr, nullptr, qr, Tt, NH * DR, Dm, Dm, Dm, NH * DR, 0,0,0,0,0,0, 1.f);
        mm_k<true,false><<<grid, 256>>>(kvn, cwkr, nullptr, kr, Tt, NH * DR, Dm, Dm, Dm, NH * DR, 0,0,0,0,0,0, 1.f);
    }

    // 3. RoPE
    {
        long long pairs = (long long)Tt * NH * (DR / 2);
        int blocks = (int)((pairs + 255) / 256);
        rope_k<<<blocks, 256>>>(qr, Mq);
        rope_k<<<blocks, 256>>>(kr, Nq);
    }

    // 4. Pack [C|R]
    {
        long long tot = (long long)Tt * NH * DCAT;
        int blocks = (int)((tot + 255) / 256);
        pack_k<<<blocks, 256>>>(qc, qr, qcat);
        pack_k<<<blocks, 256>>>(kc, kr, kcat);
    }

    // 5. Scores = scale * Qcat @ Kcat^T (TB path)
    {
        dim3 grid(Nq / BN, Mq / BM, Bq * NH);
        mm_k<true,false><<<grid, 256>>>(qcat, kcat, nullptr, sc,
            Mq, Nq, DCAT, NH * DCAT, NH * DCAT, Nq,
            (long long)Mq * NH * DCAT, (long long)DCAT,
            (long long)Nq * NH * DCAT, (long long)DCAT,
            (long long)NH * Mq * Nq, (long long)Mq * Nq,
            SCALE_);
    }

    // 6. Softmax
    softmax_k<<<Bq * NH * Mq, 256>>>(sc);

    // 7. attn @ V (non-TB: B = vv [k][n])
    {
        dim3 grid(DH / BN, Mq / BM, Bq * NH);
        mm_k<false,true><<<grid, 256>>>(sc, vv, nullptr, att,
            Mq, DH, Nq, Nq, NH * DH, NH * DH,
            (long long)NH * Mq * Nq, (long long)Mq * Nq,
            (long long)Nq * NH * DH, (long long)DH,
            (long long)Mq * NH * DH, (long long)DH,
            1.f);
    }

    // 8. x = att @ w_o + query
    {
        dim3 grid(Dm / BN, Tt / BM, 1);
        mm_k<true,false><<<grid, 256>>>(att, cwo, query, x, Tt, Dm, NH * DH,
                                        NH * DH, NH * DH, Dm, 0,0,0,0,0,0, 1.f);
    }

    // 9. RMSNorm -> xn
    rmsnorm_k<<<Tt, 256>>>(x, g_ffn, xn);

    // 10. gate / up
    {
        dim3 grid(FFN_ / BN, Tt / BM, 1);
        mm_k<true,false><<<grid, 256>>>(xn, cwg, nullptr, gate, Tt, FFN_, Dm, Dm, Dm, FFN_, 0,0,0,0,0,0, 1.f);
        mm_k<true,false><<<grid, 256>>>(xn, cwu, nullptr, up,   Tt, FFN_, Dm, Dm, Dm, FFN_, 0,0,0,0,0,0, 1.f);
    }

    // 11. silu(gate)*up
    {
        long long tot = (long long)Tt * FFN_;
        int blocks = (int)((tot + 255) / 256);
        silumul_k<<<blocks, 256>>>(gate, up);
    }

    // 12. out = h @ w_down + x
    {
        dim3 grid(Dm / BN, Tt / BM, 1);
        mm_k<true,false><<<grid, 256>>>(gate, cwd, x, out, Tt, Dm, FFN_,
                                        FFN_, FFN_, Dm, 0,0,0,0,0,0, 1.f);
    }
}

// round 10
// speedup vs baseline: 3.0425x; 1.0104x over previous
#include <cuda_runtime.h>
#include <cuda_bf16.h>
#include <math.h>

// Problem constants
#define Bq   2
#define Mq   2048
#define Nq   2048
#define Dm   2048
#define NH   16
#define DH   128
#define DR   64
#define FFN_ 8192
#define Tt   (Bq*Mq)
#define DCAT (DH+DR)          // 192
#define SCALE_ (0.0721687836487032f) // 1/sqrt(192)

// ---------------- scratch ----------------
#define O_QN    0LL
#define O_KVN   (O_QN   + (long long)Tt*Dm)
#define O_QC    (O_KVN  + (long long)Tt*Dm)
#define O_KC    (O_QC   + (long long)Tt*NH*DH)
#define O_QR    (O_KC   + (long long)Tt*NH*DH)
#define O_KR    (O_QR   + (long long)Tt*NH*DR)
#define O_V     (O_KR   + (long long)Tt*NH*DR)
#define O_QCAT  (O_V    + (long long)Tt*NH*DH)
#define O_KCAT  (O_QCAT + (long long)Tt*NH*DCAT)
#define O_SC    (O_KCAT + (long long)Tt*NH*DCAT)
#define O_ATT   (O_SC   + (long long)Bq*NH*Mq*Nq)
#define O_X     (O_ATT  + (long long)Tt*NH*DH)
#define O_XN    (O_X    + (long long)Tt*Dm)
#define O_GATE  (O_XN   + (long long)Tt*Dm)
#define O_UP    (O_GATE + (long long)Tt*FFN_)
// converted (tf32-rounded, TRANSPOSED [n][k]) weights
#define SZ_DD   ((long long)Dm*Dm)
#define SZ_DR2  ((long long)Dm*NH*DR)
#define SZ_DF   ((long long)Dm*FFN_)
#define O_WQC   (O_UP   + (long long)Tt*FFN_)
#define O_WKC   (O_WQC  + SZ_DD)
#define O_WQR   (O_WKC  + SZ_DD)
#define O_WKR   (O_WQR  + SZ_DR2)
#define O_WV    (O_WKR  + SZ_DR2)
#define O_WO    (O_WV   + SZ_DD)
#define O_WGATE (O_WO   + SZ_DD)
#define O_WUP   (O_WGATE+ SZ_DF)
#define O_WDOWN (O_WUP  + SZ_DF)
#define O_TOTAL (O_WDOWN+ SZ_DF)

__device__ float g_scratch[O_TOTAL];

__device__ __forceinline__ float tf32r(float f) {
    unsigned r; asm("cvt.rna.tf32.f32 %0, %1;" : "=r"(r) : "f"(f));
    return __uint_as_float(r);
}

// ---------------- weight tf32 round + transpose: src[K][N] -> dst[N][K] ----------------
__global__ void cvtwT_k(const float* __restrict__ src, float* __restrict__ dst,
                        int K, int N) {
    __shared__ float t[32][33];
    int n0 = blockIdx.x * 32, k0 = blockIdx.y * 32;
    int tx = threadIdx.x, ty0 = threadIdx.y;
    #pragma unroll
    for (int ty = ty0; ty < 32; ty += 8)
        t[ty][tx] = src[(long long)(k0 + ty) * N + n0 + tx];
    __syncthreads();
    #pragma unroll
    for (int ty = ty0; ty < 32; ty += 8)
        dst[(long long)(n0 + ty) * K + k0 + tx] = tf32r(t[tx][ty]);
}

// ---------------- RMSNorm (output tf32-rounded) ----------------
__global__ void rmsnorm_k(const float* __restrict__ x, const float* __restrict__ g,
                          float* __restrict__ y) {
    const int D = Dm;
    long long row = blockIdx.x;
    const float* xr = x + row * D;
    float* yr = y + row * D;
    float s = 0.f;
    for (int i = threadIdx.x; i < D; i += blockDim.x) { float v = xr[i]; s += v * v; }
    #pragma unroll
    for (int o = 16; o; o >>= 1) s += __shfl_xor_sync(0xffffffffu, s, o);
    __shared__ float sh[8];
    if ((threadIdx.x & 31) == 0) sh[threadIdx.x >> 5] = s;
    __syncthreads();
    float tot = 0.f;
    #pragma unroll
    for (int i = 0; i < 8; i++) tot += sh[i];
    float n = rsqrtf(tot / (float)D + 1e-6f);
    for (int i = threadIdx.x; i < D; i += blockDim.x) yr[i] = tf32r(xr[i] * n * g[i]);
}

// ---------------- ldmatrix helper ----------------
__device__ __forceinline__ void ldsm_x4(unsigned& r0, unsigned& r1, unsigned& r2, unsigned& r3,
                                        const float* p) {
    unsigned a = (unsigned)__cvta_generic_to_shared(p);
    asm volatile("ldmatrix.sync.aligned.m8n8.x4.shared.b16 {%0,%1,%2,%3}, [%4];"
                 : "=r"(r0), "=r"(r1), "=r"(r2), "=r"(r3) : "r"(a));
}

// ---------------- tf32 tensor-core GEMM, 4-stage cp.async pipeline ----------------
// C[M,N] = alpha * A[M,K] @ B + residual R
// TB=true : B row-major [N,K] (C = A @ B^T). A and B fragments via ldmatrix.x4.
// TB=false: B row-major [K,N] (attn@V only). A via ldmatrix; B via LDS.
// RND: round output to tf32.
#define BM 128
#define BN 128
#define BK 16
#define LDA_S 20
#define LDB_S 136
#define NSTAGE 4
#define ASZ (BM * LDA_S)                       // 2560 floats per A stage

template<bool TB, bool RND>
__global__ void __launch_bounds__(256, 2) mm_k(
    const float* __restrict__ A, const float* __restrict__ B,
    const float* __restrict__ R, float* __restrict__ C,
    int M, int N, int K, int lda, int ldb, int ldc,
    long long aB, long long aH, long long bB, long long bH,
    long long cB, long long cH, float alpha)
{
    int z = blockIdx.z, bb = z >> 4, hh = z & 15;
    A += bb * aB + hh * aH;
    B += bb * bB + hh * bH;
    C += bb * cB + hh * cH;
    if (R) R += bb * cB + hh * cH;

    constexpr int BSZ = TB ? (BN * LDA_S) : (BK * LDB_S);
    extern __shared__ float smem[];
    float* AsBase = smem;                 // NSTAGE * ASZ
    float* BsBase = smem + NSTAGE * ASZ;  // NSTAGE * BSZ

    const int tid = threadIdx.x;
    const int row0 = blockIdx.y * BM, col0 = blockIdx.x * BN;

    const int lane = tid & 31, warp = tid >> 5;
    const int g  = lane >> 2, tg = lane & 3;
    const int mb = (warp >> 1) * 32;
    const int nb = (warp & 1) * 64;

    const int lm = lane >> 3, lr = lane & 7;
    const int aoff0 = (mb + (lm & 1) * 8 + lr) * LDA_S + (lm >> 1) * 4;
    const int boff0 = (nb + (lm >> 1) * 8 + lr) * LDA_S + (lm & 1) * 4;

    float acc[2][8][4];
    #pragma unroll
    for (int mi = 0; mi < 2; mi++)
        #pragma unroll
        for (int ni = 0; ni < 8; ni++)
            #pragma unroll
            for (int q = 0; q < 4; q++) acc[mi][ni][q] = 0.f;

    auto copyA = [&](int buf, int kt) {
        float* dst = AsBase + buf * ASZ;
        #pragma unroll
        for (int q = tid; q < 512; q += 256) {
            int r = q >> 2, cs = (q & 3) * 4;
            const float* gp = A + (long long)(row0 + r) * lda + kt + cs;
            unsigned s = (unsigned)__cvta_generic_to_shared(&dst[r * LDA_S + cs]);
            asm volatile("cp.async.ca.shared.global [%0], [%1], 16;\n" :: "r"(s), "l"(gp));
        }
    };
    auto copyB = [&](int buf, int kt) {
        float* dst = BsBase + buf * BSZ;
        if (TB) {
            #pragma unroll
            for (int q = tid; q < 512; q += 256) {
                int r = q >> 2, cs = (q & 3) * 4;
                const float* gp = B + (long long)(col0 + r) * ldb + kt + cs;
                unsigned s = (unsigned)__cvta_generic_to_shared(&dst[r * LDA_S + cs]);
                asm volatile("cp.async.ca.shared.global [%0], [%1], 16;\n" :: "r"(s), "l"(gp));
            }
        } else {
            #pragma unroll
            for (int q = tid; q < 512; q += 256) {
                int kr = q >> 5, ns = (q & 31) * 4;
                const float* gp = B + (long long)(kt + kr) * ldb + col0 + ns;
                unsigned s = (unsigned)__cvta_generic_to_shared(&dst[kr * LDB_S + ns]);
                asm volatile("cp.async.ca.shared.global [%0], [%1], 16;\n" :: "r"(s), "l"(gp));
            }
        }
    };

    const int nt = K / BK;   // all call sites have nt >= 12

    // prologue: 3 stages in flight
    #pragma unroll
    for (int s = 0; s < NSTAGE - 1; ++s) {
        copyA(s, s * BK);
        copyB(s, s * BK);
        asm volatile("cp.async.commit_group;\n" ::: "memory");
    }

    for (int t = 0; t < nt; ++t) {
        // stage t ready when all but the last (NSTAGE-2) committed groups are done
        asm volatile("cp.async.wait_group %0;\n" :: "n"(NSTAGE - 2) : "memory");
        __syncthreads();

        // issue copy for stage t+3 into slot (t+3)%4 (slot freed by compute t-1)
        int nxt = t + NSTAGE - 1;
        if (nxt < nt) {
            copyA(nxt & (NSTAGE - 1), nxt * BK);
            copyB(nxt & (NSTAGE - 1), nxt * BK);
        }
        asm volatile("cp.async.commit_group;\n" ::: "memory");

        const int cur = t & (NSTAGE - 1);
        const float* as = AsBase + cur * ASZ;
        const float* bs = BsBase + cur * BSZ;

        #pragma unroll
        for (int kk = 0; kk < BK; kk += 8) {
            unsigned a[2][4], b[8][2];
            #pragma unroll
            for (int mi = 0; mi < 2; ++mi)
                ldsm_x4(a[mi][0], a[mi][1], a[mi][2], a[mi][3],
                        as + aoff0 + mi * 16 * LDA_S + kk);
            if (TB) {
                #pragma unroll
                for (int j = 0; j < 4; ++j)
                    ldsm_x4(b[2 * j][0], b[2 * j][1], b[2 * j + 1][0], b[2 * j + 1][1],
                            bs + boff0 + j * 16 * LDA_S + kk);
            } else {
                #pragma unroll
                for (int ni = 0; ni < 8; ++ni) {
                    int n = nb + ni * 8 + g;
                    b[ni][0] = __float_as_uint(bs[(kk + tg) * LDB_S + n]);
                    b[ni][1] = __float_as_uint(bs[(kk + tg + 4) * LDB_S + n]);
                }
            }
            #pragma unroll
            for (int mi = 0; mi < 2; ++mi)
                #pragma unroll
                for (int ni = 0; ni < 8; ++ni)
                    asm volatile(
                        "mma.sync.aligned.m16n8k8.row.col.f32.tf32.tf32.f32 "
                        "{%0,%1,%2,%3}, {%4,%5,%6,%7}, {%8,%9}, {%0,%1,%2,%3};\n"
                        : "+f"(acc[mi][ni][0]), "+f"(acc[mi][ni][1]),
                          "+f"(acc[mi][ni][2]), "+f"(acc[mi][ni][3])
                        : "r"(a[mi][0]), "r"(a[mi][1]), "r"(a[mi][2]), "r"(a[mi][3]),
                          "r"(b[ni][0]), "r"(b[ni][1]));
        }
    }

    #pragma unroll
    for (int mi = 0; mi < 2; ++mi) {
        #pragma unroll
        for (int ni = 0; ni < 8; ++ni) {
            long long rr = row0 + mb + mi * 16 + g;
            long long cc = col0 + nb + ni * 8 + tg * 2;
            float2 v0 = make_float2(acc[mi][ni][0] * alpha, acc[mi][ni][1] * alpha);
            float2 v1 = make_float2(acc[mi][ni][2] * alpha, acc[mi][ni][3] * alpha);
            if (R) {
                float2 r0 = *(const float2*)&R[rr * ldc + cc];
                float2 r1 = *(const float2*)&R[(rr + 8) * ldc + cc];
                v0.x += r0.x; v0.y += r0.y; v1.x += r1.x; v1.y += r1.y;
            }
            if (RND) {
                v0.x = tf32r(v0.x); v0.y = tf32r(v0.y);
                v1.x = tf32r(v1.x); v1.y = tf32r(v1.y);
            }
            *(float2*)&C[rr * ldc + cc] = v0;
            *(float2*)&C[(rr + 8) * ldc + cc] = v1;
        }
    }
}

// smem byte sizes for the two instantiations
#define SMEM_TB  (NSTAGE * (ASZ + BN * LDA_S) * 4)   // 81920
#define SMEM_NTB (NSTAGE * (ASZ + BK * LDB_S) * 4)   // 75776

// ---------------- RoPE ----------------
__global__ void rope_k(float* __restrict__ x, int seqlen) {
    long long g = (long long)blockIdx.x * blockDim.x + threadIdx.x;
    const long long total = (long long)Tt * NH * (DR / 2);
    if (g >= total) return;
    int j = (int)(g % (DR / 2));
    long long th = g / (DR / 2);
    int h = (int)(th % NH);
    long long tok = th / NH;
    int s = (int)(tok % seqlen);
    float freq = (float)pow((double)1000000.0, -2.0 * j / (double)DR);
    float ang = (float)s * freq;
    float c = cosf(ang), si = sinf(ang);
    long long idx = tok * (NH * DR) + h * DR + 2 * j;
    float x1 = x[idx], x2 = x[idx + 1];
    x[idx]     = x1 * c - x2 * si;
    x[idx + 1] = x2 * c + x1 * si;
}

// ---------------- pack [C | R] -> (T, NH, 192), tf32-rounded ----------------
__global__ void pack_k(const float* __restrict__ c, const float* __restrict__ rr,
                       float* __restrict__ cat) {
    long long i = (long long)blockIdx.x * blockDim.x + threadIdx.x;
    const long long total = (long long)Tt * NH * DCAT;
    if (i >= total) return;
    int d = (int)(i % DCAT);
    long long th = i / DCAT;
    int h = (int)(th % NH);
    long long tok = th / NH;
    float v = (d < DH) ? c[tok * (NH * DH) + h * DH + d]
                       : rr[tok * (NH * DR) + h * DR + (d - DH)];
    cat[i] = tf32r(v);
}

// ---------------- row softmax (tf32-rounded output) ----------------
__global__ void softmax_k(float* __restrict__ sc) {
    const int N = Nq;
    float* r = sc + (long long)blockIdx.x * N;
    float v[8];
    float m = -3.4e38f;
    #pragma unroll
    for (int k = 0; k < 8; k++) { v[k] = r[threadIdx.x + k * 256]; m = fmaxf(m, v[k]); }
    #pragma unroll
    for (int o = 16; o; o >>= 1) m = fmaxf(m, __shfl_xor_sync(0xffffffffu, m, o));
    __shared__ float shm[8], shs[8];
    if ((threadIdx.x & 31) == 0) shm[threadIdx.x >> 5] = m;
    __syncthreads();
    #pragma unroll
    for (int i = 0; i < 8; i++) m = fmaxf(m, shm[i]);
    float s = 0.f;
    #pragma unroll
    for (int k = 0; k < 8; k++) { v[k] = expf(v[k] - m); s += v[k]; }
    #pragma unroll
    for (int o = 16; o; o >>= 1) s += __shfl_xor_sync(0xffffffffu, s, o);
    if ((threadIdx.x & 31) == 0) shs[threadIdx.x >> 5] = s;
    __syncthreads();
    float tot = 0.f;
    #pragma unroll
    for (int i = 0; i < 8; i++) tot += shs[i];
    float inv = 1.f / tot;
    #pragma unroll
    for (int k = 0; k < 8; k++) r[threadIdx.x + k * 256] = tf32r(v[k] * inv);
}

// ---------------- silu(gate)*up, tf32-rounded ----------------
__global__ void silumul_k(float* __restrict__ g, const float* __restrict__ u) {
    long long i = (long long)blockIdx.x * blockDim.x + threadIdx.x;
    const long long total = (long long)Tt * FFN_;
    if (i >= total) return;
    float x = g[i];
    g[i] = tf32r((x / (1.f + expf(-x))) * u[i]);
}

// ---------------- launch ----------------
extern "C" void kernel_launch(void* const* d_in, const int* in_sizes, int n_in,
                              void* d_out, int out_size) {
    (void)in_sizes; (void)n_in; (void)out_size;
    const float* query  = (const float*)d_in[0];
    const float* keyval = (const float*)d_in[1];
    const float* g_q    = (const float*)d_in[2];
    const float* g_kv   = (const float*)d_in[3];
    const float* g_ffn  = (const float*)d_in[4];
    const float* w_qc   = (const float*)d_in[5];
    const float* w_kc   = (const float*)d_in[6];
    const float* w_qr   = (const float*)d_in[7];
    const float* w_kr   = (const float*)d_in[8];
    const float* w_v    = (const float*)d_in[9];
    const float* w_o    = (const float*)d_in[10];
    const float* w_gate = (const float*)d_in[11];
    const float* w_up   = (const float*)d_in[12];
    const float* w_down = (const float*)d_in[13];
    float* out = (float*)d_out;

    // raise dynamic smem limits (idempotent, host-side only)
    static bool attr_done = false;
    if (!attr_done) {
        cudaFuncSetAttribute(mm_k<true, false>,  cudaFuncAttributeMaxDynamicSharedMemorySize, SMEM_TB);
        cudaFuncSetAttribute(mm_k<true, true>,   cudaFuncAttributeMaxDynamicSharedMemorySize, SMEM_TB);
        cudaFuncSetAttribute(mm_k<false, true>,  cudaFuncAttributeMaxDynamicSharedMemorySize, SMEM_NTB);
        cudaFuncSetAttribute(mm_k<false, false>, cudaFuncAttributeMaxDynamicSharedMemorySize, SMEM_NTB);
        attr_done = true;
    }

    float* S = nullptr;
    cudaGetSymbolAddress((void**)&S, g_scratch);
    float* qn    = S + O_QN;
    float* kvn   = S + O_KVN;
    float* qc    = S + O_QC;
    float* kc    = S + O_KC;
    float* qr    = S + O_QR;
    float* kr    = S + O_KR;
    float* vv    = S + O_V;
    float* qcat  = S + O_QCAT;
    float* kcat  = S + O_KCAT;
    float* sc    = S + O_SC;
    float* att   = S + O_ATT;
    float* x     = S + O_X;
    float* xn    = S + O_XN;
    float* gate  = S + O_GATE;
    float* up    = S + O_UP;
    float* cwqc  = S + O_WQC;
    float* cwkc  = S + O_WKC;
    float* cwqr  = S + O_WQR;
    float* cwkr  = S + O_WKR;
    float* cwv   = S + O_WV;
    float* cwo   = S + O_WO;
    float* cwg   = S + O_WGATE;
    float* cwu   = S + O_WUP;
    float* cwd   = S + O_WDOWN;

    // 0. Pre-round + transpose weights to [n][k] tf32
    {
        dim3 blk(32, 8);
        dim3 gDD(Dm / 32, Dm / 32);
        dim3 gDR((NH * DR) / 32, Dm / 32);
        dim3 gDF(FFN_ / 32, Dm / 32);
        dim3 gFD(Dm / 32, FFN_ / 32);
        cvtwT_k<<<gDD, blk>>>(w_qc,   cwqc, Dm, Dm);
        cvtwT_k<<<gDD, blk>>>(w_kc,   cwkc, Dm, Dm);
        cvtwT_k<<<gDR, blk>>>(w_qr,   cwqr, Dm, NH * DR);
        cvtwT_k<<<gDR, blk>>>(w_kr,   cwkr, Dm, NH * DR);
        cvtwT_k<<<gDD, blk>>>(w_v,    cwv,  Dm, Dm);
        cvtwT_k<<<gDD, blk>>>(w_o,    cwo,  NH * DH, Dm);
        cvtwT_k<<<gDF, blk>>>(w_gate, cwg,  Dm, FFN_);
        cvtwT_k<<<gDF, blk>>>(w_up,   cwu,  Dm, FFN_);
        cvtwT_k<<<gFD, blk>>>(w_down, cwd,  FFN_, Dm);
    }

    // 1. RMSNorm inputs
    rmsnorm_k<<<Tt, 256>>>(query,  g_q,  qn);
    rmsnorm_k<<<Tt, 256>>>(keyval, g_kv, kvn);

    // 2. Projections (TB path, B = transposed weights [n][k], ldb = K)
    {
        dim3 grid(Dm / BN, Tt / BM, 1);
        mm_k<true,false><<<grid, 256, SMEM_TB>>>(qn,  cwqc, nullptr, qc, Tt, Dm, Dm, Dm, Dm, Dm, 0,0,0,0,0,0, 1.f);
        mm_k<true,false><<<grid, 256, SMEM_TB>>>(kvn, cwkc, nullptr, kc, Tt, Dm, Dm, Dm, Dm, Dm, 0,0,0,0,0,0, 1.f);
        mm_k<true,true ><<<grid, 256, SMEM_TB>>>(kvn, cwv,  nullptr, vv, Tt, Dm, Dm, Dm, Dm, Dm, 0,0,0,0,0,0, 1.f);
    }
    {
        dim3 grid((NH * DR) / BN, Tt / BM, 1);
        mm_k<true,false><<<grid, 256, SMEM_TB>>>(qn,  cwqr, nullptr, qr, Tt, NH * DR, Dm, Dm, Dm, NH * DR, 0,0,0,0,0,0, 1.f);
        mm_k<true,false><<<grid, 256, SMEM_TB>>>(kvn, cwkr, nullptr, kr, Tt, NH * DR, Dm, Dm, Dm, NH * DR, 0,0,0,0,0,0, 1.f);
    }

    // 3. RoPE
    {
        long long pairs = (long long)Tt * NH * (DR / 2);
        int blocks = (int)((pairs + 255) / 256);
        rope_k<<<blocks, 256>>>(qr, Mq);
        rope_k<<<blocks, 256>>>(kr, Nq);
    }

    // 4. Pack [C|R]
    {
        long long tot = (long long)Tt * NH * DCAT;
        int blocks = (int)((tot + 255) / 256);
        pack_k<<<blocks, 256>>>(qc, qr, qcat);
        pack_k<<<blocks, 256>>>(kc, kr, kcat);
    }

    // 5. Scores = scale * Qcat @ Kcat^T (TB path)
    {
        dim3 grid(Nq / BN, Mq / BM, Bq * NH);
        mm_k<true,false><<<grid, 256, SMEM_TB>>>(qcat, kcat, nullptr, sc,
            Mq, Nq, DCAT, NH * DCAT, NH * DCAT, Nq,
            (long long)Mq * NH * DCAT, (long long)DCAT,
            (long long)Nq * NH * DCAT, (long long)DCAT,
            (long long)NH * Mq * Nq, (long long)Mq * Nq,
            SCALE_);
    }

    // 6. Softmax
    softmax_k<<<Bq * NH * Mq, 256>>>(sc);

    // 7. attn @ V (non-TB: B = vv [k][n])
    {
        dim3 grid(DH / BN, Mq / BM, Bq * NH);
        mm_k<false,true><<<grid, 256, SMEM_NTB>>>(sc, vv, nullptr, att,
            Mq, DH, Nq, Nq, NH * DH, NH * DH,
            (long long)NH * Mq * Nq, (long long)Mq * Nq,
            (long long)Nq * NH * DH, (long long)DH,
            (long long)Mq * NH * DH, (long long)DH,
            1.f);
    }

    // 8. x = att @ w_o + query
    {
        dim3 grid(Dm / BN, Tt / BM, 1);
        mm_k<true,false><<<grid, 256, SMEM_TB>>>(att, cwo, query, x, Tt, Dm, NH * DH,
                                                 NH * DH, NH * DH, Dm, 0,0,0,0,0,0, 1.f);
    }

    // 9. RMSNorm -> xn
    rmsnorm_k<<<Tt, 256>>>(x, g_ffn, xn);

    // 10. gate / up
    {
        dim3 grid(FFN_ / BN, Tt / BM, 1);
        mm_k<true,false><<<grid, 256, SMEM_TB>>>(xn, cwg, nullptr, gate, Tt, FFN_, Dm, Dm, Dm, FFN_, 0,0,0,0,0,0, 1.f);
        mm_k<true,false><<<grid, 256, SMEM_TB>>>(xn, cwu, nullptr, up,   Tt, FFN_, Dm, Dm, Dm, FFN_, 0,0,0,0,0,0, 1.f);
    }

    // 11. silu(gate)*up
    {
        long long tot = (long long)Tt * FFN_;
        int blocks = (int)((tot + 255) / 256);
        silumul_k<<<blocks, 256>>>(gate, up);
    }

    // 12. out = h @ w_down + x
    {
        dim3 grid(Dm / BN, Tt / BM, 1);
        mm_k<true,false><<<grid, 256, SMEM_TB>>>(gate, cwd, x, out, Tt, Dm, FFN_,
                                                 FFN_, FFN_, Dm, 0,0,0,0,0,0, 1.f);
    }
}

// round 13
// speedup vs baseline: 3.0860x; 1.0143x over previous
#include <cuda_runtime.h>
#include <cuda_bf16.h>
#include <math.h>
#include <stdint.h>

// Problem constants
#define Bq   2
#define Mq   2048
#define Nq   2048
#define Dm   2048
#define NH   16
#define DH   128
#define DR   64
#define FFN_ 8192
#define Tt   (Bq*Mq)
#define DCAT (DH+DR)          // 192
#define SCALE_ (0.0721687836487032f) // 1/sqrt(192)
#define L2E_  1.4426950408889634f

// ---------------- scratch ----------------
#define O_QN    0LL
#define O_KVN   (O_QN   + (long long)Tt*Dm)
#define O_QC    (O_KVN  + (long long)Tt*Dm)
#define O_KC    (O_QC   + (long long)Tt*NH*DH)
#define O_QR    (O_KC   + (long long)Tt*NH*DH)
#define O_KR    (O_QR   + (long long)Tt*NH*DR)
#define O_V     (O_KR   + (long long)Tt*NH*DR)
#define O_QCAT  (O_V    + (long long)Tt*NH*DH)
#define O_KCAT  (O_QCAT + (long long)Tt*NH*DCAT)
#define O_SC    (O_KCAT + (long long)Tt*NH*DCAT)
#define O_ATT   (O_SC   + (long long)Bq*NH*Mq*Nq)
#define O_X     (O_ATT  + (long long)Tt*NH*DH)
#define O_XN    (O_X    + (long long)Tt*Dm)
#define O_GATE  (O_XN   + (long long)Tt*Dm)
#define O_UP    (O_GATE + (long long)Tt*FFN_)
#define SZ_DD   ((long long)Dm*Dm)
#define SZ_DR2  ((long long)Dm*NH*DR)
#define SZ_DF   ((long long)Dm*FFN_)
#define O_WQC   (O_UP   + (long long)Tt*FFN_)
#define O_WKC   (O_WQC  + SZ_DD)
#define O_WQR   (O_WKC  + SZ_DD)
#define O_WKR   (O_WQR  + SZ_DR2)
#define O_WV    (O_WKR  + SZ_DR2)
#define O_WO    (O_WV   + SZ_DD)
#define O_WGATE (O_WO   + SZ_DD)
#define O_WUP   (O_WGATE+ SZ_DF)
#define O_WDOWN (O_WUP  + SZ_DF)
// softmax stats: per (z,row) 16 tiles of float2  + combined rows
#define N_ROWS  ((long long)Bq*NH*Mq)                 // 65536
#define O_ST    (O_WDOWN+ SZ_DF)                      // float2[N_ROWS*16] = 2M floats
#define O_CML2  (O_ST   + N_ROWS*16*2)
#define O_CINV  (O_CML2 + N_ROWS)
#define O_TOTAL (O_CINV + N_ROWS)

__device__ float g_scratch[O_TOTAL];

__device__ __forceinline__ float tf32r(float f) {
    unsigned r; asm("cvt.rna.tf32.f32 %0, %1;" : "=r"(r) : "f"(f));
    return __uint_as_float(r);
}
__device__ __forceinline__ unsigned f2tfu(float f) {
    unsigned r; asm("cvt.rna.tf32.f32 %0, %1;" : "=r"(r) : "f"(f));
    return r;
}

// ---------------- weight tf32 round + transpose: src[K][N] -> dst[N][K] ----------------
__global__ void cvtwT_k(const float* __restrict__ src, float* __restrict__ dst,
                        int K, int N) {
    __shared__ float t[32][33];
    int n0 = blockIdx.x * 32, k0 = blockIdx.y * 32;
    int tx = threadIdx.x, ty0 = threadIdx.y;
    #pragma unroll
    for (int ty = ty0; ty < 32; ty += 8)
        t[ty][tx] = src[(long long)(k0 + ty) * N + n0 + tx];
    __syncthreads();
    #pragma unroll
    for (int ty = ty0; ty < 32; ty += 8)
        dst[(long long)(n0 + ty) * K + k0 + tx] = tf32r(t[tx][ty]);
}

// ---------------- RMSNorm (output tf32-rounded) ----------------
__global__ void rmsnorm_k(const float* __restrict__ x, const float* __restrict__ g,
                          float* __restrict__ y) {
    const int D = Dm;
    long long row = blockIdx.x;
    const float* xr = x + row * D;
    float* yr = y + row * D;
    float s = 0.f;
    for (int i = threadIdx.x; i < D; i += blockDim.x) { float v = xr[i]; s += v * v; }
    #pragma unroll
    for (int o = 16; o; o >>= 1) s += __shfl_xor_sync(0xffffffffu, s, o);
    __shared__ float sh[8];
    if ((threadIdx.x & 31) == 0) sh[threadIdx.x >> 5] = s;
    __syncthreads();
    float tot = 0.f;
    #pragma unroll
    for (int i = 0; i < 8; i++) tot += sh[i];
    float n = rsqrtf(tot / (float)D + 1e-6f);
    for (int i = threadIdx.x; i < D; i += blockDim.x) yr[i] = tf32r(xr[i] * n * g[i]);
}

// ---------------- ldmatrix helper ----------------
__device__ __forceinline__ void ldsm_x4(unsigned& r0, unsigned& r1, unsigned& r2, unsigned& r3,
                                        const float* p) {
    unsigned a = (unsigned)__cvta_generic_to_shared(p);
    asm volatile("ldmatrix.sync.aligned.m8n8.x4.shared.b16 {%0,%1,%2,%3}, [%4];"
                 : "=r"(r0), "=r"(r1), "=r"(r2), "=r"(r3) : "r"(a));
}

// ---------------- tf32 tensor-core GEMM, 4-stage cp.async pipeline ----------------
// C[M,N] = alpha * A[M,K] @ B + residual R
// TB=true : B row-major [N,K] (C = A @ B^T). A and B fragments via ldmatrix.x4.
// TB=false: B row-major [K,N] (attn@V only). A via ldmatrix; B via LDS.
// RND : round output to tf32.
// SST : epilogue computes per-(row, N-tile) softmax partials (max, sum-exp) -> stats.
// PEX : A-fragments transformed a' = tf32(exp2(a*l2e - Ml2[row])); epilogue scales rows by 1/S.
#define BM 128
#define BN 128
#define BK 16
#define LDA_S 20
#define LDB_S 136
#define NSTAGE 4
#define ASZ (BM * LDA_S)

template<bool TB, bool RND, bool SST, bool PEX>
__global__ void __launch_bounds__(256, 2) mm_k(
    const float* __restrict__ A, const float* __restrict__ B,
    const float* __restrict__ R, float* __restrict__ C,
    int M, int N, int K, int lda, int ldb, int ldc,
    long long aB, long long aH, long long bB, long long bH,
    long long cB, long long cH, float alpha,
    float2* __restrict__ stats, const float* __restrict__ cml2,
    const float* __restrict__ cinv)
{
    int z = blockIdx.z, bb = z >> 4, hh = z & 15;
    A += bb * aB + hh * aH;
    B += bb * bB + hh * bH;
    C += bb * cB + hh * cH;
    if (R) R += bb * cB + hh * cH;

    constexpr int BSZ = TB ? (BN * LDA_S) : (BK * LDB_S);
    extern __shared__ float smem[];
    float* AsBase = smem;
    float* BsBase = smem + NSTAGE * ASZ;

    const int tid = threadIdx.x;
    const int row0 = blockIdx.y * BM, col0 = blockIdx.x * BN;

    const int lane = tid & 31, warp = tid >> 5;
    const int g  = lane >> 2, tg = lane & 3;
    const int mb = (warp >> 1) * 32;
    const int nb = (warp & 1) * 64;

    const int lm = lane >> 3, lr = lane & 7;
    const int aoff0 = (mb + (lm & 1) * 8 + lr) * LDA_S + (lm >> 1) * 4;
    const int boff0 = (nb + (lm >> 1) * 8 + lr) * LDA_S + (lm & 1) * 4;

    // PEX: per-row softmax constants
    __shared__ float sMl2[128], sInv[128];
    float mlA[2], mlB[2];
    if (PEX) {
        if (tid < 128) {
            long long ridx = (long long)z * Mq + row0 + tid;
            sMl2[tid] = cml2[ridx];
            sInv[tid] = cinv[ridx];
        }
        __syncthreads();
        #pragma unroll
        for (int mi = 0; mi < 2; ++mi) {
            mlA[mi] = sMl2[mb + mi * 16 + g];
            mlB[mi] = sMl2[mb + mi * 16 + 8 + g];
        }
    }

    float acc[2][8][4];
    #pragma unroll
    for (int mi = 0; mi < 2; mi++)
        #pragma unroll
        for (int ni = 0; ni < 8; ni++)
            #pragma unroll
            for (int q = 0; q < 4; q++) acc[mi][ni][q] = 0.f;

    auto copyA = [&](int buf, int kt) {
        float* dst = AsBase + buf * ASZ;
        #pragma unroll
        for (int q = tid; q < 512; q += 256) {
            int r = q >> 2, cs = (q & 3) * 4;
            const float* gp = A + (long long)(row0 + r) * lda + kt + cs;
            unsigned s = (unsigned)__cvta_generic_to_shared(&dst[r * LDA_S + cs]);
            asm volatile("cp.async.ca.shared.global [%0], [%1], 16;\n" :: "r"(s), "l"(gp));
        }
    };
    auto copyB = [&](int buf, int kt) {
        float* dst = BsBase + buf * BSZ;
        if (TB) {
            #pragma unroll
            for (int q = tid; q < 512; q += 256) {
                int r = q >> 2, cs = (q & 3) * 4;
                const float* gp = B + (long long)(col0 + r) * ldb + kt + cs;
                unsigned s = (unsigned)__cvta_generic_to_shared(&dst[r * LDA_S + cs]);
                asm volatile("cp.async.ca.shared.global [%0], [%1], 16;\n" :: "r"(s), "l"(gp));
            }
        } else {
            #pragma unroll
            for (int q = tid; q < 512; q += 256) {
                int kr = q >> 5, ns = (q & 31) * 4;
                const float* gp = B + (long long)(kt + kr) * ldb + col0 + ns;
                unsigned s = (unsigned)__cvta_generic_to_shared(&dst[kr * LDB_S + ns]);
                asm volatile("cp.async.ca.shared.global [%0], [%1], 16;\n" :: "r"(s), "l"(gp));
            }
        }
    };

    const int nt = K / BK;

    #pragma unroll
    for (int s = 0; s < NSTAGE - 1; ++s) {
        copyA(s, s * BK);
        copyB(s, s * BK);
        asm volatile("cp.async.commit_group;\n" ::: "memory");
    }

    for (int t = 0; t < nt; ++t) {
        asm volatile("cp.async.wait_group %0;\n" :: "n"(NSTAGE - 2) : "memory");
        __syncthreads();

        int nxt = t + NSTAGE - 1;
        if (nxt < nt) {
            copyA(nxt & (NSTAGE - 1), nxt * BK);
            copyB(nxt & (NSTAGE - 1), nxt * BK);
        }
        asm volatile("cp.async.commit_group;\n" ::: "memory");

        const int cur = t & (NSTAGE - 1);
        const float* as = AsBase + cur * ASZ;
        const float* bs = BsBase + cur * BSZ;

        #pragma unroll
        for (int kk = 0; kk < BK; kk += 8) {
            unsigned a[2][4], b[8][2];
            #pragma unroll
            for (int mi = 0; mi < 2; ++mi)
                ldsm_x4(a[mi][0], a[mi][1], a[mi][2], a[mi][3],
                        as + aoff0 + mi * 16 * LDA_S + kk);
            if (PEX) {
                #pragma unroll
                for (int mi = 0; mi < 2; ++mi) {
                    a[mi][0] = f2tfu(exp2f(fmaf(__uint_as_float(a[mi][0]), L2E_, -mlA[mi])));
                    a[mi][2] = f2tfu(exp2f(fmaf(__uint_as_float(a[mi][2]), L2E_, -mlA[mi])));
                    a[mi][1] = f2tfu(exp2f(fmaf(__uint_as_float(a[mi][1]), L2E_, -mlB[mi])));
                    a[mi][3] = f2tfu(exp2f(fmaf(__uint_as_float(a[mi][3]), L2E_, -mlB[mi])));
                }
            }
            if (TB) {
                #pragma unroll
                for (int j = 0; j < 4; ++j)
                    ldsm_x4(b[2 * j][0], b[2 * j][1], b[2 * j + 1][0], b[2 * j + 1][1],
                            bs + boff0 + j * 16 * LDA_S + kk);
            } else {
                #pragma unroll
                for (int ni = 0; ni < 8; ++ni) {
                    int n = nb + ni * 8 + g;
                    b[ni][0] = __float_as_uint(bs[(kk + tg) * LDB_S + n]);
                    b[ni][1] = __float_as_uint(bs[(kk + tg + 4) * LDB_S + n]);
                }
            }
            #pragma unroll
            for (int mi = 0; mi < 2; ++mi)
                #pragma unroll
                for (int ni = 0; ni < 8; ++ni)
                    asm volatile(
                        "mma.sync.aligned.m16n8k8.row.col.f32.tf32.tf32.f32 "
                        "{%0,%1,%2,%3}, {%4,%5,%6,%7}, {%8,%9}, {%0,%1,%2,%3};\n"
                        : "+f"(acc[mi][ni][0]), "+f"(acc[mi][ni][1]),
                          "+f"(acc[mi][ni][2]), "+f"(acc[mi][ni][3])
                        : "r"(a[mi][0]), "r"(a[mi][1]), "r"(a[mi][2]), "r"(a[mi][3]),
                          "r"(b[ni][0]), "r"(b[ni][1]));
        }
    }

    // -------- C write --------
    #pragma unroll
    for (int mi = 0; mi < 2; ++mi) {
        float ivA = 1.f, ivB = 1.f;
        if (PEX) {
            ivA = sInv[mb + mi * 16 + g];
            ivB = sInv[mb + mi * 16 + 8 + g];
        }
        #pragma unroll
        for (int ni = 0; ni < 8; ++ni) {
            long long rr = row0 + mb + mi * 16 + g;
            long long cc = col0 + nb + ni * 8 + tg * 2;
            float2 v0 = make_float2(acc[mi][ni][0] * alpha, acc[mi][ni][1] * alpha);
            float2 v1 = make_float2(acc[mi][ni][2] * alpha, acc[mi][ni][3] * alpha);
            if (PEX) { v0.x *= ivA; v0.y *= ivA; v1.x *= ivB; v1.y *= ivB; }
            if (R) {
                float2 r0 = *(const float2*)&R[rr * ldc + cc];
                float2 r1 = *(const float2*)&R[(rr + 8) * ldc + cc];
                v0.x += r0.x; v0.y += r0.y; v1.x += r1.x; v1.y += r1.y;
            }
            if (RND) {
                v0.x = tf32r(v0.x); v0.y = tf32r(v0.y);
                v1.x = tf32r(v1.x); v1.y = tf32r(v1.y);
            }
            *(float2*)&C[rr * ldc + cc] = v0;
            *(float2*)&C[(rr + 8) * ldc + cc] = v1;
        }
    }

    // -------- softmax partial stats (scores GEMM only) --------
    if (SST) {
        __syncthreads();                 // stage buffers now reusable
        float* st  = smem;               // [2][128] per-warp-column max parts
        float* st2 = smem + 256;         // [2][128] sum parts
        const int wc = warp & 1;
        float mx[2][2], sm[2][2];
        #pragma unroll
        for (int mi = 0; mi < 2; ++mi)
            #pragma unroll
            for (int h = 0; h < 2; ++h) {
                float m = -3.4e38f;
                #pragma unroll
                for (int ni = 0; ni < 8; ++ni)
                    m = fmaxf(m, fmaxf(acc[mi][ni][2 * h] * alpha,
                                       acc[mi][ni][2 * h + 1] * alpha));
                #pragma unroll
                for (int o = 1; o <= 2; o <<= 1)
                    m = fmaxf(m, __shfl_xor_sync(0xffffffffu, m, o));
                mx[mi][h] = m;
            }
        if (tg == 0) {
            #pragma unroll
            for (int mi = 0; mi < 2; ++mi)
                #pragma unroll
                for (int h = 0; h < 2; ++h)
                    st[wc * 128 + mb + mi * 16 + h * 8 + g] = mx[mi][h];
        }
        __syncthreads();
        #pragma unroll
        for (int mi = 0; mi < 2; ++mi)
            #pragma unroll
            for (int h = 0; h < 2; ++h) {
                int lrw = mb + mi * 16 + h * 8 + g;
                float M2 = fmaxf(st[lrw], st[128 + lrw]);
                float s = 0.f;
                #pragma unroll
                for (int ni = 0; ni < 8; ++ni)
                    s += expf(acc[mi][ni][2 * h] * alpha - M2)
                       + expf(acc[mi][ni][2 * h + 1] * alpha - M2);
                #pragma unroll
                for (int o = 1; o <= 2; o <<= 1)
                    s += __shfl_xor_sync(0xffffffffu, s, o);
                sm[mi][h] = s;
            }
        if (tg == 0) {
            #pragma unroll
            for (int mi = 0; mi < 2; ++mi)
                #pragma unroll
                for (int h = 0; h < 2; ++h)
                    st2[wc * 128 + mb + mi * 16 + h * 8 + g] = sm[mi][h];
        }
        __syncthreads();
        if (wc == 0 && tg == 0) {
            #pragma unroll
            for (int mi = 0; mi < 2; ++mi)
                #pragma unroll
                for (int h = 0; h < 2; ++h) {
                    int lrw = mb + mi * 16 + h * 8 + g;
                    float M2 = fmaxf(st[lrw], st[128 + lrw]);
                    float S2 = st2[lrw] + st2[128 + lrw];
                    stats[((long long)z * Mq + row0 + lrw) * 16 + blockIdx.x] =
                        make_float2(M2, S2);
                }
        }
    }
}

#define SMEM_TB  (NSTAGE * (ASZ + BN * LDA_S) * 4)
#define SMEM_NTB (NSTAGE * (ASZ + BK * LDB_S) * 4)

// ---------------- combine softmax stats ----------------
__global__ void combine_k(const float2* __restrict__ st, float* __restrict__ cml2,
                          float* __restrict__ cinv) {
    long long row = (long long)blockIdx.x * 256 + threadIdx.x;   // N_ROWS total
    const float2* p = st + row * 16;
    float2 v[16];
    float M = -3.4e38f;
    #pragma unroll
    for (int i = 0; i < 16; i++) { v[i] = p[i]; M = fmaxf(M, v[i].x); }
    float S = 0.f;
    #pragma unroll
    for (int i = 0; i < 16; i++) S += v[i].y * expf(v[i].x - M);
    cml2[row] = M * L2E_;
    cinv[row] = 1.f / S;
}

// ---------------- RoPE ----------------
__global__ void rope_k(float* __restrict__ x, int seqlen) {
    long long g = (long long)blockIdx.x * blockDim.x + threadIdx.x;
    const long long total = (long long)Tt * NH * (DR / 2);
    if (g >= total) return;
    int j = (int)(g % (DR / 2));
    long long th = g / (DR / 2);
    int h = (int)(th % NH);
    long long tok = th / NH;
    int s = (int)(tok % seqlen);
    float freq = (float)pow((double)1000000.0, -2.0 * j / (double)DR);
    float ang = (float)s * freq;
    float c = cosf(ang), si = sinf(ang);
    long long idx = tok * (NH * DR) + h * DR + 2 * j;
    float x1 = x[idx], x2 = x[idx + 1];
    x[idx]     = x1 * c - x2 * si;
    x[idx + 1] = x2 * c + x1 * si;
}

// ---------------- pack [C | R] -> (T, NH, 192), tf32-rounded ----------------
__global__ void pack_k(const float* __restrict__ c, const float* __restrict__ rr,
                       float* __restrict__ cat) {
    long long i = (long long)blockIdx.x * blockDim.x + threadIdx.x;
    const long long total = (long long)Tt * NH * DCAT;
    if (i >= total) return;
    int d = (int)(i % DCAT);
    long long th = i / DCAT;
    int h = (int)(th % NH);
    long long tok = th / NH;
    float v = (d < DH) ? c[tok * (NH * DH) + h * DH + d]
                       : rr[tok * (NH * DR) + h * DR + (d - DH)];
    cat[i] = tf32r(v);
}

// ---------------- silu(gate)*up, tf32-rounded ----------------
__global__ void silumul_k(float* __restrict__ g, const float* __restrict__ u) {
    long long i = (long long)blockIdx.x * blockDim.x + threadIdx.x;
    const long long total = (long long)Tt * FFN_;
    if (i >= total) return;
    float x = g[i];
    g[i] = tf32r((x / (1.f + expf(-x))) * u[i]);
}

// ---------------- launch ----------------
extern "C" void kernel_launch(void* const* d_in, const int* in_sizes, int n_in,
                              void* d_out, int out_size) {
    (void)in_sizes; (void)n_in; (void)out_size;
    const float* query  = (const float*)d_in[0];
    const float* keyval = (const float*)d_in[1];
    const float* g_q    = (const float*)d_in[2];
    const float* g_kv   = (const float*)d_in[3];
    const float* g_ffn  = (const float*)d_in[4];
    const float* w_qc   = (const float*)d_in[5];
    const float* w_kc   = (const float*)d_in[6];
    const float* w_qr   = (const float*)d_in[7];
    const float* w_kr   = (const float*)d_in[8];
    const float* w_v    = (const float*)d_in[9];
    const float* w_o    = (const float*)d_in[10];
    const float* w_gate = (const float*)d_in[11];
    const float* w_up   = (const float*)d_in[12];
    const float* w_down = (const float*)d_in[13];
    float* out = (float*)d_out;

    static bool attr_done = false;
    if (!attr_done) {
        cudaFuncSetAttribute(mm_k<true,  false, false, false>, cudaFuncAttributeMaxDynamicSharedMemorySize, SMEM_TB);
        cudaFuncSetAttribute(mm_k<true,  true,  false, false>, cudaFuncAttributeMaxDynamicSharedMemorySize, SMEM_TB);
        cudaFuncSetAttribute(mm_k<true,  false, true,  false>, cudaFuncAttributeMaxDynamicSharedMemorySize, SMEM_TB);
        cudaFuncSetAttribute(mm_k<false, true,  false, true >, cudaFuncAttributeMaxDynamicSharedMemorySize, SMEM_NTB);
        attr_done = true;
    }

    float* S = nullptr;
    cudaGetSymbolAddress((void**)&S, g_scratch);
    float* qn    = S + O_QN;
    float* kvn   = S + O_KVN;
    float* qc    = S + O_QC;
    float* kc    = S + O_KC;
    float* qr    = S + O_QR;
    float* kr    = S + O_KR;
    float* vv    = S + O_V;
    float* qcat  = S + O_QCAT;
    float* kcat  = S + O_KCAT;
    float* sc    = S + O_SC;
    float* att   = S + O_ATT;
    float* x     = S + O_X;
    float* xn    = S + O_XN;
    float* gate  = S + O_GATE;
    float* up    = S + O_UP;
    float* cwqc  = S + O_WQC;
    float* cwkc  = S + O_WKC;
    float* cwqr  = S + O_WQR;
    float* cwkr  = S + O_WKR;
    float* cwv   = S + O_WV;
    float* cwo   = S + O_WO;
    float* cwg   = S + O_WGATE;
    float* cwu   = S + O_WUP;
    float* cwd   = S + O_WDOWN;
    float2* stb  = (float2*)(S + O_ST);
    float* cml2  = S + O_CML2;
    float* cinv  = S + O_CINV;

    // 0. Pre-round + transpose weights to [n][k] tf32
    {
        dim3 blk(32, 8);
        dim3 gDD(Dm / 32, Dm / 32);
        dim3 gDR((NH * DR) / 32, Dm / 32);
        dim3 gDF(FFN_ / 32, Dm / 32);
        dim3 gFD(Dm / 32, FFN_ / 32);
        cvtwT_k<<<gDD, blk>>>(w_qc,   cwqc, Dm, Dm);
        cvtwT_k<<<gDD, blk>>>(w_kc,   cwkc, Dm, Dm);
        cvtwT_k<<<gDR, blk>>>(w_qr,   cwqr, Dm, NH * DR);
        cvtwT_k<<<gDR, blk>>>(w_kr,   cwkr, Dm, NH * DR);
        cvtwT_k<<<gDD, blk>>>(w_v,    cwv,  Dm, Dm);
        cvtwT_k<<<gDD, blk>>>(w_o,    cwo,  NH * DH, Dm);
        cvtwT_k<<<gDF, blk>>>(w_gate, cwg,  Dm, FFN_);
        cvtwT_k<<<gDF, blk>>>(w_up,   cwu,  Dm, FFN_);
        cvtwT_k<<<gFD, blk>>>(w_down, cwd,  FFN_, Dm);
    }

    // 1. RMSNorm inputs
    rmsnorm_k<<<Tt, 256>>>(query,  g_q,  qn);
    rmsnorm_k<<<Tt, 256>>>(keyval, g_kv, kvn);

    // 2. Projections (TB path, transposed weights [n][k], ldb = K)
    {
        dim3 grid(Dm / BN, Tt / BM, 1);
        mm_k<true,false,false,false><<<grid, 256, SMEM_TB>>>(qn,  cwqc, nullptr, qc, Tt, Dm, Dm, Dm, Dm, Dm, 0,0,0,0,0,0, 1.f, nullptr, nullptr, nullptr);
        mm_k<true,false,false,false><<<grid, 256, SMEM_TB>>>(kvn, cwkc, nullptr, kc, Tt, Dm, Dm, Dm, Dm, Dm, 0,0,0,0,0,0, 1.f, nullptr, nullptr, nullptr);
        mm_k<true,true ,false,false><<<grid, 256, SMEM_TB>>>(kvn, cwv,  nullptr, vv, Tt, Dm, Dm, Dm, Dm, Dm, 0,0,0,0,0,0, 1.f, nullptr, nullptr, nullptr);
    }
    {
        dim3 grid((NH * DR) / BN, Tt / BM, 1);
        mm_k<true,false,false,false><<<grid, 256, SMEM_TB>>>(qn,  cwqr, nullptr, qr, Tt, NH * DR, Dm, Dm, Dm, NH * DR, 0,0,0,0,0,0, 1.f, nullptr, nullptr, nullptr);
        mm_k<true,false,false,false><<<grid, 256, SMEM_TB>>>(kvn, cwkr, nullptr, kr, Tt, NH * DR, Dm, Dm, Dm, NH * DR, 0,0,0,0,0,0, 1.f, nullptr, nullptr, nullptr);
    }

    // 3. RoPE
    {
        long long pairs = (long long)Tt * NH * (DR / 2);
        int blocks = (int)((pairs + 255) / 256);
        rope_k<<<blocks, 256>>>(qr, Mq);
        rope_k<<<blocks, 256>>>(kr, Nq);
    }

    // 4. Pack [C|R]
    {
        long long tot = (long long)Tt * NH * DCAT;
        int blocks = (int)((tot + 255) / 256);
        pack_k<<<blocks, 256>>>(qc, qr, qcat);
        pack_k<<<blocks, 256>>>(kc, kr, kcat);
    }

    // 5. Scores = scale * Qcat @ Kcat^T  (+ per-tile softmax stats)
    {
        dim3 grid(Nq / BN, Mq / BM, Bq * NH);
        mm_k<true,false,true,false><<<grid, 256, SMEM_TB>>>(qcat, kcat, nullptr, sc,
            Mq, Nq, DCAT, NH * DCAT, NH * DCAT, Nq,
            (long long)Mq * NH * DCAT, (long long)DCAT,
            (long long)Nq * NH * DCAT, (long long)DCAT,
            (long long)NH * Mq * Nq, (long long)Mq * Nq,
            SCALE_, stb, nullptr, nullptr);
    }

    // 6. Combine stats -> per-row (M*log2e, 1/S)
    combine_k<<<(int)(N_ROWS / 256), 256>>>(stb, cml2, cinv);

    // 7. attn @ V with in-register softmax (A = raw scores, exp applied to fragments)
    {
        dim3 grid(DH / BN, Mq / BM, Bq * NH);
        mm_k<false,true,false,true><<<grid, 256, SMEM_NTB>>>(sc, vv, nullptr, att,
            Mq, DH, Nq, Nq, NH * DH, NH * DH,
            (long long)NH * Mq * Nq, (long long)Mq * Nq,
            (long long)Nq * NH * DH, (long long)DH,
            (long long)Mq * NH * DH, (long long)DH,
            1.f, nullptr, cml2, cinv);
    }

    // 8. x = att @ w_o + query
    {
        dim3 grid(Dm / BN, Tt / BM, 1);
        mm_k<true,false,false,false><<<grid, 256, SMEM_TB>>>(att, cwo, query, x, Tt, Dm, NH * DH,
                                        NH * DH, NH * DH, Dm, 0,0,0,0,0,0, 1.f, nullptr, nullptr, nullptr);
    }

    // 9. RMSNorm -> xn
    rmsnorm_k<<<Tt, 256>>>(x, g_ffn, xn);

    // 10. gate / up
    {
        dim3 grid(FFN_ / BN, Tt / BM, 1);
        mm_k<true,false,false,false><<<grid, 256, SMEM_TB>>>(xn, cwg, nullptr, gate, Tt, FFN_, Dm, Dm, Dm, FFN_, 0,0,0,0,0,0, 1.f, nullptr, nullptr, nullptr);
        mm_k<true,false,false,false><<<grid, 256, SMEM_TB>>>(xn, cwu, nullptr, up,   Tt, FFN_, Dm, Dm, Dm, FFN_, 0,0,0,0,0,0, 1.f, nullptr, nullptr, nullptr);
    }

    // 11. silu(gate)*up
    {
        long long tot = (long long)Tt * FFN_;
        int blocks = (int)((tot + 255) / 256);
        silumul_k<<<blocks, 256>>>(gate, up);
    }

    // 12. out = h @ w_down + x
    {
        dim3 grid(Dm / BN, Tt / BM, 1);
        mm_k<true,false,false,false><<<grid, 256, SMEM_TB>>>(gate, cwd, x, out, Tt, Dm, FFN_,
                                        FFN_, FFN_, Dm, 0,0,0,0,0,0, 1.f, nullptr, nullptr, nullptr);
    }
}

// round 14
// speedup vs baseline: 4.8820x; 1.5820x over previous
#include <cuda_runtime.h>
#include <cuda_fp16.h>
#include <math.h>
#include <stdint.h>

// Problem constants
#define Bq   2
#define Mq   2048
#define Nq   2048
#define Dm   2048
#define NH   16
#define DH   128
#define DR   64
#define FFN_ 8192
#define Tt   (Bq*Mq)
#define DCAT (DH+DR)          // 192
#define SCALE_ (0.0721687836487032f) // 1/sqrt(192)
#define L2E_  1.4426950408889634f

// ---------------- scratch (float units; half buffers reuse same regions) ----------------
#define O_QN    0LL
#define O_KVN   (O_QN   + (long long)Tt*Dm)
#define O_QC    (O_KVN  + (long long)Tt*Dm)
#define O_KC    (O_QC   + (long long)Tt*NH*DH)
#define O_QR    (O_KC   + (long long)Tt*NH*DH)
#define O_KR    (O_QR   + (long long)Tt*NH*DR)
#define O_V     (O_KR   + (long long)Tt*NH*DR)
#define O_QCAT  (O_V    + (long long)Tt*NH*DH)
#define O_KCAT  (O_QCAT + (long long)Tt*NH*DCAT)
#define O_SC    (O_KCAT + (long long)Tt*NH*DCAT)
#define O_ATT   (O_SC   + (long long)Bq*NH*Mq*Nq)
#define O_X     (O_ATT  + (long long)Tt*NH*DH)
#define O_XN    (O_X    + (long long)Tt*Dm)
#define O_GATE  (O_XN   + (long long)Tt*Dm)
#define O_UP    (O_GATE + (long long)Tt*FFN_)
#define SZ_DD   ((long long)Dm*Dm)
#define SZ_DR2  ((long long)Dm*NH*DR)
#define SZ_DF   ((long long)Dm*FFN_)
#define O_WQC   (O_UP   + (long long)Tt*FFN_)
#define O_WKC   (O_WQC  + SZ_DD)
#define O_WQR   (O_WKC  + SZ_DD)
#define O_WKR   (O_WQR  + SZ_DR2)
#define O_WV    (O_WKR  + SZ_DR2)
#define O_WO    (O_WV   + SZ_DD)
#define O_WGATE (O_WO   + SZ_DD)
#define O_WUP   (O_WGATE+ SZ_DF)
#define O_WDOWN (O_WUP  + SZ_DF)
#define N_ROWS  ((long long)Bq*NH*Mq)
#define O_ST    (O_WDOWN+ SZ_DF)
#define O_CML2  (O_ST   + N_ROWS*16*2)
#define O_CINV  (O_CML2 + N_ROWS)
#define O_VT    (O_CINV + N_ROWS)          // half[Tt*NH*DH] -> Tt*NH*DH/2 floats; reserve full
#define O_TOTAL (O_VT   + (long long)Tt*NH*DH)

__device__ float g_scratch[O_TOTAL];

// ---------------- weight fp16 round + transpose: src[K][N] fp32 -> dst[N][K] half ----------------
__global__ void cvtwT_h(const float* __restrict__ src, __half* __restrict__ dst,
                        int K, int N) {
    __shared__ float t[32][33];
    int n0 = blockIdx.x * 32, k0 = blockIdx.y * 32;
    int tx = threadIdx.x, ty0 = threadIdx.y;
    #pragma unroll
    for (int ty = ty0; ty < 32; ty += 8)
        t[ty][tx] = src[(long long)(k0 + ty) * N + n0 + tx];
    __syncthreads();
    #pragma unroll
    for (int ty = ty0; ty < 32; ty += 8)
        dst[(long long)(n0 + ty) * K + k0 + tx] = __float2half_rn(t[tx][ty]);
}

// ---------------- RMSNorm -> half ----------------
__global__ void rmsnorm_h(const float* __restrict__ x, const float* __restrict__ g,
                          __half* __restrict__ y) {
    const int D = Dm;
    long long row = blockIdx.x;
    const float* xr = x + row * D;
    __half* yr = y + row * D;
    float s = 0.f;
    for (int i = threadIdx.x; i < D; i += blockDim.x) { float v = xr[i]; s += v * v; }
    #pragma unroll
    for (int o = 16; o; o >>= 1) s += __shfl_xor_sync(0xffffffffu, s, o);
    __shared__ float sh[8];
    if ((threadIdx.x & 31) == 0) sh[threadIdx.x >> 5] = s;
    __syncthreads();
    float tot = 0.f;
    #pragma unroll
    for (int i = 0; i < 8; i++) tot += sh[i];
    float n = rsqrtf(tot / (float)D + 1e-6f);
    for (int i = threadIdx.x; i < D; i += blockDim.x)
        yr[i] = __float2half_rn(xr[i] * n * g[i]);
}

// ---------------- ldmatrix ----------------
__device__ __forceinline__ void ldsm_x4(unsigned& r0, unsigned& r1, unsigned& r2, unsigned& r3,
                                        const __half* p) {
    unsigned a = (unsigned)__cvta_generic_to_shared(p);
    asm volatile("ldmatrix.sync.aligned.m8n8.x4.shared.b16 {%0,%1,%2,%3}, [%4];"
                 : "=r"(r0), "=r"(r1), "=r"(r2), "=r"(r3) : "r"(a));
}

// ---------------- fp16 tensor-core GEMM, multi-stage cp.async ----------------
// C[M,N] = alpha * A[M,K] @ B[N,K]^T (+R).  B always half [N][K] (k-contig).
// PEX=false: A half [M][K], fragments via ldmatrix.
// PEX=true : A fp32 scores; fragments = half(exp2(a*l2e - Ml2[row])); epilogue *= 1/S.
// SST: epilogue emits per-(row,128-col-tile) softmax partials.
// HOUT: C is half, no residual; else C fp32 with optional residual R.
#define BM 128
#define BN 128
#define BKH 32          // K per tile (elements)
#define PH  40          // half-tile row pitch (halves): conflict-free ldmatrix
#define PF  36          // fp32 score-tile row pitch (floats)

template<bool PEX, bool SST, bool HOUT>
__global__ void __launch_bounds__(256, 2) mm_h(
    const void* __restrict__ Av, const __half* __restrict__ B,
    const float* __restrict__ R, void* __restrict__ Cv,
    int M, int N, int K, int lda, int ldb, int ldc,
    long long aB, long long aH, long long bB, long long bH,
    long long cB, long long cH, float alpha,
    float2* __restrict__ stats, const float* __restrict__ cml2,
    const float* __restrict__ cinv)
{
    constexpr int NST = PEX ? 3 : 4;
    constexpr int ABYTES = PEX ? (BM * PF * 4) : (BM * PH * 2);
    constexpr int BBYTES = BN * PH * 2;

    int z = blockIdx.z, bb = z >> 4, hh = z & 15;
    const __half* Ah = (const __half*)Av + bb * aB + hh * aH;
    const float*  Af = (const float*)Av + bb * aB + hh * aH;
    B += bb * bB + hh * bH;
    float*  Cf = (float*)Cv + bb * cB + hh * cH;
    __half* Ch = (__half*)Cv + bb * cB + hh * cH;
    if (R) R += bb * cB + hh * cH;

    extern __shared__ __align__(16) char smraw[];
    char* AsBase = smraw;
    char* BsBase = smraw + NST * ABYTES;

    const int tid = threadIdx.x;
    const int row0 = blockIdx.y * BM, col0 = blockIdx.x * BN;

    const int lane = tid & 31, warp = tid >> 5;
    const int g  = lane >> 2, tg = lane & 3;
    const int mb = (warp >> 1) * 32;
    const int nb = (warp & 1) * 64;
    const int lm = lane >> 3, lr = lane & 7;
    // ldmatrix per-lane element offset (halves) within a tile at (rowbase, kk):
    const int lrow = (lm & 1) * 8 + lr, lcol = (lm >> 1) * 8;

    __shared__ float sMl2[128], sInv[128];
    float mlA[2], mlB_[2];
    if (PEX) {
        if (tid < 128) {
            long long ridx = (long long)z * Mq + row0 + tid;
            sMl2[tid] = cml2[ridx];
            sInv[tid] = cinv[ridx];
        }
        __syncthreads();
        #pragma unroll
        for (int mi = 0; mi < 2; ++mi) {
            mlA[mi]  = sMl2[mb + mi * 16 + g];
            mlB_[mi] = sMl2[mb + mi * 16 + 8 + g];
        }
    }

    float acc[2][8][4];
    #pragma unroll
    for (int mi = 0; mi < 2; mi++)
        #pragma unroll
        for (int ni = 0; ni < 8; ni++)
            #pragma unroll
            for (int q = 0; q < 4; q++) acc[mi][ni][q] = 0.f;

    auto copyA = [&](int buf, int kt) {
        if (PEX) {
            float* dst = (float*)(AsBase + buf * ABYTES);
            #pragma unroll
            for (int q = tid; q < 1024; q += 256) {
                int r = q >> 3, c = q & 7;
                const float* gp = Af + (long long)(row0 + r) * lda + kt + c * 4;
                unsigned s = (unsigned)__cvta_generic_to_shared(&dst[r * PF + c * 4]);
                asm volatile("cp.async.ca.shared.global [%0], [%1], 16;\n" :: "r"(s), "l"(gp));
            }
        } else {
            __half* dst = (__half*)(AsBase + buf * ABYTES);
            #pragma unroll
            for (int q = tid; q < 512; q += 256) {
                int r = q >> 2, c = q & 3;
                const __half* gp = Ah + (long long)(row0 + r) * lda + kt + c * 8;
                unsigned s = (unsigned)__cvta_generic_to_shared(&dst[r * PH + c * 8]);
                asm volatile("cp.async.ca.shared.global [%0], [%1], 16;\n" :: "r"(s), "l"(gp));
            }
        }
    };
    auto copyB = [&](int buf, int kt) {
        __half* dst = (__half*)(BsBase + buf * BBYTES);
        #pragma unroll
        for (int q = tid; q < 512; q += 256) {
            int r = q >> 2, c = q & 3;
            const __half* gp = B + (long long)(col0 + r) * ldb + kt + c * 8;
            unsigned s = (unsigned)__cvta_generic_to_shared(&dst[r * PH + c * 8]);
            asm volatile("cp.async.ca.shared.global [%0], [%1], 16;\n" :: "r"(s), "l"(gp));
        }
    };

    const int nt = K / BKH;

    #pragma unroll
    for (int s = 0; s < NST - 1; ++s) {
        copyA(s, s * BKH);
        copyB(s, s * BKH);
        asm volatile("cp.async.commit_group;\n" ::: "memory");
    }

    for (int t = 0; t < nt; ++t) {
        asm volatile("cp.async.wait_group %0;\n" :: "n"(NST - 2) : "memory");
        __syncthreads();

        int nxt = t + NST - 1;
        if (nxt < nt) {
            copyA(nxt % NST, nxt * BKH);
            copyB(nxt % NST, nxt * BKH);
        }
        asm volatile("cp.async.commit_group;\n" ::: "memory");

        const int cur = t % NST;
        const __half* asH = (const __half*)(AsBase + cur * ABYTES);
        const float*  asF = (const float*)(AsBase + cur * ABYTES);
        const __half* bs  = (const __half*)(BsBase + cur * BBYTES);

        #pragma unroll
        for (int kk = 0; kk < BKH; kk += 16) {
            unsigned a[2][4], b[8][2];
            if (PEX) {
                #pragma unroll
                for (int mi = 0; mi < 2; ++mi) {
                    int mlo = mb + mi * 16 + g;
                    float2 v00 = *(const float2*)&asF[mlo * PF + kk + 2 * tg];
                    float2 v10 = *(const float2*)&asF[(mlo + 8) * PF + kk + 2 * tg];
                    float2 v01 = *(const float2*)&asF[mlo * PF + kk + 8 + 2 * tg];
                    float2 v11 = *(const float2*)&asF[(mlo + 8) * PF + kk + 8 + 2 * tg];
                    __half2 h0 = __floats2half2_rn(exp2f(fmaf(v00.x, L2E_, -mlA[mi])),
                                                   exp2f(fmaf(v00.y, L2E_, -mlA[mi])));
                    __half2 h1 = __floats2half2_rn(exp2f(fmaf(v10.x, L2E_, -mlB_[mi])),
                                                   exp2f(fmaf(v10.y, L2E_, -mlB_[mi])));
                    __half2 h2 = __floats2half2_rn(exp2f(fmaf(v01.x, L2E_, -mlA[mi])),
                                                   exp2f(fmaf(v01.y, L2E_, -mlA[mi])));
                    __half2 h3 = __floats2half2_rn(exp2f(fmaf(v11.x, L2E_, -mlB_[mi])),
                                                   exp2f(fmaf(v11.y, L2E_, -mlB_[mi])));
                    a[mi][0] = *(unsigned*)&h0; a[mi][1] = *(unsigned*)&h1;
                    a[mi][2] = *(unsigned*)&h2; a[mi][3] = *(unsigned*)&h3;
                }
            } else {
                #pragma unroll
                for (int mi = 0; mi < 2; ++mi)
                    ldsm_x4(a[mi][0], a[mi][1], a[mi][2], a[mi][3],
                            asH + (mb + mi * 16 + lrow) * PH + kk + lcol);
            }
            #pragma unroll
            for (int j = 0; j < 4; ++j) {
                unsigned r0, r1, r2, r3;
                ldsm_x4(r0, r1, r2, r3,
                        bs + (nb + j * 16 + lrow) * PH + kk + lcol);
                b[2 * j][0] = r0; b[2 * j][1] = r2;
                b[2 * j + 1][0] = r1; b[2 * j + 1][1] = r3;
            }
            #pragma unroll
            for (int mi = 0; mi < 2; ++mi)
                #pragma unroll
                for (int ni = 0; ni < 8; ++ni)
                    asm volatile(
                        "mma.sync.aligned.m16n8k16.row.col.f32.f16.f16.f32 "
                        "{%0,%1,%2,%3}, {%4,%5,%6,%7}, {%8,%9}, {%0,%1,%2,%3};\n"
                        : "+f"(acc[mi][ni][0]), "+f"(acc[mi][ni][1]),
                          "+f"(acc[mi][ni][2]), "+f"(acc[mi][ni][3])
                        : "r"(a[mi][0]), "r"(a[mi][1]), "r"(a[mi][2]), "r"(a[mi][3]),
                          "r"(b[ni][0]), "r"(b[ni][1]));
        }
    }

    // -------- C write --------
    #pragma unroll
    for (int mi = 0; mi < 2; ++mi) {
        float ivA = 1.f, ivB = 1.f;
        if (PEX) {
            ivA = sInv[mb + mi * 16 + g];
            ivB = sInv[mb + mi * 16 + 8 + g];
        }
        #pragma unroll
        for (int ni = 0; ni < 8; ++ni) {
            long long rr = row0 + mb + mi * 16 + g;
            long long cc = col0 + nb + ni * 8 + tg * 2;
            float2 v0 = make_float2(acc[mi][ni][0] * alpha, acc[mi][ni][1] * alpha);
            float2 v1 = make_float2(acc[mi][ni][2] * alpha, acc[mi][ni][3] * alpha);
            if (PEX) { v0.x *= ivA; v0.y *= ivA; v1.x *= ivB; v1.y *= ivB; }
            if (HOUT) {
                __half2 h0 = __floats2half2_rn(v0.x, v0.y);
                __half2 h1 = __floats2half2_rn(v1.x, v1.y);
                *(__half2*)&Ch[rr * ldc + cc] = h0;
                *(__half2*)&Ch[(rr + 8) * ldc + cc] = h1;
            } else {
                if (R) {
                    float2 r0 = *(const float2*)&R[rr * ldc + cc];
                    float2 r1 = *(const float2*)&R[(rr + 8) * ldc + cc];
                    v0.x += r0.x; v0.y += r0.y; v1.x += r1.x; v1.y += r1.y;
                }
                *(float2*)&Cf[rr * ldc + cc] = v0;
                *(float2*)&Cf[(rr + 8) * ldc + cc] = v1;
            }
        }
    }

    // -------- softmax partial stats --------
    if (SST) {
        __syncthreads();
        float* st  = (float*)smraw;
        float* st2 = (float*)smraw + 256;
        const int wc = warp & 1;
        float mx[2][2], sm[2][2];
        #pragma unroll
        for (int mi = 0; mi < 2; ++mi)
            #pragma unroll
            for (int h = 0; h < 2; ++h) {
                float m = -3.4e38f;
                #pragma unroll
                for (int ni = 0; ni < 8; ++ni)
                    m = fmaxf(m, fmaxf(acc[mi][ni][2 * h] * alpha,
                                       acc[mi][ni][2 * h + 1] * alpha));
                #pragma unroll
                for (int o = 1; o <= 2; o <<= 1)
                    m = fmaxf(m, __shfl_xor_sync(0xffffffffu, m, o));
                mx[mi][h] = m;
            }
        if (tg == 0) {
            #pragma unroll
            for (int mi = 0; mi < 2; ++mi)
                #pragma unroll
                for (int h = 0; h < 2; ++h)
                    st[wc * 128 + mb + mi * 16 + h * 8 + g] = mx[mi][h];
        }
        __syncthreads();
        #pragma unroll
        for (int mi = 0; mi < 2; ++mi)
            #pragma unroll
            for (int h = 0; h < 2; ++h) {
                int lrw = mb + mi * 16 + h * 8 + g;
                float M2 = fmaxf(st[lrw], st[128 + lrw]);
                float s = 0.f;
                #pragma unroll
                for (int ni = 0; ni < 8; ++ni)
                    s += expf(acc[mi][ni][2 * h] * alpha - M2)
                       + expf(acc[mi][ni][2 * h + 1] * alpha - M2);
                #pragma unroll
                for (int o = 1; o <= 2; o <<= 1)
                    s += __shfl_xor_sync(0xffffffffu, s, o);
                sm[mi][h] = s;
            }
        if (tg == 0) {
            #pragma unroll
            for (int mi = 0; mi < 2; ++mi)
                #pragma unroll
                for (int h = 0; h < 2; ++h)
                    st2[wc * 128 + mb + mi * 16 + h * 8 + g] = sm[mi][h];
        }
        __syncthreads();
        if (wc == 0 && tg == 0) {
            #pragma unroll
            for (int mi = 0; mi < 2; ++mi)
                #pragma unroll
                for (int h = 0; h < 2; ++h) {
                    int lrw = mb + mi * 16 + h * 8 + g;
                    float M2 = fmaxf(st[lrw], st[128 + lrw]);
                    float S2 = st2[lrw] + st2[128 + lrw];
                    stats[((long long)z * Mq + row0 + lrw) * 16 + blockIdx.x] =
                        make_float2(M2, S2);
                }
        }
    }
}

#define SMEM_H   (4 * (BM * PH * 2 + BN * PH * 2))          // 81920
#define SMEM_PEX (3 * (BM * PF * 4 + BN * PH * 2))          // 86016

// ---------------- combine softmax stats ----------------
__global__ void combine_k(const float2* __restrict__ st, float* __restrict__ cml2,
                          float* __restrict__ cinv) {
    long long row = (long long)blockIdx.x * 256 + threadIdx.x;
    const float2* p = st + row * 16;
    float2 v[16];
    float M = -3.4e38f;
    #pragma unroll
    for (int i = 0; i < 16; i++) { v[i] = p[i]; M = fmaxf(M, v[i].x); }
    float S = 0.f;
    #pragma unroll
    for (int i = 0; i < 16; i++) S += v[i].y * expf(v[i].x - M);
    cml2[row] = M * L2E_;
    cinv[row] = 1.f / S;
}

// ---------------- RoPE (fp32) ----------------
__global__ void rope_k(float* __restrict__ x, int seqlen) {
    long long g = (long long)blockIdx.x * blockDim.x + threadIdx.x;
    const long long total = (long long)Tt * NH * (DR / 2);
    if (g >= total) return;
    int j = (int)(g % (DR / 2));
    long long th = g / (DR / 2);
    int h = (int)(th % NH);
    long long tok = th / NH;
    int s = (int)(tok % seqlen);
    float freq = (float)pow((double)1000000.0, -2.0 * j / (double)DR);
    float ang = (float)s * freq;
    float c = cosf(ang), si = sinf(ang);
    long long idx = tok * (NH * DR) + h * DR + 2 * j;
    float x1 = x[idx], x2 = x[idx + 1];
    x[idx]     = x1 * c - x2 * si;
    x[idx + 1] = x2 * c + x1 * si;
}

// ---------------- pack [C(half) | R(fp32)] -> half (T, NH, 192) ----------------
__global__ void pack_h(const __half* __restrict__ c, const float* __restrict__ rr,
                       __half* __restrict__ cat) {
    long long i = (long long)blockIdx.x * blockDim.x + threadIdx.x;
    const long long total = (long long)Tt * NH * DCAT;
    if (i >= total) return;
    int d = (int)(i % DCAT);
    long long th = i / DCAT;
    int h = (int)(th % NH);
    long long tok = th / NH;
    cat[i] = (d < DH) ? c[tok * (NH * DH) + h * DH + d]
                      : __float2half_rn(rr[tok * (NH * DR) + h * DR + (d - DH)]);
}

// ---------------- V transpose per batch: vv half [n][NH*DH] -> vvT half [NH*DH][n] ----------------
__global__ void transpV_h(const __half* __restrict__ src, __half* __restrict__ dst) {
    __shared__ __half t[32][33];
    long long bo = (long long)blockIdx.z * Mq * (NH * DH);
    int x0 = blockIdx.x * 32, y0 = blockIdx.y * 32;   // x: hd, y: n
    int tx = threadIdx.x, ty0 = threadIdx.y;
    #pragma unroll
    for (int ty = ty0; ty < 32; ty += 8)
        t[ty][tx] = src[bo + (long long)(y0 + ty) * (NH * DH) + x0 + tx];
    __syncthreads();
    #pragma unroll
    for (int ty = ty0; ty < 32; ty += 8)
        dst[bo + (long long)(x0 + ty) * Nq + y0 + tx] = t[tx][ty];
}

// ---------------- h = silu(gate)*up (fp32 in) -> half out ----------------
__global__ void silumul_h(const float* __restrict__ g, const float* __restrict__ u,
                          __half* __restrict__ h) {
    long long i = (long long)blockIdx.x * blockDim.x + threadIdx.x;
    const long long total = (long long)Tt * FFN_;
    if (i >= total) return;
    float x = g[i];
    h[i] = __float2half_rn((x / (1.f + expf(-x))) * u[i]);
}

// ---------------- launch ----------------
extern "C" void kernel_launch(void* const* d_in, const int* in_sizes, int n_in,
                              void* d_out, int out_size) {
    (void)in_sizes; (void)n_in; (void)out_size;
    const float* query  = (const float*)d_in[0];
    const float* keyval = (const float*)d_in[1];
    const float* g_q    = (const float*)d_in[2];
    const float* g_kv   = (const float*)d_in[3];
    const float* g_ffn  = (const float*)d_in[4];
    const float* w_qc   = (const float*)d_in[5];
    const float* w_kc   = (const float*)d_in[6];
    const float* w_qr   = (const float*)d_in[7];
    const float* w_kr   = (const float*)d_in[8];
    const float* w_v    = (const float*)d_in[9];
    const float* w_o    = (const float*)d_in[10];
    const float* w_gate = (const float*)d_in[11];
    const float* w_up   = (const float*)d_in[12];
    const float* w_down = (const float*)d_in[13];
    float* out = (float*)d_out;

    static bool attr_done = false;
    if (!attr_done) {
        cudaFuncSetAttribute(mm_h<false, false, false>, cudaFuncAttributeMaxDynamicSharedMemorySize, SMEM_H);
        cudaFuncSetAttribute(mm_h<false, false, true >, cudaFuncAttributeMaxDynamicSharedMemorySize, SMEM_H);
        cudaFuncSetAttribute(mm_h<false, true,  false>, cudaFuncAttributeMaxDynamicSharedMemorySize, SMEM_H);
        cudaFuncSetAttribute(mm_h<true,  false, true >, cudaFuncAttributeMaxDynamicSharedMemorySize, SMEM_PEX);
        attr_done = true;
    }

    float* S = nullptr;
    cudaGetSymbolAddress((void**)&S, g_scratch);
    __half* qn   = (__half*)(S + O_QN);
    __half* kvn  = (__half*)(S + O_KVN);
    __half* qc   = (__half*)(S + O_QC);
    __half* kc   = (__half*)(S + O_KC);
    float*  qr   = S + O_QR;
    float*  kr   = S + O_KR;
    __half* vv   = (__half*)(S + O_V);
    __half* qcat = (__half*)(S + O_QCAT);
    __half* kcat = (__half*)(S + O_KCAT);
    float*  sc   = S + O_SC;
    __half* att  = (__half*)(S + O_ATT);
    float*  x    = S + O_X;
    __half* xn   = (__half*)(S + O_XN);
    float*  gate = S + O_GATE;
    float*  up   = S + O_UP;
    __half* cwqc = (__half*)(S + O_WQC);
    __half* cwkc = (__half*)(S + O_WKC);
    __half* cwqr = (__half*)(S + O_WQR);
    __half* cwkr = (__half*)(S + O_WKR);
    __half* cwv  = (__half*)(S + O_WV);
    __half* cwo  = (__half*)(S + O_WO);
    __half* cwg  = (__half*)(S + O_WGATE);
    __half* cwu  = (__half*)(S + O_WUP);
    __half* cwd  = (__half*)(S + O_WDOWN);
    float2* stb  = (float2*)(S + O_ST);
    float*  cml2 = S + O_CML2;
    float*  cinv = S + O_CINV;
    __half* vvT  = (__half*)(S + O_VT);
    __half* hbuf = (__half*)(S + O_SC);   // reuse sc region after attn@V for silu output

    // 0. Weights -> half [n][k]
    {
        dim3 blk(32, 8);
        dim3 gDD(Dm / 32, Dm / 32);
        dim3 gDR((NH * DR) / 32, Dm / 32);
        dim3 gDF(FFN_ / 32, Dm / 32);
        dim3 gFD(Dm / 32, FFN_ / 32);
        cvtwT_h<<<gDD, blk>>>(w_qc,   cwqc, Dm, Dm);
        cvtwT_h<<<gDD, blk>>>(w_kc,   cwkc, Dm, Dm);
        cvtwT_h<<<gDR, blk>>>(w_qr,   cwqr, Dm, NH * DR);
        cvtwT_h<<<gDR, blk>>>(w_kr,   cwkr, Dm, NH * DR);
        cvtwT_h<<<gDD, blk>>>(w_v,    cwv,  Dm, Dm);
        cvtwT_h<<<gDD, blk>>>(w_o,    cwo,  NH * DH, Dm);
        cvtwT_h<<<gDF, blk>>>(w_gate, cwg,  Dm, FFN_);
        cvtwT_h<<<gDF, blk>>>(w_up,   cwu,  Dm, FFN_);
        cvtwT_h<<<gFD, blk>>>(w_down, cwd,  FFN_, Dm);
    }

    // 1. RMSNorm -> half
    rmsnorm_h<<<Tt, 256>>>(query,  g_q,  qn);
    rmsnorm_h<<<Tt, 256>>>(keyval, g_kv, kvn);

    // 2. Projections
    {
        dim3 grid(Dm / BN, Tt / BM, 1);
        mm_h<false,false,true ><<<grid, 256, SMEM_H>>>(qn,  cwqc, nullptr, qc, Tt, Dm, Dm, Dm, Dm, Dm, 0,0,0,0,0,0, 1.f, nullptr, nullptr, nullptr);
        mm_h<false,false,true ><<<grid, 256, SMEM_H>>>(kvn, cwkc, nullptr, kc, Tt, Dm, Dm, Dm, Dm, Dm, 0,0,0,0,0,0, 1.f, nullptr, nullptr, nullptr);
        mm_h<false,false,true ><<<grid, 256, SMEM_H>>>(kvn, cwv,  nullptr, vv, Tt, Dm, Dm, Dm, Dm, Dm, 0,0,0,0,0,0, 1.f, nullptr, nullptr, nullptr);
    }
    {
        dim3 grid((NH * DR) / BN, Tt / BM, 1);
        mm_h<false,false,false><<<grid, 256, SMEM_H>>>(qn,  cwqr, nullptr, qr, Tt, NH * DR, Dm, Dm, Dm, NH * DR, 0,0,0,0,0,0, 1.f, nullptr, nullptr, nullptr);
        mm_h<false,false,false><<<grid, 256, SMEM_H>>>(kvn, cwkr, nullptr, kr, Tt, NH * DR, Dm, Dm, Dm, NH * DR, 0,0,0,0,0,0, 1.f, nullptr, nullptr, nullptr);
    }

    // 2b. V transpose
    {
        dim3 blk(32, 8);
        dim3 grid((NH * DH) / 32, Nq / 32, Bq);
        transpV_h<<<grid, blk>>>(vv, vvT);
    }

    // 3. RoPE (fp32)
    {
        long long pairs = (long long)Tt * NH * (DR / 2);
        int blocks = (int)((pairs + 255) / 256);
        rope_k<<<blocks, 256>>>(qr, Mq);
        rope_k<<<blocks, 256>>>(kr, Nq);
    }

    // 4. Pack
    {
        long long tot = (long long)Tt * NH * DCAT;
        int blocks = (int)((tot + 255) / 256);
        pack_h<<<blocks, 256>>>(qc, qr, qcat);
        pack_h<<<blocks, 256>>>(kc, kr, kcat);
    }

    // 5. Scores (fp32 out) + stats
    {
        dim3 grid(Nq / BN, Mq / BM, Bq * NH);
        mm_h<false,true,false><<<grid, 256, SMEM_H>>>(qcat, kcat, nullptr, sc,
            Mq, Nq, DCAT, NH * DCAT, NH * DCAT, Nq,
            (long long)Mq * NH * DCAT, (long long)DCAT,
            (long long)Nq * NH * DCAT, (long long)DCAT,
            (long long)NH * Mq * Nq, (long long)Mq * Nq,
            SCALE_, stb, nullptr, nullptr);
    }

    // 6. Combine
    combine_k<<<(int)(N_ROWS / 256), 256>>>(stb, cml2, cinv);

    // 7. attn @ V (in-register softmax, half out)
    {
        dim3 grid(DH / BN, Mq / BM, Bq * NH);
        mm_h<true,false,true><<<grid, 256, SMEM_PEX>>>(sc, vvT, nullptr, att,
            Mq, DH, Nq, Nq, Nq, NH * DH,
            (long long)NH * Mq * Nq, (long long)Mq * Nq,
            (long long)NH * DH * Nq, (long long)DH * Nq,
            (long long)Mq * NH * DH, (long long)DH,
            1.f, nullptr, cml2, cinv);
    }

    // 8. x = att @ w_o + query (fp32)
    {
        dim3 grid(Dm / BN, Tt / BM, 1);
        mm_h<false,false,false><<<grid, 256, SMEM_H>>>(att, cwo, query, x, Tt, Dm, NH * DH,
                                       NH * DH, NH * DH, Dm, 0,0,0,0,0,0, 1.f, nullptr, nullptr, nullptr);
    }

    // 9. RMSNorm -> xn half
    rmsnorm_h<<<Tt, 256>>>(x, g_ffn, xn);

    // 10. gate / up (fp32 out)
    {
        dim3 grid(FFN_ / BN, Tt / BM, 1);
        mm_h<false,false,false><<<grid, 256, SMEM_H>>>(xn, cwg, nullptr, gate, Tt, FFN_, Dm, Dm, Dm, FFN_, 0,0,0,0,0,0, 1.f, nullptr, nullptr, nullptr);
        mm_h<false,false,false><<<grid, 256, SMEM_H>>>(xn, cwu, nullptr, up,   Tt, FFN_, Dm, Dm, Dm, FFN_, 0,0,0,0,0,0, 1.f, nullptr, nullptr, nullptr);
    }

    // 11. h = silu(gate)*up -> half (into reused sc region)
    {
        long long tot = (long long)Tt * FFN_;
        int blocks = (int)((tot + 255) / 256);
        silumul_h<<<blocks, 256>>>(gate, up, hbuf);
    }

    // 12. out = h @ w_down + x (fp32)
    {
        dim3 grid(Dm / BN, Tt / BM, 1);
        mm_h<false,false,false><<<grid, 256, SMEM_H>>>(hbuf, cwd, x, out, Tt, Dm, FFN_,
                                       FFN_, FFN_, Dm, 0,0,0,0,0,0, 1.f, nullptr, nullptr, nullptr);
    }
}

// round 15
// speedup vs baseline: 4.9709x; 1.0182x over previous
#include <cuda_runtime.h>
#include <cuda_fp16.h>
#include <math.h>
#include <stdint.h>

// Problem constants
#define Bq   2
#define Mq   2048
#define Nq   2048
#define Dm   2048
#define NH   16
#define DH   128
#define DR   64
#define FFN_ 8192
#define Tt   (Bq*Mq)
#define DCAT (DH+DR)          // 192
#define SCALE_ (0.0721687836487032f) // 1/sqrt(192)

// ---------------- scratch (float units; half buffers reuse regions) ----------------
#define O_QN    0LL
#define O_KVN   (O_QN   + (long long)Tt*Dm)
#define O_QC    (O_KVN  + (long long)Tt*Dm)
#define O_KC    (O_QC   + (long long)Tt*NH*DH)
#define O_QR    (O_KC   + (long long)Tt*NH*DH)
#define O_KR    (O_QR   + (long long)Tt*NH*DR)
#define O_V     (O_KR   + (long long)Tt*NH*DR)
#define O_QCAT  (O_V    + (long long)Tt*NH*DH)
#define O_KCAT  (O_QCAT + (long long)Tt*NH*DCAT)
#define O_SC    (O_KCAT + (long long)Tt*NH*DCAT)
#define O_ATT   (O_SC   + (long long)Bq*NH*Mq*Nq)
#define O_X     (O_ATT  + (long long)Tt*NH*DH)
#define O_XN    (O_X    + (long long)Tt*Dm)
#define O_GATE  (O_XN   + (long long)Tt*Dm)
#define O_UP    (O_GATE + (long long)Tt*FFN_)
#define SZ_DD   ((long long)Dm*Dm)
#define SZ_DR2  ((long long)Dm*NH*DR)
#define SZ_DF   ((long long)Dm*FFN_)
#define O_WQC   (O_UP   + (long long)Tt*FFN_)
#define O_WKC   (O_WQC  + SZ_DD)
#define O_WQR   (O_WKC  + SZ_DD)
#define O_WKR   (O_WQR  + SZ_DR2)
#define O_WV    (O_WKR  + SZ_DR2)
#define O_WO    (O_WV   + SZ_DD)
#define O_WGATE (O_WO   + SZ_DD)
#define O_WUP   (O_WGATE+ SZ_DF)
#define O_WDOWN (O_WUP  + SZ_DF)
#define N_ROWS  ((long long)Bq*NH*Mq)
#define O_ST    (O_WDOWN+ SZ_DF)          // float2[N_ROWS*16]
#define O_CTILE (O_ST   + N_ROWS*16*2)    // float [N_ROWS*16]
#define O_CINV  (O_CTILE+ N_ROWS*16)
#define O_VT    (O_CINV + N_ROWS)
#define O_TOTAL (O_VT   + (long long)Tt*NH*DH)

__device__ float g_scratch[O_TOTAL];

// ---------------- weight fp16 round + transpose: src[K][N] fp32 -> dst[N][K] half ----------------
__global__ void cvtwT_h(const float* __restrict__ src, __half* __restrict__ dst,
                        int K, int N) {
    __shared__ float t[32][33];
    int n0 = blockIdx.x * 32, k0 = blockIdx.y * 32;
    int tx = threadIdx.x, ty0 = threadIdx.y;
    #pragma unroll
    for (int ty = ty0; ty < 32; ty += 8)
        t[ty][tx] = src[(long long)(k0 + ty) * N + n0 + tx];
    __syncthreads();
    #pragma unroll
    for (int ty = ty0; ty < 32; ty += 8)
        dst[(long long)(n0 + ty) * K + k0 + tx] = __float2half_rn(t[tx][ty]);
}

// ---------------- RMSNorm -> half ----------------
__global__ void rmsnorm_h(const float* __restrict__ x, const float* __restrict__ g,
                          __half* __restrict__ y) {
    const int D = Dm;
    long long row = blockIdx.x;
    const float* xr = x + row * D;
    __half* yr = y + row * D;
    float s = 0.f;
    for (int i = threadIdx.x; i < D; i += blockDim.x) { float v = xr[i]; s += v * v; }
    #pragma unroll
    for (int o = 16; o; o >>= 1) s += __shfl_xor_sync(0xffffffffu, s, o);
    __shared__ float sh[8];
    if ((threadIdx.x & 31) == 0) sh[threadIdx.x >> 5] = s;
    __syncthreads();
    float tot = 0.f;
    #pragma unroll
    for (int i = 0; i < 8; i++) tot += sh[i];
    float n = rsqrtf(tot / (float)D + 1e-6f);
    for (int i = threadIdx.x; i < D; i += blockDim.x)
        yr[i] = __float2half_rn(xr[i] * n * g[i]);
}

// ---------------- ldmatrix ----------------
__device__ __forceinline__ void ldsm_x4(unsigned& r0, unsigned& r1, unsigned& r2, unsigned& r3,
                                        const __half* p) {
    unsigned a = (unsigned)__cvta_generic_to_shared(p);
    asm volatile("ldmatrix.sync.aligned.m8n8.x4.shared.b16 {%0,%1,%2,%3}, [%4];"
                 : "=r"(r0), "=r"(r1), "=r"(r2), "=r"(r3) : "r"(a));
}

// ---------------- fp16 tensor-core GEMM, 4-stage cp.async ----------------
// C[M,N] = alpha * A[M,K](half) @ B[N,K]^T(half) (+R fp32 when !HOUT)
// PEX : A = half P_tile values; fragments *= ctile[row][ktile/4]; epilogue *= cinv[row].
// SST : epilogue computes per-(row,128-col-tile) (max, sum-exp) stats and writes
//       C = half(exp(v - M_tile)) instead of the normal write. Requires HOUT.
// HOUT: C half (no residual); else C fp32 with optional residual R.
#define BM 128
#define BN 128
#define BKH 32
#define PH  40          // half-tile row pitch (halves)
#define NST 4
#define ABYTES (BM * PH * 2)
#define BBYTES (BN * PH * 2)
#define SMEM_H (NST * (ABYTES + BBYTES))   // 81920

template<bool PEX, bool SST, bool HOUT>
__global__ void __launch_bounds__(256, 2) mm_h(
    const __half* __restrict__ A, const __half* __restrict__ B,
    const float* __restrict__ R, void* __restrict__ Cv,
    int M, int N, int K, int lda, int ldb, int ldc,
    long long aB, long long aH, long long bB, long long bH,
    long long cB, long long cH, float alpha,
    float2* __restrict__ stats, const float* __restrict__ ctile,
    const float* __restrict__ cinv)
{
    int z = blockIdx.z, bb = z >> 4, hh = z & 15;
    A += bb * aB + hh * aH;
    B += bb * bB + hh * bH;
    float*  Cf = (float*)Cv + bb * cB + hh * cH;
    __half* Ch = (__half*)Cv + bb * cB + hh * cH;
    if (R) R += bb * cB + hh * cH;

    extern __shared__ __align__(16) char smraw[];
    char* AsBase = smraw;
    char* BsBase = smraw + NST * ABYTES;

    const int tid = threadIdx.x;
    const int row0 = blockIdx.y * BM, col0 = blockIdx.x * BN;

    const int lane = tid & 31, warp = tid >> 5;
    const int g  = lane >> 2, tg = lane & 3;
    const int mb = (warp >> 1) * 32;
    const int nb = (warp & 1) * 64;
    const int lm = lane >> 3, lr = lane & 7;
    const int lrow = (lm & 1) * 8 + lr, lcol = (lm >> 1) * 8;

    __shared__ __half2 csm[PEX ? 2048 : 1];
    __shared__ float   sInv[PEX ? 128 : 1];
    if (PEX) {
        for (int i = tid; i < 2048; i += 256) {
            int r = i >> 4;
            float c = ctile[((long long)z * Mq + row0 + r) * 16 + (i & 15)];
            csm[i] = __floats2half2_rn(c, c);
        }
        if (tid < 128)
            sInv[tid] = cinv[(long long)z * Mq + row0 + tid];
        __syncthreads();
    }

    float acc[2][8][4];
    #pragma unroll
    for (int mi = 0; mi < 2; mi++)
        #pragma unroll
        for (int ni = 0; ni < 8; ni++)
            #pragma unroll
            for (int q = 0; q < 4; q++) acc[mi][ni][q] = 0.f;

    auto copyA = [&](int buf, int kt) {
        __half* dst = (__half*)(AsBase + buf * ABYTES);
        #pragma unroll
        for (int q = tid; q < 512; q += 256) {
            int r = q >> 2, c = q & 3;
            const __half* gp = A + (long long)(row0 + r) * lda + kt + c * 8;
            unsigned s = (unsigned)__cvta_generic_to_shared(&dst[r * PH + c * 8]);
            asm volatile("cp.async.ca.shared.global [%0], [%1], 16;\n" :: "r"(s), "l"(gp));
        }
    };
    auto copyB = [&](int buf, int kt) {
        __half* dst = (__half*)(BsBase + buf * BBYTES);
        #pragma unroll
        for (int q = tid; q < 512; q += 256) {
            int r = q >> 2, c = q & 3;
            const __half* gp = B + (long long)(col0 + r) * ldb + kt + c * 8;
            unsigned s = (unsigned)__cvta_generic_to_shared(&dst[r * PH + c * 8]);
            asm volatile("cp.async.ca.shared.global [%0], [%1], 16;\n" :: "r"(s), "l"(gp));
        }
    };

    const int nt = K / BKH;

    #pragma unroll
    for (int s = 0; s < NST - 1; ++s) {
        copyA(s, s * BKH);
        copyB(s, s * BKH);
        asm volatile("cp.async.commit_group;\n" ::: "memory");
    }

    for (int t = 0; t < nt; ++t) {
        asm volatile("cp.async.wait_group %0;\n" :: "n"(NST - 2) : "memory");
        __syncthreads();

        int nxt = t + NST - 1;
        if (nxt < nt) {
            copyA(nxt % NST, nxt * BKH);
            copyB(nxt % NST, nxt * BKH);
        }
        asm volatile("cp.async.commit_group;\n" ::: "memory");

        const int cur = t % NST;
        const __half* as = (const __half*)(AsBase + cur * ABYTES);
        const __half* bs = (const __half*)(BsBase + cur * BBYTES);

        __half2 chA[2], chB[2];
        if (PEX) {
            int si = t >> 2;   // 128-col stats tile index
            chA[0] = csm[(mb + g) * 16 + si];
            chA[1] = csm[(mb + 16 + g) * 16 + si];
            chB[0] = csm[(mb + 8 + g) * 16 + si];
            chB[1] = csm[(mb + 24 + g) * 16 + si];
        }

        #pragma unroll
        for (int kk = 0; kk < BKH; kk += 16) {
            unsigned a[2][4], b[8][2];
            #pragma unroll
            for (int mi = 0; mi < 2; ++mi) {
                ldsm_x4(a[mi][0], a[mi][1], a[mi][2], a[mi][3],
                        as + (mb + mi * 16 + lrow) * PH + kk + lcol);
                if (PEX) {
                    __half2* ap = (__half2*)a[mi];
                    ap[0] = __hmul2(ap[0], chA[mi]);
                    ap[1] = __hmul2(ap[1], chB[mi]);
                    ap[2] = __hmul2(ap[2], chA[mi]);
                    ap[3] = __hmul2(ap[3], chB[mi]);
                }
            }
            #pragma unroll
            for (int j = 0; j < 4; ++j) {
                unsigned r0, r1, r2, r3;
                ldsm_x4(r0, r1, r2, r3,
                        bs + (nb + j * 16 + lrow) * PH + kk + lcol);
                b[2 * j][0] = r0; b[2 * j][1] = r2;
                b[2 * j + 1][0] = r1; b[2 * j + 1][1] = r3;
            }
            #pragma unroll
            for (int mi = 0; mi < 2; ++mi)
                #pragma unroll
                for (int ni = 0; ni < 8; ++ni)
                    asm volatile(
                        "mma.sync.aligned.m16n8k16.row.col.f32.f16.f16.f32 "
                        "{%0,%1,%2,%3}, {%4,%5,%6,%7}, {%8,%9}, {%0,%1,%2,%3};\n"
                        : "+f"(acc[mi][ni][0]), "+f"(acc[mi][ni][1]),
                          "+f"(acc[mi][ni][2]), "+f"(acc[mi][ni][3])
                        : "r"(a[mi][0]), "r"(a[mi][1]), "r"(a[mi][2]), "r"(a[mi][3]),
                          "r"(b[ni][0]), "r"(b[ni][1]));
        }
    }

    if (!SST) {
        // -------- normal C write --------
        #pragma unroll
        for (int mi = 0; mi < 2; ++mi) {
            float ivA = 1.f, ivB = 1.f;
            if (PEX) {
                ivA = sInv[mb + mi * 16 + g];
                ivB = sInv[mb + mi * 16 + 8 + g];
            }
            #pragma unroll
            for (int ni = 0; ni < 8; ++ni) {
                long long rr = row0 + mb + mi * 16 + g;
                long long cc = col0 + nb + ni * 8 + tg * 2;
                float2 v0 = make_float2(acc[mi][ni][0] * alpha, acc[mi][ni][1] * alpha);
                float2 v1 = make_float2(acc[mi][ni][2] * alpha, acc[mi][ni][3] * alpha);
                if (PEX) { v0.x *= ivA; v0.y *= ivA; v1.x *= ivB; v1.y *= ivB; }
                if (HOUT) {
                    __half2 h0 = __floats2half2_rn(v0.x, v0.y);
                    __half2 h1 = __floats2half2_rn(v1.x, v1.y);
                    *(__half2*)&Ch[rr * ldc + cc] = h0;
                    *(__half2*)&Ch[(rr + 8) * ldc + cc] = h1;
                } else {
                    if (R) {
                        float2 r0 = *(const float2*)&R[rr * ldc + cc];
                        float2 r1 = *(const float2*)&R[(rr + 8) * ldc + cc];
                        v0.x += r0.x; v0.y += r0.y; v1.x += r1.x; v1.y += r1.y;
                    }
                    *(float2*)&Cf[rr * ldc + cc] = v0;
                    *(float2*)&Cf[(rr + 8) * ldc + cc] = v1;
                }
            }
        }
    } else {
        // -------- softmax stats + exp-half C write --------
        __syncthreads();                      // stage smem reusable
        float* st  = (float*)smraw;           // [2][128] max parts
        float* st2 = (float*)smraw + 256;     // [2][128] sum parts
        const int wc = warp & 1;
        // max phase
        #pragma unroll
        for (int mi = 0; mi < 2; ++mi)
            #pragma unroll
            for (int h = 0; h < 2; ++h) {
                float m = -3.4e38f;
                #pragma unroll
                for (int ni = 0; ni < 8; ++ni)
                    m = fmaxf(m, fmaxf(acc[mi][ni][2 * h] * alpha,
                                       acc[mi][ni][2 * h + 1] * alpha));
                #pragma unroll
                for (int o = 1; o <= 2; o <<= 1)
                    m = fmaxf(m, __shfl_xor_sync(0xffffffffu, m, o));
                if (tg == 0) st[wc * 128 + mb + mi * 16 + h * 8 + g] = m;
            }
        __syncthreads();
        float M2[2][2];
        // sum phase
        #pragma unroll
        for (int mi = 0; mi < 2; ++mi)
            #pragma unroll
            for (int h = 0; h < 2; ++h) {
                int lrw = mb + mi * 16 + h * 8 + g;
                M2[mi][h] = fmaxf(st[lrw], st[128 + lrw]);
                float s = 0.f;
                #pragma unroll
                for (int ni = 0; ni < 8; ++ni)
                    s += expf(acc[mi][ni][2 * h] * alpha - M2[mi][h])
                       + expf(acc[mi][ni][2 * h + 1] * alpha - M2[mi][h]);
                #pragma unroll
                for (int o = 1; o <= 2; o <<= 1)
                    s += __shfl_xor_sync(0xffffffffu, s, o);
                if (tg == 0) st2[wc * 128 + mb + mi * 16 + h * 8 + g] = s;
            }
        __syncthreads();
        if (wc == 0 && tg == 0) {
            #pragma unroll
            for (int mi = 0; mi < 2; ++mi)
                #pragma unroll
                for (int h = 0; h < 2; ++h) {
                    int lrw = mb + mi * 16 + h * 8 + g;
                    stats[((long long)z * Mq + row0 + lrw) * 16 + blockIdx.x] =
                        make_float2(M2[mi][h], st2[lrw] + st2[128 + lrw]);
                }
        }
        // C write: half exp(v - M_tile)
        #pragma unroll
        for (int mi = 0; mi < 2; ++mi) {
            #pragma unroll
            for (int ni = 0; ni < 8; ++ni) {
                long long rr = row0 + mb + mi * 16 + g;
                long long cc = col0 + nb + ni * 8 + tg * 2;
                __half2 h0 = __floats2half2_rn(
                    expf(acc[mi][ni][0] * alpha - M2[mi][0]),
                    expf(acc[mi][ni][1] * alpha - M2[mi][0]));
                __half2 h1 = __floats2half2_rn(
                    expf(acc[mi][ni][2] * alpha - M2[mi][1]),
                    expf(acc[mi][ni][3] * alpha - M2[mi][1]));
                *(__half2*)&Ch[rr * ldc + cc] = h0;
                *(__half2*)&Ch[(rr + 8) * ldc + cc] = h1;
            }
        }
    }
}

// ---------------- combine stats -> per-row 1/S and per-(row,tile) correction ----------------
__global__ void combine_k(const float2* __restrict__ st, float* __restrict__ ctile,
                          float* __restrict__ cinv) {
    long long row = (long long)blockIdx.x * 256 + threadIdx.x;
    const float2* p = st + row * 16;
    float2 v[16];
    float M = -3.4e38f;
    #pragma unroll
    for (int i = 0; i < 16; i++) { v[i] = p[i]; M = fmaxf(M, v[i].x); }
    float S = 0.f;
    #pragma unroll
    for (int i = 0; i < 16; i++) {
        float c = expf(v[i].x - M);
        S += v[i].y * c;
        ctile[row * 16 + i] = c;
    }
    cinv[row] = 1.f / S;
}

// ---------------- RoPE (fp32) ----------------
__global__ void rope_k(float* __restrict__ x, int seqlen) {
    long long g = (long long)blockIdx.x * blockDim.x + threadIdx.x;
    const long long total = (long long)Tt * NH * (DR / 2);
    if (g >= total) return;
    int j = (int)(g % (DR / 2));
    long long th = g / (DR / 2);
    int h = (int)(th % NH);
    long long tok = th / NH;
    int s = (int)(tok % seqlen);
    float freq = (float)pow((double)1000000.0, -2.0 * j / (double)DR);
    float ang = (float)s * freq;
    float c = cosf(ang), si = sinf(ang);
    long long idx = tok * (NH * DR) + h * DR + 2 * j;
    float x1 = x[idx], x2 = x[idx + 1];
    x[idx]     = x1 * c - x2 * si;
    x[idx + 1] = x2 * c + x1 * si;
}

// ---------------- pack [C(half) | R(fp32)] -> half (T, NH, 192) ----------------
__global__ void pack_h(const __half* __restrict__ c, const float* __restrict__ rr,
                       __half* __restrict__ cat) {
    long long i = (long long)blockIdx.x * blockDim.x + threadIdx.x;
    const long long total = (long long)Tt * NH * DCAT;
    if (i >= total) return;
    int d = (int)(i % DCAT);
    long long th = i / DCAT;
    int h = (int)(th % NH);
    long long tok = th / NH;
    cat[i] = (d < DH) ? c[tok * (NH * DH) + h * DH + d]
                      : __float2half_rn(rr[tok * (NH * DR) + h * DR + (d - DH)]);
}

// ---------------- V transpose per batch: vv half [n][NH*DH] -> vvT half [NH*DH][n] ----------------
__global__ void transpV_h(const __half* __restrict__ src, __half* __restrict__ dst) {
    __shared__ __half t[32][33];
    long long bo = (long long)blockIdx.z * Mq * (NH * DH);
    int x0 = blockIdx.x * 32, y0 = blockIdx.y * 32;
    int tx = threadIdx.x, ty0 = threadIdx.y;
    #pragma unroll
    for (int ty = ty0; ty < 32; ty += 8)
        t[ty][tx] = src[bo + (long long)(y0 + ty) * (NH * DH) + x0 + tx];
    __syncthreads();
    #pragma unroll
    for (int ty = ty0; ty < 32; ty += 8)
        dst[bo + (long long)(x0 + ty) * Nq + y0 + tx] = t[tx][ty];
}

// ---------------- h = silu(gate)*up, half in / half out (in-place safe) ----------------
__global__ void silumul_h(const __half* __restrict__ g, const __half* __restrict__ u,
                          __half* __restrict__ h) {
    long long i = (long long)blockIdx.x * blockDim.x + threadIdx.x;
    const long long total = (long long)Tt * FFN_;
    if (i >= total) return;
    float x = __half2float(g[i]);
    h[i] = __float2half_rn((x / (1.f + expf(-x))) * __half2float(u[i]));
}

// ---------------- launch ----------------
extern "C" void kernel_launch(void* const* d_in, const int* in_sizes, int n_in,
                              void* d_out, int out_size) {
    (void)in_sizes; (void)n_in; (void)out_size;
    const float* query  = (const float*)d_in[0];
    const float* keyval = (const float*)d_in[1];
    const float* g_q    = (const float*)d_in[2];
    const float* g_kv   = (const float*)d_in[3];
    const float* g_ffn  = (const float*)d_in[4];
    const float* w_qc   = (const float*)d_in[5];
    const float* w_kc   = (const float*)d_in[6];
    const float* w_qr   = (const float*)d_in[7];
    const float* w_kr   = (const float*)d_in[8];
    const float* w_v    = (const float*)d_in[9];
    const float* w_o    = (const float*)d_in[10];
    const float* w_gate = (const float*)d_in[11];
    const float* w_up   = (const float*)d_in[12];
    const float* w_down = (const float*)d_in[13];
    float* out = (float*)d_out;

    static bool attr_done = false;
    if (!attr_done) {
        cudaFuncSetAttribute(mm_h<false, false, false>, cudaFuncAttributeMaxDynamicSharedMemorySize, SMEM_H);
        cudaFuncSetAttribute(mm_h<false, false, true >, cudaFuncAttributeMaxDynamicSharedMemorySize, SMEM_H);
        cudaFuncSetAttribute(mm_h<false, true,  true >, cudaFuncAttributeMaxDynamicSharedMemorySize, SMEM_H);
        cudaFuncSetAttribute(mm_h<true,  false, true >, cudaFuncAttributeMaxDynamicSharedMemorySize, SMEM_H);
        attr_done = true;
    }

    float* S = nullptr;
    cudaGetSymbolAddress((void**)&S, g_scratch);
    __half* qn   = (__half*)(S + O_QN);
    __half* kvn  = (__half*)(S + O_KVN);
    __half* qc   = (__half*)(S + O_QC);
    __half* kc   = (__half*)(S + O_KC);
    float*  qr   = S + O_QR;
    float*  kr   = S + O_KR;
    __half* vv   = (__half*)(S + O_V);
    __half* qcat = (__half*)(S + O_QCAT);
    __half* kcat = (__half*)(S + O_KCAT);
    __half* sch  = (__half*)(S + O_SC);     // half P_tile scores
    __half* att  = (__half*)(S + O_ATT);
    float*  x    = S + O_X;
    __half* xn   = (__half*)(S + O_XN);
    __half* gateh= (__half*)(S + O_GATE);
    __half* uph  = (__half*)(S + O_UP);
    __half* cwqc = (__half*)(S + O_WQC);
    __half* cwkc = (__half*)(S + O_WKC);
    __half* cwqr = (__half*)(S + O_WQR);
    __half* cwkr = (__half*)(S + O_WKR);
    __half* cwv  = (__half*)(S + O_WV);
    __half* cwo  = (__half*)(S + O_WO);
    __half* cwg  = (__half*)(S + O_WGATE);
    __half* cwu  = (__half*)(S + O_WUP);
    __half* cwd  = (__half*)(S + O_WDOWN);
    float2* stb  = (float2*)(S + O_ST);
    float*  ctl  = S + O_CTILE;
    float*  cinv = S + O_CINV;
    __half* vvT  = (__half*)(S + O_VT);

    // 0. Weights -> half [n][k]
    {
        dim3 blk(32, 8);
        dim3 gDD(Dm / 32, Dm / 32);
        dim3 gDR((NH * DR) / 32, Dm / 32);
        dim3 gDF(FFN_ / 32, Dm / 32);
        dim3 gFD(Dm / 32, FFN_ / 32);
        cvtwT_h<<<gDD, blk>>>(w_qc,   cwqc, Dm, Dm);
        cvtwT_h<<<gDD, blk>>>(w_kc,   cwkc, Dm, Dm);
        cvtwT_h<<<gDR, blk>>>(w_qr,   cwqr, Dm, NH * DR);
        cvtwT_h<<<gDR, blk>>>(w_kr,   cwkr, Dm, NH * DR);
        cvtwT_h<<<gDD, blk>>>(w_v,    cwv,  Dm, Dm);
        cvtwT_h<<<gDD, blk>>>(w_o,    cwo,  NH * DH, Dm);
        cvtwT_h<<<gDF, blk>>>(w_gate, cwg,  Dm, FFN_);
        cvtwT_h<<<gDF, blk>>>(w_up,   cwu,  Dm, FFN_);
        cvtwT_h<<<gFD, blk>>>(w_down, cwd,  FFN_, Dm);
    }

    // 1. RMSNorm -> half
    rmsnorm_h<<<Tt, 256>>>(query,  g_q,  qn);
    rmsnorm_h<<<Tt, 256>>>(keyval, g_kv, kvn);

    // 2. Projections
    {
        dim3 grid(Dm / BN, Tt / BM, 1);
        mm_h<false,false,true ><<<grid, 256, SMEM_H>>>(qn,  cwqc, nullptr, qc, Tt, Dm, Dm, Dm, Dm, Dm, 0,0,0,0,0,0, 1.f, nullptr, nullptr, nullptr);
        mm_h<false,false,true ><<<grid, 256, SMEM_H>>>(kvn, cwkc, nullptr, kc, Tt, Dm, Dm, Dm, Dm, Dm, 0,0,0,0,0,0, 1.f, nullptr, nullptr, nullptr);
        mm_h<false,false,true ><<<grid, 256, SMEM_H>>>(kvn, cwv,  nullptr, vv, Tt, Dm, Dm, Dm, Dm, Dm, 0,0,0,0,0,0, 1.f, nullptr, nullptr, nullptr);
    }
    {
        dim3 grid((NH * DR) / BN, Tt / BM, 1);
        mm_h<false,false,false><<<grid, 256, SMEM_H>>>(qn,  cwqr, nullptr, qr, Tt, NH * DR, Dm, Dm, Dm, NH * DR, 0,0,0,0,0,0, 1.f, nullptr, nullptr, nullptr);
        mm_h<false,false,false><<<grid, 256, SMEM_H>>>(kvn, cwkr, nullptr, kr, Tt, NH * DR, Dm, Dm, Dm, NH * DR, 0,0,0,0,0,0, 1.f, nullptr, nullptr, nullptr);
    }

    // 2b. V transpose
    {
        dim3 blk(32, 8);
        dim3 grid((NH * DH) / 32, Nq / 32, Bq);
        transpV_h<<<grid, blk>>>(vv, vvT);
    }

    // 3. RoPE (fp32)
    {
        long long pairs = (long long)Tt * NH * (DR / 2);
        int blocks = (int)((pairs + 255) / 256);
        rope_k<<<blocks, 256>>>(qr, Mq);
        rope_k<<<blocks, 256>>>(kr, Nq);
    }

    // 4. Pack
    {
        long long tot = (long long)Tt * NH * DCAT;
        int blocks = (int)((tot + 255) / 256);
        pack_h<<<blocks, 256>>>(qc, qr, qcat);
        pack_h<<<blocks, 256>>>(kc, kr, kcat);
    }

    // 5. Scores -> half P_tile + stats
    {
        dim3 grid(Nq / BN, Mq / BM, Bq * NH);
        mm_h<false,true,true><<<grid, 256, SMEM_H>>>(qcat, kcat, nullptr, sch,
            Mq, Nq, DCAT, NH * DCAT, NH * DCAT, Nq,
            (long long)Mq * NH * DCAT, (long long)DCAT,
            (long long)Nq * NH * DCAT, (long long)DCAT,
            (long long)NH * Mq * Nq, (long long)Mq * Nq,
            SCALE_, stb, nullptr, nullptr);
    }

    // 6. Combine -> ctile, cinv
    combine_k<<<(int)(N_ROWS / 256), 256>>>(stb, ctl, cinv);

    // 7. attn @ V (A = half P_tile, fragments *= ctile, epilogue *= 1/S)
    {
        dim3 grid(DH / BN, Mq / BM, Bq * NH);
        mm_h<true,false,true><<<grid, 256, SMEM_H>>>(sch, vvT, nullptr, att,
            Mq, DH, Nq, Nq, Nq, NH * DH,
            (long long)NH * Mq * Nq, (long long)Mq * Nq,
            (long long)NH * DH * Nq, (long long)DH * Nq,
            (long long)Mq * NH * DH, (long long)DH,
            1.f, nullptr, ctl, cinv);
    }

    // 8. x = att @ w_o + query (fp32)
    {
        dim3 grid(Dm / BN, Tt / BM, 1);
        mm_h<false,false,false><<<grid, 256, SMEM_H>>>(att, cwo, query, x, Tt, Dm, NH * DH,
                                       NH * DH, NH * DH, Dm, 0,0,0,0,0,0, 1.f, nullptr, nullptr, nullptr);
    }

    // 9. RMSNorm -> xn half
    rmsnorm_h<<<Tt, 256>>>(x, g_ffn, xn);

    // 10. gate / up (half out)
    {
        dim3 grid(FFN_ / BN, Tt / BM, 1);
        mm_h<false,false,true><<<grid, 256, SMEM_H>>>(xn, cwg, nullptr, gateh, Tt, FFN_, Dm, Dm, Dm, FFN_, 0,0,0,0,0,0, 1.f, nullptr, nullptr, nullptr);
        mm_h<false,false,true><<<grid, 256, SMEM_H>>>(xn, cwu, nullptr, uph,   Tt, FFN_, Dm, Dm, Dm, FFN_, 0,0,0,0,0,0, 1.f, nullptr, nullptr, nullptr);
    }

    // 11. h = silu(gate)*up (half, in-place on gate)
    {
        long long tot = (long long)Tt * FFN_;
        int blocks = (int)((tot + 255) / 256);
        silumul_h<<<blocks, 256>>>(gateh, uph, gateh);
    }

    // 12. out = h @ w_down + x (fp32)
    {
        dim3 grid(Dm / BN, Tt / BM, 1);
        mm_h<false,false,false><<<grid, 256, SMEM_H>>>(gateh, cwd, x, out, Tt, Dm, FFN_,
                                       FFN_, FFN_, Dm, 0,0,0,0,0,0, 1.f, nullptr, nullptr, nullptr);
    }
}

// round 16
// speedup vs baseline: 5.5312x; 1.1127x over previous
#include <cuda_runtime.h>
#include <cuda_fp16.h>
#include <math.h>
#include <stdint.h>

// Problem constants
#define Bq   2
#define Mq   2048
#define Nq   2048
#define Dm   2048
#define NH   16
#define DH   128
#define DR   64
#define FFN_ 8192
#define Tt   (Bq*Mq)
#define DCAT (DH+DR)          // 192
#define SCALE_ (0.0721687836487032f) // 1/sqrt(192)

// ---------------- scratch (float units; half buffers reuse regions) ----------------
#define O_QN    0LL
#define O_KVN   (O_QN   + (long long)Tt*Dm)
#define O_QC    (O_KVN  + (long long)Tt*Dm)
#define O_KC    (O_QC   + (long long)Tt*NH*DH)
#define O_QR    (O_KC   + (long long)Tt*NH*DH)
#define O_KR    (O_QR   + (long long)Tt*NH*DR)
#define O_V     (O_KR   + (long long)Tt*NH*DR)
#define O_QCAT  (O_V    + (long long)Tt*NH*DH)
#define O_KCAT  (O_QCAT + (long long)Tt*NH*DCAT)
#define O_SC    (O_KCAT + (long long)Tt*NH*DCAT)
#define O_ATT   (O_SC   + (long long)Bq*NH*Mq*Nq)
#define O_X     (O_ATT  + (long long)Tt*NH*DH)
#define O_XN    (O_X    + (long long)Tt*Dm)
#define O_GATE  (O_XN   + (long long)Tt*Dm)     // gu combined half [Tt][2*FFN_] spans GATE+UP
#define O_UP    (O_GATE + (long long)Tt*FFN_)
#define SZ_DD   ((long long)Dm*Dm)
#define SZ_DR2  ((long long)Dm*NH*DR)
#define SZ_DF   ((long long)Dm*FFN_)
#define O_WQC   (O_UP   + (long long)Tt*FFN_)
#define O_WKC   (O_WQC  + SZ_DD)
#define O_WQR   (O_WKC  + SZ_DD)
#define O_WKR   (O_WQR  + SZ_DR2)
#define O_WV    (O_WKR  + SZ_DR2)
#define O_WO    (O_WV   + SZ_DD)
#define O_WGU   (O_WO   + SZ_DD)                // [Dm][2*FFN_] half interleaved (gate|up)
#define O_WDOWN (O_WGU  + 2*SZ_DF)
#define N_ROWS  ((long long)Bq*NH*Mq)
#define O_ST    (O_WDOWN+ SZ_DF)
#define O_CTILE (O_ST   + N_ROWS*16*2)
#define O_CINV  (O_CTILE+ N_ROWS*16)
#define O_TOTAL (O_CINV + N_ROWS)

__device__ float g_scratch[O_TOTAL];

// ---------------- streaming fp32 -> fp16 convert (no transpose) ----------------
__global__ void cvt_lin(const float4* __restrict__ src, __half2* __restrict__ dst,
                        long long n4) {
    long long i = (long long)blockIdx.x * blockDim.x + threadIdx.x;
    long long stride = (long long)gridDim.x * blockDim.x;
    for (; i < n4; i += stride) {
        float4 v = src[i];
        dst[2 * i]     = __floats2half2_rn(v.x, v.y);
        dst[2 * i + 1] = __floats2half2_rn(v.z, v.w);
    }
}

// convert [K][8192] fp32 into interleaved dst [K][16384] half at column offset
__global__ void cvt_off8k(const float4* __restrict__ src, __half* __restrict__ dst,
                          long long n4, int coloff) {
    long long i = (long long)blockIdx.x * blockDim.x + threadIdx.x;
    long long stride = (long long)gridDim.x * blockDim.x;
    for (; i < n4; i += stride) {
        float4 v = src[i];
        long long e = i * 4;
        long long k = e >> 13;          // / 8192
        int n = (int)(e & 8191);
        __half2* d = (__half2*)(dst + k * 16384 + coloff + n);
        d[0] = __floats2half2_rn(v.x, v.y);
        d[1] = __floats2half2_rn(v.z, v.w);
    }
}

// ---------------- RMSNorm -> half ----------------
__global__ void rmsnorm_h(const float* __restrict__ x, const float* __restrict__ g,
                          __half* __restrict__ y) {
    const int D = Dm;
    long long row = blockIdx.x;
    const float* xr = x + row * D;
    __half* yr = y + row * D;
    float s = 0.f;
    for (int i = threadIdx.x; i < D; i += blockDim.x) { float v = xr[i]; s += v * v; }
    #pragma unroll
    for (int o = 16; o; o >>= 1) s += __shfl_xor_sync(0xffffffffu, s, o);
    __shared__ float sh[8];
    if ((threadIdx.x & 31) == 0) sh[threadIdx.x >> 5] = s;
    __syncthreads();
    float tot = 0.f;
    #pragma unroll
    for (int i = 0; i < 8; i++) tot += sh[i];
    float n = rsqrtf(tot / (float)D + 1e-6f);
    for (int i = threadIdx.x; i < D; i += blockDim.x)
        yr[i] = __float2half_rn(xr[i] * n * g[i]);
}

// ---------------- ldmatrix ----------------
__device__ __forceinline__ void ldsm_x4(unsigned& r0, unsigned& r1, unsigned& r2, unsigned& r3,
                                        const __half* p) {
    unsigned a = (unsigned)__cvta_generic_to_shared(p);
    asm volatile("ldmatrix.sync.aligned.m8n8.x4.shared.b16 {%0,%1,%2,%3}, [%4];"
                 : "=r"(r0), "=r"(r1), "=r"(r2), "=r"(r3) : "r"(a));
}
__device__ __forceinline__ void ldsm_x4t(unsigned& r0, unsigned& r1, unsigned& r2, unsigned& r3,
                                         const __half* p) {
    unsigned a = (unsigned)__cvta_generic_to_shared(p);
    asm volatile("ldmatrix.sync.aligned.m8n8.x4.trans.shared.b16 {%0,%1,%2,%3}, [%4];"
                 : "=r"(r0), "=r"(r1), "=r"(r2), "=r"(r3) : "r"(a));
}

// ---------------- fp16 tensor-core GEMM, 4-stage cp.async ----------------
// C[M,N] = alpha * A[M,K](half) @ B (+R fp32 when !HOUT)
// BT=true : B row-major [K,N] (weights' native layout); fragments via ldmatrix.trans.
// BT=false: B row-major [N,K]; fragments via ldmatrix (scores GEMM).
// PEX : A = half P_tile; fragments *= ctile[row][t/4]; epilogue *= cinv[row].
// SST : epilogue emits per-(row,128-col-tile) (max,sum-exp) stats; C = half exp(v-Mtile).
// HOUT: C half (no residual); else fp32 + optional residual.
#define BM 128
#define BN 128
#define BKH 32
#define PH  40          // [n][k] & A tile pitch (halves)
#define PBT 136         // [k][n] B tile pitch (halves)
#define NST 4
#define ABYTES (BM * PH * 2)
#define SMEM_BT (NST * (ABYTES + BKH * PBT * 2))   // 75776
#define SMEM_BF (NST * (ABYTES + BN * PH * 2))     // 81920

template<bool BT, bool PEX, bool SST, bool HOUT>
__global__ void __launch_bounds__(256, 2) mm_h(
    const __half* __restrict__ A, const __half* __restrict__ B,
    const float* __restrict__ R, void* __restrict__ Cv,
    int M, int N, int K, int lda, int ldb, int ldc,
    long long aB, long long aH, long long bB, long long bH,
    long long cB, long long cH, float alpha,
    float2* __restrict__ stats, const float* __restrict__ ctile,
    const float* __restrict__ cinv)
{
    constexpr int BBYTES = BT ? (BKH * PBT * 2) : (BN * PH * 2);

    int z = blockIdx.z, bb = z >> 4, hh = z & 15;
    A += bb * aB + hh * aH;
    B += bb * bB + hh * bH;
    float*  Cf = (float*)Cv + bb * cB + hh * cH;
    __half* Ch = (__half*)Cv + bb * cB + hh * cH;
    if (R) R += bb * cB + hh * cH;

    extern __shared__ __align__(16) char smraw[];
    char* AsBase = smraw;
    char* BsBase = smraw + NST * ABYTES;

    const int tid = threadIdx.x;
    const int row0 = blockIdx.y * BM, col0 = blockIdx.x * BN;

    const int lane = tid & 31, warp = tid >> 5;
    const int g  = lane >> 2, tg = lane & 3;
    const int mb = (warp >> 1) * 32;
    const int nb = (warp & 1) * 64;
    const int lm = lane >> 3, lr = lane & 7;
    const int lrow = (lm & 1) * 8 + lr, lcol = (lm >> 1) * 8;

    __shared__ __half2 csm[PEX ? 2048 : 1];
    __shared__ float   sInv[PEX ? 128 : 1];
    if (PEX) {
        for (int i = tid; i < 2048; i += 256) {
            int r = i >> 4;
            float c = ctile[((long long)z * Mq + row0 + r) * 16 + (i & 15)];
            csm[i] = __floats2half2_rn(c, c);
        }
        if (tid < 128)
            sInv[tid] = cinv[(long long)z * Mq + row0 + tid];
        __syncthreads();
    }

    float acc[2][8][4];
    #pragma unroll
    for (int mi = 0; mi < 2; mi++)
        #pragma unroll
        for (int ni = 0; ni < 8; ni++)
            #pragma unroll
            for (int q = 0; q < 4; q++) acc[mi][ni][q] = 0.f;

    auto copyA = [&](int buf, int kt) {
        __half* dst = (__half*)(AsBase + buf * ABYTES);
        #pragma unroll
        for (int q = tid; q < 512; q += 256) {
            int r = q >> 2, c = q & 3;
            const __half* gp = A + (long long)(row0 + r) * lda + kt + c * 8;
            unsigned s = (unsigned)__cvta_generic_to_shared(&dst[r * PH + c * 8]);
            asm volatile("cp.async.ca.shared.global [%0], [%1], 16;\n" :: "r"(s), "l"(gp));
        }
    };
    auto copyB = [&](int buf, int kt) {
        __half* dst = (__half*)(BsBase + buf * BBYTES);
        if (BT) {
            // B [k][n]: 32 k-rows x 128 n-halves
            #pragma unroll
            for (int q = tid; q < 512; q += 256) {
                int r = q >> 4, c = q & 15;
                const __half* gp = B + (long long)(kt + r) * ldb + col0 + c * 8;
                unsigned s = (unsigned)__cvta_generic_to_shared(&dst[r * PBT + c * 8]);
                asm volatile("cp.async.ca.shared.global [%0], [%1], 16;\n" :: "r"(s), "l"(gp));
            }
        } else {
            // B [n][k]: 128 n-rows x 32 k-halves
            #pragma unroll
            for (int q = tid; q < 512; q += 256) {
                int r = q >> 2, c = q & 3;
                const __half* gp = B + (long long)(col0 + r) * ldb + kt + c * 8;
                unsigned s = (unsigned)__cvta_generic_to_shared(&dst[r * PH + c * 8]);
                asm volatile("cp.async.ca.shared.global [%0], [%1], 16;\n" :: "r"(s), "l"(gp));
            }
        }
    };

    const int nt = K / BKH;

    #pragma unroll
    for (int s = 0; s < NST - 1; ++s) {
        copyA(s, s * BKH);
        copyB(s, s * BKH);
        asm volatile("cp.async.commit_group;\n" ::: "memory");
    }

    for (int t = 0; t < nt; ++t) {
        asm volatile("cp.async.wait_group %0;\n" :: "n"(NST - 2) : "memory");
        __syncthreads();

        int nxt = t + NST - 1;
        if (nxt < nt) {
            copyA(nxt % NST, nxt * BKH);
            copyB(nxt % NST, nxt * BKH);
        }
        asm volatile("cp.async.commit_group;\n" ::: "memory");

        const int cur = t % NST;
        const __half* as = (const __half*)(AsBase + cur * ABYTES);
        const __half* bs = (const __half*)(BsBase + cur * BBYTES);

        __half2 chA[2], chB[2];
        if (PEX) {
            int si = t >> 2;
            chA[0] = csm[(mb + g) * 16 + si];
            chA[1] = csm[(mb + 16 + g) * 16 + si];
            chB[0] = csm[(mb + 8 + g) * 16 + si];
            chB[1] = csm[(mb + 24 + g) * 16 + si];
        }

        #pragma unroll
        for (int kk = 0; kk < BKH; kk += 16) {
            unsigned a[2][4], b[8][2];
            #pragma unroll
            for (int mi = 0; mi < 2; ++mi) {
                ldsm_x4(a[mi][0], a[mi][1], a[mi][2], a[mi][3],
                        as + (mb + mi * 16 + lrow) * PH + kk + lcol);
                if (PEX) {
                    __half2* ap = (__half2*)a[mi];
                    ap[0] = __hmul2(ap[0], chA[mi]);
                    ap[1] = __hmul2(ap[1], chB[mi]);
                    ap[2] = __hmul2(ap[2], chA[mi]);
                    ap[3] = __hmul2(ap[3], chB[mi]);
                }
            }
            if (BT) {
                // [k][n] tile + ldmatrix.trans:
                // lanes: lm&1 -> k-halfblock, lm>>1 -> n-halfblock within 16-col group
                #pragma unroll
                for (int j = 0; j < 4; ++j) {
                    unsigned r0, r1, r2, r3;
                    ldsm_x4t(r0, r1, r2, r3,
                             bs + (kk + (lm & 1) * 8 + lr) * PBT
                                + nb + j * 16 + (lm >> 1) * 8);
                    b[2 * j][0] = r0; b[2 * j][1] = r1;
                    b[2 * j + 1][0] = r2; b[2 * j + 1][1] = r3;
                }
            } else {
                #pragma unroll
                for (int j = 0; j < 4; ++j) {
                    unsigned r0, r1, r2, r3;
                    ldsm_x4(r0, r1, r2, r3,
                            bs + (nb + j * 16 + lrow) * PH + kk + lcol);
                    b[2 * j][0] = r0; b[2 * j][1] = r2;
                    b[2 * j + 1][0] = r1; b[2 * j + 1][1] = r3;
                }
            }
            #pragma unroll
            for (int mi = 0; mi < 2; ++mi)
                #pragma unroll
                for (int ni = 0; ni < 8; ++ni)
                    asm volatile(
                        "mma.sync.aligned.m16n8k16.row.col.f32.f16.f16.f32 "
                        "{%0,%1,%2,%3}, {%4,%5,%6,%7}, {%8,%9}, {%0,%1,%2,%3};\n"
                        : "+f"(acc[mi][ni][0]), "+f"(acc[mi][ni][1]),
                          "+f"(acc[mi][ni][2]), "+f"(acc[mi][ni][3])
                        : "r"(a[mi][0]), "r"(a[mi][1]), "r"(a[mi][2]), "r"(a[mi][3]),
                          "r"(b[ni][0]), "r"(b[ni][1]));
        }
    }

    if (!SST) {
        #pragma unroll
        for (int mi = 0; mi < 2; ++mi) {
            float ivA = 1.f, ivB = 1.f;
            if (PEX) {
                ivA = sInv[mb + mi * 16 + g];
                ivB = sInv[mb + mi * 16 + 8 + g];
            }
            #pragma unroll
            for (int ni = 0; ni < 8; ++ni) {
                long long rr = row0 + mb + mi * 16 + g;
                long long cc = col0 + nb + ni * 8 + tg * 2;
                float2 v0 = make_float2(acc[mi][ni][0] * alpha, acc[mi][ni][1] * alpha);
                float2 v1 = make_float2(acc[mi][ni][2] * alpha, acc[mi][ni][3] * alpha);
                if (PEX) { v0.x *= ivA; v0.y *= ivA; v1.x *= ivB; v1.y *= ivB; }
                if (HOUT) {
                    *(__half2*)&Ch[rr * ldc + cc] = __floats2half2_rn(v0.x, v0.y);
                    *(__half2*)&Ch[(rr + 8) * ldc + cc] = __floats2half2_rn(v1.x, v1.y);
                } else {
                    if (R) {
                        float2 r0 = *(const float2*)&R[rr * ldc + cc];
                        float2 r1 = *(const float2*)&R[(rr + 8) * ldc + cc];
                        v0.x += r0.x; v0.y += r0.y; v1.x += r1.x; v1.y += r1.y;
                    }
                    *(float2*)&Cf[rr * ldc + cc] = v0;
                    *(float2*)&Cf[(rr + 8) * ldc + cc] = v1;
                }
            }
        }
    } else {
        // softmax stats + exp-half write
        __syncthreads();
        float* st  = (float*)smraw;
        float* st2 = (float*)smraw + 256;
        const int wc = warp & 1;
        #pragma unroll
        for (int mi = 0; mi < 2; ++mi)
            #pragma unroll
            for (int h = 0; h < 2; ++h) {
                float m = -3.4e38f;
                #pragma unroll
                for (int ni = 0; ni < 8; ++ni)
                    m = fmaxf(m, fmaxf(acc[mi][ni][2 * h] * alpha,
                                       acc[mi][ni][2 * h + 1] * alpha));
                #pragma unroll
                for (int o = 1; o <= 2; o <<= 1)
                    m = fmaxf(m, __shfl_xor_sync(0xffffffffu, m, o));
                if (tg == 0) st[wc * 128 + mb + mi * 16 + h * 8 + g] = m;
            }
        __syncthreads();
        float M2[2][2];
        #pragma unroll
        for (int mi = 0; mi < 2; ++mi)
            #pragma unroll
            for (int h = 0; h < 2; ++h) {
                int lrw = mb + mi * 16 + h * 8 + g;
                M2[mi][h] = fmaxf(st[lrw], st[128 + lrw]);
                float s = 0.f;
                #pragma unroll
                for (int ni = 0; ni < 8; ++ni)
                    s += expf(acc[mi][ni][2 * h] * alpha - M2[mi][h])
                       + expf(acc[mi][ni][2 * h + 1] * alpha - M2[mi][h]);
                #pragma unroll
                for (int o = 1; o <= 2; o <<= 1)
                    s += __shfl_xor_sync(0xffffffffu, s, o);
                if (tg == 0) st2[wc * 128 + mb + mi * 16 + h * 8 + g] = s;
            }
        __syncthreads();
        if (wc == 0 && tg == 0) {
            #pragma unroll
            for (int mi = 0; mi < 2; ++mi)
                #pragma unroll
                for (int h = 0; h < 2; ++h) {
                    int lrw = mb + mi * 16 + h * 8 + g;
                    stats[((long long)z * Mq + row0 + lrw) * 16 + blockIdx.x] =
                        make_float2(M2[mi][h], st2[lrw] + st2[128 + lrw]);
                }
        }
        #pragma unroll
        for (int mi = 0; mi < 2; ++mi) {
            #pragma unroll
            for (int ni = 0; ni < 8; ++ni) {
                long long rr = row0 + mb + mi * 16 + g;
                long long cc = col0 + nb + ni * 8 + tg * 2;
                *(__half2*)&Ch[rr * ldc + cc] = __floats2half2_rn(
                    expf(acc[mi][ni][0] * alpha - M2[mi][0]),
                    expf(acc[mi][ni][1] * alpha - M2[mi][0]));
                *(__half2*)&Ch[(rr + 8) * ldc + cc] = __floats2half2_rn(
                    expf(acc[mi][ni][2] * alpha - M2[mi][1]),
                    expf(acc[mi][ni][3] * alpha - M2[mi][1]));
            }
        }
    }
}

// ---------------- combine stats ----------------
__global__ void combine_k(const float2* __restrict__ st, float* __restrict__ ctile,
                          float* __restrict__ cinv) {
    long long row = (long long)blockIdx.x * 256 + threadIdx.x;
    const float2* p = st + row * 16;
    float2 v[16];
    float M = -3.4e38f;
    #pragma unroll
    for (int i = 0; i < 16; i++) { v[i] = p[i]; M = fmaxf(M, v[i].x); }
    float S = 0.f;
    #pragma unroll
    for (int i = 0; i < 16; i++) {
        float c = expf(v[i].x - M);
        S += v[i].y * c;
        ctile[row * 16 + i] = c;
    }
    cinv[row] = 1.f / S;
}

// ---------------- RoPE (fp32) ----------------
__global__ void rope_k(float* __restrict__ x, int seqlen) {
    long long g = (long long)blockIdx.x * blockDim.x + threadIdx.x;
    const long long total = (long long)Tt * NH * (DR / 2);
    if (g >= total) return;
    int j = (int)(g % (DR / 2));
    long long th = g / (DR / 2);
    int h = (int)(th % NH);
    long long tok = th / NH;
    int s = (int)(tok % seqlen);
    float freq = (float)pow((double)1000000.0, -2.0 * j / (double)DR);
    float ang = (float)s * freq;
    float c = cosf(ang), si = sinf(ang);
    long long idx = tok * (NH * DR) + h * DR + 2 * j;
    float x1 = x[idx], x2 = x[idx + 1];
    x[idx]     = x1 * c - x2 * si;
    x[idx + 1] = x2 * c + x1 * si;
}

// ---------------- pack [C(half) | R(fp32)] -> half (T, NH, 192) ----------------
__global__ void pack_h(const __half* __restrict__ c, const float* __restrict__ rr,
                       __half* __restrict__ cat) {
    long long i = (long long)blockIdx.x * blockDim.x + threadIdx.x;
    const long long total = (long long)Tt * NH * DCAT;
    if (i >= total) return;
    int d = (int)(i % DCAT);
    long long th = i / DCAT;
    int h = (int)(th % NH);
    long long tok = th / NH;
    cat[i] = (d < DH) ? c[tok * (NH * DH) + h * DH + d]
                      : __float2half_rn(rr[tok * (NH * DR) + h * DR + (d - DH)]);
}

// ---------------- h = silu(gate)*up from interleaved gu [t][16384] ----------------
__global__ void silumul_gu(const __half* __restrict__ gu, __half* __restrict__ h) {
    long long i = (long long)blockIdx.x * blockDim.x + threadIdx.x;
    const long long total = (long long)Tt * FFN_;
    if (i >= total) return;
    long long t = i >> 13;
    int f = (int)(i & 8191);
    float x = __half2float(gu[t * 16384 + f]);
    float u = __half2float(gu[t * 16384 + 8192 + f]);
    h[i] = __float2half_rn((x / (1.f + expf(-x))) * u);
}

// ---------------- launch ----------------
extern "C" void kernel_launch(void* const* d_in, const int* in_sizes, int n_in,
                              void* d_out, int out_size) {
    (void)in_sizes; (void)n_in; (void)out_size;
    const float* query  = (const float*)d_in[0];
    const float* keyval = (const float*)d_in[1];
    const float* g_q    = (const float*)d_in[2];
    const float* g_kv   = (const float*)d_in[3];
    const float* g_ffn  = (const float*)d_in[4];
    const float* w_qc   = (const float*)d_in[5];
    const float* w_kc   = (const float*)d_in[6];
    const float* w_qr   = (const float*)d_in[7];
    const float* w_kr   = (const float*)d_in[8];
    const float* w_v    = (const float*)d_in[9];
    const float* w_o    = (const float*)d_in[10];
    const float* w_gate = (const float*)d_in[11];
    const float* w_up   = (const float*)d_in[12];
    const float* w_down = (const float*)d_in[13];
    float* out = (float*)d_out;

    static bool attr_done = false;
    if (!attr_done) {
        cudaFuncSetAttribute(mm_h<true,  false, false, true >, cudaFuncAttributeMaxDynamicSharedMemorySize, SMEM_BT);
        cudaFuncSetAttribute(mm_h<true,  false, false, false>, cudaFuncAttributeMaxDynamicSharedMemorySize, SMEM_BT);
        cudaFuncSetAttribute(mm_h<true,  true,  false, true >, cudaFuncAttributeMaxDynamicSharedMemorySize, SMEM_BT);
        cudaFuncSetAttribute(mm_h<false, false, true,  true >, cudaFuncAttributeMaxDynamicSharedMemorySize, SMEM_BF);
        attr_done = true;
    }

    float* S = nullptr;
    cudaGetSymbolAddress((void**)&S, g_scratch);
    __half* qn   = (__half*)(S + O_QN);
    __half* kvn  = (__half*)(S + O_KVN);
    __half* qc   = (__half*)(S + O_QC);
    __half* kc   = (__half*)(S + O_KC);
    float*  qr   = S + O_QR;
    float*  kr   = S + O_KR;
    __half* vv   = (__half*)(S + O_V);
    __half* qcat = (__half*)(S + O_QCAT);
    __half* kcat = (__half*)(S + O_KCAT);
    __half* sch  = (__half*)(S + O_SC);
    __half* att  = (__half*)(S + O_ATT);
    float*  x    = S + O_X;
    __half* xn   = (__half*)(S + O_XN);
    __half* gu   = (__half*)(S + O_GATE);    // [Tt][16384]
    __half* cwqc = (__half*)(S + O_WQC);
    __half* cwkc = (__half*)(S + O_WKC);
    __half* cwqr = (__half*)(S + O_WQR);
    __half* cwkr = (__half*)(S + O_WKR);
    __half* cwv  = (__half*)(S + O_WV);
    __half* cwo  = (__half*)(S + O_WO);
    __half* cwgu = (__half*)(S + O_WGU);     // [Dm][16384]
    __half* cwd  = (__half*)(S + O_WDOWN);
    float2* stb  = (float2*)(S + O_ST);
    float*  ctl  = S + O_CTILE;
    float*  cinv = S + O_CINV;
    __half* hbuf = (__half*)(S + O_SC);      // silu output reuses sc region

    // 0. Weights -> half, native [K][N] layout (pure streaming)
    cvt_lin<<<2048, 256>>>((const float4*)w_qc,   (__half2*)cwqc, SZ_DD / 4);
    cvt_lin<<<2048, 256>>>((const float4*)w_kc,   (__half2*)cwkc, SZ_DD / 4);
    cvt_lin<<<1024, 256>>>((const float4*)w_qr,   (__half2*)cwqr, SZ_DR2 / 4);
    cvt_lin<<<1024, 256>>>((const float4*)w_kr,   (__half2*)cwkr, SZ_DR2 / 4);
    cvt_lin<<<2048, 256>>>((const float4*)w_v,    (__half2*)cwv,  SZ_DD / 4);
    cvt_lin<<<2048, 256>>>((const float4*)w_o,    (__half2*)cwo,  SZ_DD / 4);
    cvt_off8k<<<4096, 256>>>((const float4*)w_gate, cwgu, SZ_DF / 4, 0);
    cvt_off8k<<<4096, 256>>>((const float4*)w_up,   cwgu, SZ_DF / 4, 8192);
    cvt_lin<<<4096, 256>>>((const float4*)w_down, (__half2*)cwd,  SZ_DF / 4);

    // 1. RMSNorm -> half
    rmsnorm_h<<<Tt, 256>>>(query,  g_q,  qn);
    rmsnorm_h<<<Tt, 256>>>(keyval, g_kv, kvn);

    // 2. Projections (BT: B = native [k][n] weights)
    {
        dim3 grid(Dm / BN, Tt / BM, 1);
        mm_h<true,false,false,true ><<<grid, 256, SMEM_BT>>>(qn,  cwqc, nullptr, qc, Tt, Dm, Dm, Dm, Dm, Dm, 0,0,0,0,0,0, 1.f, nullptr, nullptr, nullptr);
        mm_h<true,false,false,true ><<<grid, 256, SMEM_BT>>>(kvn, cwkc, nullptr, kc, Tt, Dm, Dm, Dm, Dm, Dm, 0,0,0,0,0,0, 1.f, nullptr, nullptr, nullptr);
        mm_h<true,false,false,true ><<<grid, 256, SMEM_BT>>>(kvn, cwv,  nullptr, vv, Tt, Dm, Dm, Dm, Dm, Dm, 0,0,0,0,0,0, 1.f, nullptr, nullptr, nullptr);
    }
    {
        dim3 grid((NH * DR) / BN, Tt / BM, 1);
        mm_h<true,false,false,false><<<grid, 256, SMEM_BT>>>(qn,  cwqr, nullptr, qr, Tt, NH * DR, Dm, Dm, NH * DR, NH * DR, 0,0,0,0,0,0, 1.f, nullptr, nullptr, nullptr);
        mm_h<true,false,false,false><<<grid, 256, SMEM_BT>>>(kvn, cwkr, nullptr, kr, Tt, NH * DR, Dm, Dm, NH * DR, NH * DR, 0,0,0,0,0,0, 1.f, nullptr, nullptr, nullptr);
    }

    // 3. RoPE (fp32)
    {
        long long pairs = (long long)Tt * NH * (DR / 2);
        int blocks = (int)((pairs + 255) / 256);
        rope_k<<<blocks, 256>>>(qr, Mq);
        rope_k<<<blocks, 256>>>(kr, Nq);
    }

    // 4. Pack
    {
        long long tot = (long long)Tt * NH * DCAT;
        int blocks = (int)((tot + 255) / 256);
        pack_h<<<blocks, 256>>>(qc, qr, qcat);
        pack_h<<<blocks, 256>>>(kc, kr, kcat);
    }

    // 5. Scores -> half P_tile + stats (B = kcat [n][k], non-trans path)
    {
        dim3 grid(Nq / BN, Mq / BM, Bq * NH);
        mm_h<false,false,true,true><<<grid, 256, SMEM_BF>>>(qcat, kcat, nullptr, sch,
            Mq, Nq, DCAT, NH * DCAT, NH * DCAT, Nq,
            (long long)Mq * NH * DCAT, (long long)DCAT,
            (long long)Nq * NH * DCAT, (long long)DCAT,
            (long long)NH * Mq * Nq, (long long)Mq * Nq,
            SCALE_, stb, nullptr, nullptr);
    }

    // 6. Combine -> ctile, cinv
    combine_k<<<(int)(N_ROWS / 256), 256>>>(stb, ctl, cinv);

    // 7. attn @ V (B = vv [tok][NH*DH] = [k][n], trans path; no V transpose needed)
    {
        dim3 grid(DH / BN, Mq / BM, Bq * NH);
        mm_h<true,true,false,true><<<grid, 256, SMEM_BT>>>(sch, vv, nullptr, att,
            Mq, DH, Nq, Nq, NH * DH, NH * DH,
            (long long)NH * Mq * Nq, (long long)Mq * Nq,
            (long long)Nq * NH * DH, (long long)DH,
            (long long)Mq * NH * DH, (long long)DH,
            1.f, nullptr, ctl, cinv);
    }

    // 8. x = att @ w_o + query (fp32; B native [k][n])
    {
        dim3 grid(Dm / BN, Tt / BM, 1);
        mm_h<true,false,false,false><<<grid, 256, SMEM_BT>>>(att, cwo, query, x, Tt, Dm, NH * DH,
                                         NH * DH, Dm, Dm, 0,0,0,0,0,0, 1.f, nullptr, nullptr, nullptr);
    }

    // 9. RMSNorm -> xn half
    rmsnorm_h<<<Tt, 256>>>(x, g_ffn, xn);

    // 10. gate+up fused (N=16384, half out, interleaved weights)
    {
        dim3 grid((2 * FFN_) / BN, Tt / BM, 1);
        mm_h<true,false,false,true><<<grid, 256, SMEM_BT>>>(xn, cwgu, nullptr, gu,
            Tt, 2 * FFN_, Dm, Dm, 2 * FFN_, 2 * FFN_, 0,0,0,0,0,0, 1.f, nullptr, nullptr, nullptr);
    }

    // 11. h = silu(gate)*up -> half
    {
        long long tot = (long long)Tt * FFN_;
        int blocks = (int)((tot + 255) / 256);
        silumul_gu<<<blocks, 256>>>(gu, hbuf);
    }

    // 12. out = h @ w_down + x (fp32; B native [k][n])
    {
        dim3 grid(Dm / BN, Tt / BM, 1);
        mm_h<true,false,false,false><<<grid, 256, SMEM_BT>>>(hbuf, cwd, x, out, Tt, Dm, FFN_,
                                         FFN_, Dm, Dm, 0,0,0,0,0,0, 1.f, nullptr, nullptr, nullptr);
    }
}

// round 17
// speedup vs baseline: 7.4518x; 1.3472x over previous
#include <cuda_runtime.h>
#include <cuda_fp16.h>
#include <math.h>
#include <stdint.h>

// Problem constants
#define Bq   2
#define Mq   2048
#define Nq   2048
#define Dm   2048
#define NH   16
#define DH   128
#define DR   64
#define FFN_ 8192
#define Tt   (Bq*Mq)
#define DCAT (DH+DR)          // 192
#define SCALE_ (0.0721687836487032f) // 1/sqrt(192)
#define L2_1E6_D32 0.62286151779138045f   // log2(1e6)/32

// ---------------- scratch (float units; half buffers reuse regions) ----------------
#define O_QN    0LL
#define O_KVN   (O_QN   + (long long)Tt*Dm)
#define O_QCAT  (O_KVN  + (long long)Tt*Dm)
#define O_KCAT  (O_QCAT + (long long)Tt*NH*DCAT)
#define O_V     (O_KCAT + (long long)Tt*NH*DCAT)
#define O_SC    (O_V    + (long long)Tt*NH*DH)
#define O_ATT   (O_SC   + (long long)Bq*NH*Mq*Nq)
#define O_X     (O_ATT  + (long long)Tt*NH*DH)
#define O_XN    (O_X    + (long long)Tt*Dm)
#define O_HB    (O_XN   + (long long)Tt*Dm)       // half [Tt][8192]
#define SZ_DD   ((long long)Dm*Dm)
#define SZ_DR2  ((long long)Dm*NH*DR)
#define SZ_DF   ((long long)Dm*FFN_)
#define O_WQ    (O_HB   + (long long)Tt*FFN_)     // half [2048][3072]
#define O_WKV   (O_WQ   + (long long)Dm*3072)
#define O_WO    (O_WKV  + (long long)Dm*5120)
#define O_WGU   (O_WO   + SZ_DD)                  // half [2048][16384] interleaved 8-col
#define O_WDOWN (O_WGU  + 2*SZ_DF)
#define N_ROWS  ((long long)Bq*NH*Mq)
#define O_ST    (O_WDOWN+ SZ_DF)
#define O_CTILE (O_ST   + N_ROWS*16*2)
#define O_CINV  (O_CTILE+ N_ROWS*16)
#define O_TOTAL (O_CINV + N_ROWS)

__device__ float g_scratch[O_TOTAL];

// ---------------- streaming fp32 -> fp16 (no transpose) ----------------
__global__ void cvt_lin(const float4* __restrict__ src, __half2* __restrict__ dst,
                        long long n4) {
    long long i = (long long)blockIdx.x * blockDim.x + threadIdx.x;
    long long stride = (long long)gridDim.x * blockDim.x;
    for (; i < n4; i += stride) {
        float4 v = src[i];
        dst[2 * i]     = __floats2half2_rn(v.x, v.y);
        dst[2 * i + 1] = __floats2half2_rn(v.z, v.w);
    }
}

// src [K][Nsrc=2^shift] fp32 -> dst half pitch `pitch`, at column offset coloff
__global__ void cvt_off(const float4* __restrict__ src, __half* __restrict__ dst,
                        long long n4, int shift, int pitch, int coloff) {
    long long i = (long long)blockIdx.x * blockDim.x + threadIdx.x;
    long long stride = (long long)gridDim.x * blockDim.x;
    int mask = (1 << shift) - 1;
    for (; i < n4; i += stride) {
        float4 v = src[i];
        long long e = i * 4;
        long long k = e >> shift;
        int n = (int)(e & mask);
        __half2* d = (__half2*)(dst + k * pitch + coloff + n);
        d[0] = __floats2half2_rn(v.x, v.y);
        d[1] = __floats2half2_rn(v.z, v.w);
    }
}

// gate/up -> interleaved 8-col blocks: src [K][8192]; dst [K][16384],
// col f -> ((f>>3)<<4) + (f&7) + off8
__global__ void cvt_gu(const float4* __restrict__ src, __half* __restrict__ dst,
                       long long n4, int off8) {
    long long i = (long long)blockIdx.x * blockDim.x + threadIdx.x;
    long long stride = (long long)gridDim.x * blockDim.x;
    for (; i < n4; i += stride) {
        float4 v = src[i];
        long long e = i * 4;
        long long k = e >> 13;
        int n = (int)(e & 8191);
        int dc = ((n >> 3) << 4) + (n & 7) + off8;
        __half2* d = (__half2*)(dst + k * 16384 + dc);
        d[0] = __floats2half2_rn(v.x, v.y);
        d[1] = __floats2half2_rn(v.z, v.w);
    }
}

// ---------------- RMSNorm -> half ----------------
__global__ void rmsnorm_h(const float* __restrict__ x, const float* __restrict__ g,
                          __half* __restrict__ y) {
    const int D = Dm;
    long long row = blockIdx.x;
    const float* xr = x + row * D;
    __half* yr = y + row * D;
    float s = 0.f;
    for (int i = threadIdx.x; i < D; i += blockDim.x) { float v = xr[i]; s += v * v; }
    #pragma unroll
    for (int o = 16; o; o >>= 1) s += __shfl_xor_sync(0xffffffffu, s, o);
    __shared__ float sh[8];
    if ((threadIdx.x & 31) == 0) sh[threadIdx.x >> 5] = s;
    __syncthreads();
    float tot = 0.f;
    #pragma unroll
    for (int i = 0; i < 8; i++) tot += sh[i];
    float n = rsqrtf(tot / (float)D + 1e-6f);
    for (int i = threadIdx.x; i < D; i += blockDim.x)
        yr[i] = __float2half_rn(xr[i] * n * g[i]);
}

// ---------------- ldmatrix ----------------
__device__ __forceinline__ void ldsm_x4(unsigned& r0, unsigned& r1, unsigned& r2, unsigned& r3,
                                        const __half* p) {
    unsigned a = (unsigned)__cvta_generic_to_shared(p);
    asm volatile("ldmatrix.sync.aligned.m8n8.x4.shared.b16 {%0,%1,%2,%3}, [%4];"
                 : "=r"(r0), "=r"(r1), "=r"(r2), "=r"(r3) : "r"(a));
}
__device__ __forceinline__ void ldsm_x4t(unsigned& r0, unsigned& r1, unsigned& r2, unsigned& r3,
                                         const __half* p) {
    unsigned a = (unsigned)__cvta_generic_to_shared(p);
    asm volatile("ldmatrix.sync.aligned.m8n8.x4.trans.shared.b16 {%0,%1,%2,%3}, [%4];"
                 : "=r"(r0), "=r"(r1), "=r"(r2), "=r"(r3) : "r"(a));
}

__device__ __forceinline__ float siluf(float x) {
    return x / (1.f + expf(-x));
}

// ---------------- fp16 tensor-core GEMM, 4-stage cp.async ----------------
// BT : B row-major [K,N] (native weights) via ldmatrix.trans; else [N,K] via ldmatrix.
// PEX: A = half P_tile; fragments *= ctile; epilogue *= cinv[row].
// SST: epilogue emits softmax partials; C = half exp(v-Mtile).
// HOUT: C half; else fp32 + optional residual R.
// PACK: 1 = Q proj (N=3072 -> qcat w/ RoPE), 2 = KV proj (N=5120 -> kcat + vv(C2)).
// FFN: gate/up interleaved; epilogue writes silu(g)*u to half C (pitch ldc/2 logical 8192).
#define BM 128
#define BN 128
#define BKH 32
#define PH  40
#define PBT 136
#define NST 4
#define ABYTES (BM * PH * 2)
#define SMEM_BT (NST * (ABYTES + BKH * PBT * 2))   // 75776
#define SMEM_BF (NST * (ABYTES + BN * PH * 2))     // 81920

template<bool BT, bool PEX, bool SST, bool HOUT, int PACK, bool FFN>
__global__ void __launch_bounds__(256, 2) mm_h(
    const __half* __restrict__ A, const __half* __restrict__ B,
    const float* __restrict__ R, void* __restrict__ Cv, __half* __restrict__ C2,
    int M, int N, int K, int lda, int ldb, int ldc,
    long long aB, long long aH, long long bB, long long bH,
    long long cB, long long cH, float alpha,
    float2* __restrict__ stats, const float* __restrict__ ctile,
    const float* __restrict__ cinv)
{
    constexpr int BBYTES = BT ? (BKH * PBT * 2) : (BN * PH * 2);

    int z = blockIdx.z, bb = z >> 4, hh = z & 15;
    A += bb * aB + hh * aH;
    B += bb * bB + hh * bH;
    float*  Cf = (float*)Cv + bb * cB + hh * cH;
    __half* Ch = (__half*)Cv + bb * cB + hh * cH;
    if (R) R += bb * cB + hh * cH;

    extern __shared__ __align__(16) char smraw[];
    char* AsBase = smraw;
    char* BsBase = smraw + NST * ABYTES;

    const int tid = threadIdx.x;
    const int row0 = blockIdx.y * BM, col0 = blockIdx.x * BN;

    const int lane = tid & 31, warp = tid >> 5;
    const int g  = lane >> 2, tg = lane & 3;
    const int mb = (warp >> 1) * 32;
    const int nb = (warp & 1) * 64;
    const int lm = lane >> 3, lr = lane & 7;
    const int lrow = (lm & 1) * 8 + lr, lcol = (lm >> 1) * 8;

    __shared__ __half2 csm[PEX ? 2048 : 1];
    __shared__ float   sInv[PEX ? 128 : 1];
    if (PEX) {
        for (int i = tid; i < 2048; i += 256) {
            int r = i >> 4;
            float c = ctile[((long long)z * Mq + row0 + r) * 16 + (i & 15)];
            csm[i] = __floats2half2_rn(c, c);
        }
        if (tid < 128)
            sInv[tid] = cinv[(long long)z * Mq + row0 + tid];
        __syncthreads();
    }

    float acc[2][8][4];
    #pragma unroll
    for (int mi = 0; mi < 2; mi++)
        #pragma unroll
        for (int ni = 0; ni < 8; ni++)
            #pragma unroll
            for (int q = 0; q < 4; q++) acc[mi][ni][q] = 0.f;

    auto copyA = [&](int buf, int kt) {
        __half* dst = (__half*)(AsBase + buf * ABYTES);
        #pragma unroll
        for (int q = tid; q < 512; q += 256) {
            int r = q >> 2, c = q & 3;
            const __half* gp = A + (long long)(row0 + r) * lda + kt + c * 8;
            unsigned s = (unsigned)__cvta_generic_to_shared(&dst[r * PH + c * 8]);
            asm volatile("cp.async.ca.shared.global [%0], [%1], 16;\n" :: "r"(s), "l"(gp));
        }
    };
    auto copyB = [&](int buf, int kt) {
        __half* dst = (__half*)(BsBase + buf * BBYTES);
        if (BT) {
            #pragma unroll
            for (int q = tid; q < 512; q += 256) {
                int r = q >> 4, c = q & 15;
                const __half* gp = B + (long long)(kt + r) * ldb + col0 + c * 8;
                unsigned s = (unsigned)__cvta_generic_to_shared(&dst[r * PBT + c * 8]);
                asm volatile("cp.async.ca.shared.global [%0], [%1], 16;\n" :: "r"(s), "l"(gp));
            }
        } else {
            #pragma unroll
            for (int q = tid; q < 512; q += 256) {
                int r = q >> 2, c = q & 3;
                const __half* gp = B + (long long)(col0 + r) * ldb + kt + c * 8;
                unsigned s = (unsigned)__cvta_generic_to_shared(&dst[r * PH + c * 8]);
                asm volatile("cp.async.ca.shared.global [%0], [%1], 16;\n" :: "r"(s), "l"(gp));
            }
        }
    };

    const int nt = K / BKH;

    #pragma unroll
    for (int s = 0; s < NST - 1; ++s) {
        copyA(s, s * BKH);
        copyB(s, s * BKH);
        asm volatile("cp.async.commit_group;\n" ::: "memory");
    }

    for (int t = 0; t < nt; ++t) {
        asm volatile("cp.async.wait_group %0;\n" :: "n"(NST - 2) : "memory");
        __syncthreads();

        int nxt = t + NST - 1;
        if (nxt < nt) {
            copyA(nxt % NST, nxt * BKH);
            copyB(nxt % NST, nxt * BKH);
        }
        asm volatile("cp.async.commit_group;\n" ::: "memory");

        const int cur = t % NST;
        const __half* as = (const __half*)(AsBase + cur * ABYTES);
        const __half* bs = (const __half*)(BsBase + cur * BBYTES);

        __half2 chA[2], chB[2];
        if (PEX) {
            int si = t >> 2;
            chA[0] = csm[(mb + g) * 16 + si];
            chA[1] = csm[(mb + 16 + g) * 16 + si];
            chB[0] = csm[(mb + 8 + g) * 16 + si];
            chB[1] = csm[(mb + 24 + g) * 16 + si];
        }

        #pragma unroll
        for (int kk = 0; kk < BKH; kk += 16) {
            unsigned a[2][4], b[8][2];
            #pragma unroll
            for (int mi = 0; mi < 2; ++mi) {
                ldsm_x4(a[mi][0], a[mi][1], a[mi][2], a[mi][3],
                        as + (mb + mi * 16 + lrow) * PH + kk + lcol);
                if (PEX) {
                    __half2* ap = (__half2*)a[mi];
                    ap[0] = __hmul2(ap[0], chA[mi]);
                    ap[1] = __hmul2(ap[1], chB[mi]);
                    ap[2] = __hmul2(ap[2], chA[mi]);
                    ap[3] = __hmul2(ap[3], chB[mi]);
                }
            }
            if (BT) {
                #pragma unroll
                for (int j = 0; j < 4; ++j) {
                    unsigned r0, r1, r2, r3;
                    ldsm_x4t(r0, r1, r2, r3,
                             bs + (kk + (lm & 1) * 8 + lr) * PBT
                                + nb + j * 16 + (lm >> 1) * 8);
                    b[2 * j][0] = r0; b[2 * j][1] = r1;
                    b[2 * j + 1][0] = r2; b[2 * j + 1][1] = r3;
                }
            } else {
                #pragma unroll
                for (int j = 0; j < 4; ++j) {
                    unsigned r0, r1, r2, r3;
                    ldsm_x4(r0, r1, r2, r3,
                            bs + (nb + j * 16 + lrow) * PH + kk + lcol);
                    b[2 * j][0] = r0; b[2 * j][1] = r2;
                    b[2 * j + 1][0] = r1; b[2 * j + 1][1] = r3;
                }
            }
            #pragma unroll
            for (int mi = 0; mi < 2; ++mi)
                #pragma unroll
                for (int ni = 0; ni < 8; ++ni)
                    asm volatile(
                        "mma.sync.aligned.m16n8k16.row.col.f32.f16.f16.f32 "
                        "{%0,%1,%2,%3}, {%4,%5,%6,%7}, {%8,%9}, {%0,%1,%2,%3};\n"
                        : "+f"(acc[mi][ni][0]), "+f"(acc[mi][ni][1]),
                          "+f"(acc[mi][ni][2]), "+f"(acc[mi][ni][3])
                        : "r"(a[mi][0]), "r"(a[mi][1]), "r"(a[mi][2]), "r"(a[mi][3]),
                          "r"(b[ni][0]), "r"(b[ni][1]));
        }
    }

    // ================= epilogues =================
    if (PACK != 0) {
        // project into qcat/kcat (+ vv for PACK==2). C = cat buffer, ldc = 3072.
        #pragma unroll
        for (int mi = 0; mi < 2; ++mi) {
            long long rr = row0 + mb + mi * 16 + g;
            int s1 = (int)(rr & (Mq - 1));
            int s2 = (int)((rr + 8) & (Mq - 1));
            #pragma unroll
            for (int ni = 0; ni < 8; ++ni) {
                int cc = col0 + nb + ni * 8 + tg * 2;
                float2 v0 = make_float2(acc[mi][ni][0], acc[mi][ni][1]);
                float2 v1 = make_float2(acc[mi][ni][2], acc[mi][ni][3]);
                if (cc < 2048) {
                    // C-part: h = cc>>7, d = cc&127 -> col h*192+d
                    int dst = ((cc >> 7) * 192) + (cc & 127);
                    *(__half2*)&Ch[rr * 3072 + dst] = __floats2half2_rn(v0.x, v0.y);
                    *(__half2*)&Ch[(rr + 8) * 3072 + dst] = __floats2half2_rn(v1.x, v1.y);
                } else if (PACK == 1 || cc < 3072) {
                    // R-part with RoPE: d even = 2j
                    int cr = cc - 2048;
                    int d = cr & 63, h = cr >> 6;
                    float jf = (float)(d >> 1);
                    float freq = exp2f(-jf * L2_1E6_D32);
                    float c1, si1, c2, si2;
                    sincosf((float)s1 * freq, &si1, &c1);
                    sincosf((float)s2 * freq, &si2, &c2);
                    float o0 = v0.x * c1 - v0.y * si1;
                    float o1 = v0.y * c1 + v0.x * si1;
                    float o2 = v1.x * c2 - v1.y * si2;
                    float o3 = v1.y * c2 + v1.x * si2;
                    int dst = h * 192 + 128 + d;
                    *(__half2*)&Ch[rr * 3072 + dst] = __floats2half2_rn(o0, o1);
                    *(__half2*)&Ch[(rr + 8) * 3072 + dst] = __floats2half2_rn(o2, o3);
                } else {
                    // V-part -> C2 [tok][2048]
                    int cv = cc - 3072;
                    *(__half2*)&C2[rr * 2048 + cv] = __floats2half2_rn(v0.x, v0.y);
                    *(__half2*)&C2[(rr + 8) * 2048 + cv] = __floats2half2_rn(v1.x, v1.y);
                }
            }
        }
    } else if (FFN) {
        // interleaved gate/up -> silu(g)*u, half out to C (pitch 8192)
        #pragma unroll
        for (int mi = 0; mi < 2; ++mi) {
            long long rr = row0 + mb + mi * 16 + g;
            #pragma unroll
            for (int ni = 0; ni < 8; ni += 2) {
                int f0 = (((col0 + nb + ni * 8) >> 4) << 3) + tg * 2;
                float h0 = siluf(acc[mi][ni][0]) * acc[mi][ni + 1][0];
                float h1 = siluf(acc[mi][ni][1]) * acc[mi][ni + 1][1];
                float h2 = siluf(acc[mi][ni][2]) * acc[mi][ni + 1][2];
                float h3 = siluf(acc[mi][ni][3]) * acc[mi][ni + 1][3];
                *(__half2*)&Ch[rr * 8192 + f0] = __floats2half2_rn(h0, h1);
                *(__half2*)&Ch[(rr + 8) * 8192 + f0] = __floats2half2_rn(h2, h3);
            }
        }
    } else if (!SST) {
        #pragma unroll
        for (int mi = 0; mi < 2; ++mi) {
            float ivA = 1.f, ivB = 1.f;
            if (PEX) {
                ivA = sInv[mb + mi * 16 + g];
                ivB = sInv[mb + mi * 16 + 8 + g];
            }
            #pragma unroll
            for (int ni = 0; ni < 8; ++ni) {
                long long rr = row0 + mb + mi * 16 + g;
                long long cc = col0 + nb + ni * 8 + tg * 2;
                float2 v0 = make_float2(acc[mi][ni][0] * alpha, acc[mi][ni][1] * alpha);
                float2 v1 = make_float2(acc[mi][ni][2] * alpha, acc[mi][ni][3] * alpha);
                if (PEX) { v0.x *= ivA; v0.y *= ivA; v1.x *= ivB; v1.y *= ivB; }
                if (HOUT) {
                    *(__half2*)&Ch[rr * ldc + cc] = __floats2half2_rn(v0.x, v0.y);
                    *(__half2*)&Ch[(rr + 8) * ldc + cc] = __floats2half2_rn(v1.x, v1.y);
                } else {
                    if (R) {
                        float2 r0 = *(const float2*)&R[rr * ldc + cc];
                        float2 r1 = *(const float2*)&R[(rr + 8) * ldc + cc];
                        v0.x += r0.x; v0.y += r0.y; v1.x += r1.x; v1.y += r1.y;
                    }
                    *(float2*)&Cf[rr * ldc + cc] = v0;
                    *(float2*)&Cf[(rr + 8) * ldc + cc] = v1;
                }
            }
        }
    } else {
        // softmax stats + exp-half write
        __syncthreads();
        float* st  = (float*)smraw;
        float* st2 = (float*)smraw + 256;
        const int wc = warp & 1;
        #pragma unroll
        for (int mi = 0; mi < 2; ++mi)
            #pragma unroll
            for (int h = 0; h < 2; ++h) {
                float m = -3.4e38f;
                #pragma unroll
                for (int ni = 0; ni < 8; ++ni)
                    m = fmaxf(m, fmaxf(acc[mi][ni][2 * h] * alpha,
                                       acc[mi][ni][2 * h + 1] * alpha));
                #pragma unroll
                for (int o = 1; o <= 2; o <<= 1)
                    m = fmaxf(m, __shfl_xor_sync(0xffffffffu, m, o));
                if (tg == 0) st[wc * 128 + mb + mi * 16 + h * 8 + g] = m;
            }
        __syncthreads();
        float M2[2][2];
        #pragma unroll
        for (int mi = 0; mi < 2; ++mi)
            #pragma unroll
            for (int h = 0; h < 2; ++h) {
                int lrw = mb + mi * 16 + h * 8 + g;
                M2[mi][h] = fmaxf(st[lrw], st[128 + lrw]);
                float s = 0.f;
                #pragma unroll
                for (int ni = 0; ni < 8; ++ni)
                    s += expf(acc[mi][ni][2 * h] * alpha - M2[mi][h])
                       + expf(acc[mi][ni][2 * h + 1] * alpha - M2[mi][h]);
                #pragma unroll
                for (int o = 1; o <= 2; o <<= 1)
                    s += __shfl_xor_sync(0xffffffffu, s, o);
                if (tg == 0) st2[wc * 128 + mb + mi * 16 + h * 8 + g] = s;
            }
        __syncthreads();
        if (wc == 0 && tg == 0) {
            #pragma unroll
            for (int mi = 0; mi < 2; ++mi)
                #pragma unroll
                for (int h = 0; h < 2; ++h) {
                    int lrw = mb + mi * 16 + h * 8 + g;
                    stats[((long long)z * Mq + row0 + lrw) * 16 + blockIdx.x] =
                        make_float2(M2[mi][h], st2[lrw] + st2[128 + lrw]);
                }
        }
        #pragma unroll
        for (int mi = 0; mi < 2; ++mi) {
            #pragma unroll
            for (int ni = 0; ni < 8; ++ni) {
                long long rr = row0 + mb + mi * 16 + g;
                long long cc = col0 + nb + ni * 8 + tg * 2;
                *(__half2*)&Ch[rr * ldc + cc] = __floats2half2_rn(
                    expf(acc[mi][ni][0] * alpha - M2[mi][0]),
                    expf(acc[mi][ni][1] * alpha - M2[mi][0]));
                *(__half2*)&Ch[(rr + 8) * ldc + cc] = __floats2half2_rn(
                    expf(acc[mi][ni][2] * alpha - M2[mi][1]),
                    expf(acc[mi][ni][3] * alpha - M2[mi][1]));
            }
        }
    }
}

// ---------------- combine stats ----------------
__global__ void combine_k(const float2* __restrict__ st, float* __restrict__ ctile,
                          float* __restrict__ cinv) {
    long long row = (long long)blockIdx.x * 256 + threadIdx.x;
    const float2* p = st + row * 16;
    float2 v[16];
    float M = -3.4e38f;
    #pragma unroll
    for (int i = 0; i < 16; i++) { v[i] = p[i]; M = fmaxf(M, v[i].x); }
    float S = 0.f;
    #pragma unroll
    for (int i = 0; i < 16; i++) {
        float c = expf(v[i].x - M);
        S += v[i].y * c;
        ctile[row * 16 + i] = c;
    }
    cinv[row] = 1.f / S;
}

// ---------------- launch ----------------
extern "C" void kernel_launch(void* const* d_in, const int* in_sizes, int n_in,
                              void* d_out, int out_size) {
    (void)in_sizes; (void)n_in; (void)out_size;
    const float* query  = (const float*)d_in[0];
    const float* keyval = (const float*)d_in[1];
    const float* g_q    = (const float*)d_in[2];
    const float* g_kv   = (const float*)d_in[3];
    const float* g_ffn  = (const float*)d_in[4];
    const float* w_qc   = (const float*)d_in[5];
    const float* w_kc   = (const float*)d_in[6];
    const float* w_qr   = (const float*)d_in[7];
    const float* w_kr   = (const float*)d_in[8];
    const float* w_v    = (const float*)d_in[9];
    const float* w_o    = (const float*)d_in[10];
    const float* w_gate = (const float*)d_in[11];
    const float* w_up   = (const float*)d_in[12];
    const float* w_down = (const float*)d_in[13];
    float* out = (float*)d_out;

    static bool attr_done = false;
    if (!attr_done) {
        cudaFuncSetAttribute(mm_h<true, false,false,true ,1,false>, cudaFuncAttributeMaxDynamicSharedMemorySize, SMEM_BT);
        cudaFuncSetAttribute(mm_h<true, false,false,true ,2,false>, cudaFuncAttributeMaxDynamicSharedMemorySize, SMEM_BT);
        cudaFuncSetAttribute(mm_h<false,false,true ,true ,0,false>, cudaFuncAttributeMaxDynamicSharedMemorySize, SMEM_BF);
        cudaFuncSetAttribute(mm_h<true, true ,false,true ,0,false>, cudaFuncAttributeMaxDynamicSharedMemorySize, SMEM_BT);
        cudaFuncSetAttribute(mm_h<true, false,false,false,0,false>, cudaFuncAttributeMaxDynamicSharedMemorySize, SMEM_BT);
        cudaFuncSetAttribute(mm_h<true, false,false,true ,0,true >, cudaFuncAttributeMaxDynamicSharedMemorySize, SMEM_BT);
        attr_done = true;
    }

    float* S = nullptr;
    cudaGetSymbolAddress((void**)&S, g_scratch);
    __half* qn   = (__half*)(S + O_QN);
    __half* kvn  = (__half*)(S + O_KVN);
    __half* qcat = (__half*)(S + O_QCAT);
    __half* kcat = (__half*)(S + O_KCAT);
    __half* vv   = (__half*)(S + O_V);
    __half* sch  = (__half*)(S + O_SC);
    __half* att  = (__half*)(S + O_ATT);
    float*  x    = S + O_X;
    __half* xn   = (__half*)(S + O_XN);
    __half* hbuf = (__half*)(S + O_HB);
    __half* cwq  = (__half*)(S + O_WQ);      // [2048][3072]
    __half* cwkv = (__half*)(S + O_WKV);     // [2048][5120]
    __half* cwo  = (__half*)(S + O_WO);
    __half* cwgu = (__half*)(S + O_WGU);     // [2048][16384]
    __half* cwd  = (__half*)(S + O_WDOWN);
    float2* stb  = (float2*)(S + O_ST);
    float*  ctl  = S + O_CTILE;
    float*  cinv = S + O_CINV;

    // 0. Weights -> half
    cvt_off<<<2048, 256>>>((const float4*)w_qc, cwq,  SZ_DD / 4,  11, 3072, 0);
    cvt_off<<<1024, 256>>>((const float4*)w_qr, cwq,  SZ_DR2 / 4, 10, 3072, 2048);
    cvt_off<<<2048, 256>>>((const float4*)w_kc, cwkv, SZ_DD / 4,  11, 5120, 0);
    cvt_off<<<1024, 256>>>((const float4*)w_kr, cwkv, SZ_DR2 / 4, 10, 5120, 2048);
    cvt_off<<<2048, 256>>>((const float4*)w_v,  cwkv, SZ_DD / 4,  11, 5120, 3072);
    cvt_lin<<<2048, 256>>>((const float4*)w_o,    (__half2*)cwo, SZ_DD / 4);
    cvt_gu <<<4096, 256>>>((const float4*)w_gate, cwgu, SZ_DF / 4, 0);
    cvt_gu <<<4096, 256>>>((const float4*)w_up,   cwgu, SZ_DF / 4, 8);
    cvt_lin<<<4096, 256>>>((const float4*)w_down, (__half2*)cwd, SZ_DF / 4);

    // 1. RMSNorm -> half
    rmsnorm_h<<<Tt, 256>>>(query,  g_q,  qn);
    rmsnorm_h<<<Tt, 256>>>(keyval, g_kv, kvn);

    // 2. Fused projections -> qcat / kcat+vv (RoPE + pack in epilogue)
    {
        dim3 gq(3072 / BN, Tt / BM, 1);
        mm_h<true,false,false,true,1,false><<<gq, 256, SMEM_BT>>>(qn, cwq, nullptr, qcat, nullptr,
            Tt, 3072, Dm, Dm, 3072, 3072, 0,0,0,0,0,0, 1.f, nullptr, nullptr, nullptr);
        dim3 gkv(5120 / BN, Tt / BM, 1);
        mm_h<true,false,false,true,2,false><<<gkv, 256, SMEM_BT>>>(kvn, cwkv, nullptr, kcat, vv,
            Tt, 5120, Dm, Dm, 5120, 3072, 0,0,0,0,0,0, 1.f, nullptr, nullptr, nullptr);
    }

    // 3. Scores -> half P_tile + stats
    {
        dim3 grid(Nq / BN, Mq / BM, Bq * NH);
        mm_h<false,false,true,true,0,false><<<grid, 256, SMEM_BF>>>(qcat, kcat, nullptr, sch, nullptr,
            Mq, Nq, DCAT, NH * DCAT, NH * DCAT, Nq,
            (long long)Mq * NH * DCAT, (long long)DCAT,
            (long long)Nq * NH * DCAT, (long long)DCAT,
            (long long)NH * Mq * Nq, (long long)Mq * Nq,
            SCALE_, stb, nullptr, nullptr);
    }

    // 4. Combine -> ctile, cinv
    combine_k<<<(int)(N_ROWS / 256), 256>>>(stb, ctl, cinv);

    // 5. attn @ V
    {
        dim3 grid(DH / BN, Mq / BM, Bq * NH);
        mm_h<true,true,false,true,0,false><<<grid, 256, SMEM_BT>>>(sch, vv, nullptr, att, nullptr,
            Mq, DH, Nq, Nq, NH * DH, NH * DH,
            (long long)NH * Mq * Nq, (long long)Mq * Nq,
            (long long)Nq * NH * DH, (long long)DH,
            (long long)Mq * NH * DH, (long long)DH,
            1.f, nullptr, ctl, cinv);
    }

    // 6. x = att @ w_o + query (fp32)
    {
        dim3 grid(Dm / BN, Tt / BM, 1);
        mm_h<true,false,false,false,0,false><<<grid, 256, SMEM_BT>>>(att, cwo, query, x, nullptr,
            Tt, Dm, NH * DH, NH * DH, Dm, Dm, 0,0,0,0,0,0, 1.f, nullptr, nullptr, nullptr);
    }

    // 7. RMSNorm -> xn half
    rmsnorm_h<<<Tt, 256>>>(x, g_ffn, xn);

    // 8. gate+up fused GEMM with SwiGLU epilogue -> hbuf [Tt][8192] half
    {
        dim3 grid((2 * FFN_) / BN, Tt / BM, 1);
        mm_h<true,false,false,true,0,true><<<grid, 256, SMEM_BT>>>(xn, cwgu, nullptr, hbuf, nullptr,
            Tt, 2 * FFN_, Dm, Dm, 2 * FFN_, 2 * FFN_, 0,0,0,0,0,0, 1.f, nullptr, nullptr, nullptr);
    }

    // 9. out = h @ w_down + x (fp32)
    {
        dim3 grid(Dm / BN, Tt / BM, 1);
        mm_h<true,false,false,false,0,false><<<grid, 256, SMEM_BT>>>(hbuf, cwd, x, out, nullptr,
            Tt, Dm, FFN_, FFN_, Dm, Dm, 0,0,0,0,0,0, 1.f, nullptr, nullptr, nullptr);
    }
}